// round 1
// baseline (speedup 1.0000x reference)
#include <cuda_runtime.h>
#include <math.h>

#define N_NODES 1024
#define SEQ     64
#define HID     128
#define NEDGE   4096
#define NCLS    64
#define NS      (N_NODES*SEQ)   /* 65536  */
#define ES      (NEDGE*SEQ)     /* 262144 */

// ---------------- scratch (device globals; no allocation allowed) ----------------
__device__ float g_x[NS*256];        // x, later reused as agg
__device__ float g_nf[NS*128];
__device__ float g_tmp[NS*128];
__device__ float g_P[NS*256];
__device__ float g_Q[NS*256];
__device__ float g_m1[ES*256];
__device__ float g_m2[ES*256];
__device__ float g_gates[NS*512];
__device__ float g_invdeg[N_NODES];
__device__ float g_h[N_NODES*HID];
__device__ float g_bsum[512];

// ---------------- small helpers ----------------
__device__ __forceinline__ float eluf(float v){ return v > 0.f ? v : expm1f(v); }
__device__ __forceinline__ float sigf(float v){ return 1.f/(1.f+expf(-v)); }

// ---------------- degree ----------------
__global__ void k_zero_deg(){
    int i = blockIdx.x*blockDim.x + threadIdx.x;
    if(i < N_NODES) g_invdeg[i] = 0.f;
}
__global__ void k_deg(const int* __restrict__ dst){
    int e = blockIdx.x*blockDim.x + threadIdx.x;
    if(e < NEDGE) atomicAdd(&g_invdeg[dst[e]], 1.f);
}
__global__ void k_fin_deg(){
    int i = blockIdx.x*blockDim.x + threadIdx.x;
    if(i < N_NODES){ float d = g_invdeg[i]; g_invdeg[i] = 1.f/fmaxf(d,1.f); }
}
__global__ void k_bsum(const float* __restrict__ bih, const float* __restrict__ bhh){
    int i = blockIdx.x*blockDim.x + threadIdx.x;
    if(i < 512) g_bsum[i] = bih[i] + bhh[i];
}

// ---------------- build x = [emb(127) | events(1) | te(128)] ----------------
__global__ void k_build_x(const float* __restrict__ itime, const float* __restrict__ iev,
                          const int* __restrict__ ann, const float* __restrict__ emb){
    int row = blockIdx.x;        // n*SEQ + s
    int c   = threadIdx.x;       // 0..255
    float t = itime[row];
    float e = iev[row];
    float v;
    if(c < 127){
        v = emb[ann[row]*127 + c];
    } else if(c == 127){
        v = e;
    } else {
        int j = c - 128;
        float pos = powf(10000.f, (2.f*(float)(j>>1))/128.f);
        float r = t / pos;
        float te = (j & 1) ? cosf(r) : sinf(r);
        v = (e != 0.f) ? te : 0.f;
    }
    g_x[row*256 + c] = v;
}

// ---------------- generic fp32 tiled GEMM: C = act(scale * A@B^T + bias) ----------------
// A [M,K] lda, B [Nc, ldb] row-major (we use B's rows as output cols), C [M, Nc] ldc.
// grid = (M/64, Nc/64), block = 256. M,Nc multiples of 64; K multiple of 16.
template<int ACT, bool BIAS, bool SCALE>
__global__ void k_gemm(const float* __restrict__ A, int lda,
                       const float* __restrict__ B, int ldb,
                       const float* __restrict__ bias,
                       const float* __restrict__ rowscale,
                       float* __restrict__ C, int ldc, int K)
{
    __shared__ float As[16][64];
    __shared__ float Bs[16][64];
    const int m0 = blockIdx.x*64, n0 = blockIdx.y*64;
    const int tid = threadIdx.x;
    const int tx = tid & 15, ty = tid >> 4;
    const int lr = tid >> 2;            // load row 0..63
    const int lc = (tid & 3) * 4;       // load col 0,4,8,12

    float acc[4][4];
#pragma unroll
    for(int i=0;i<4;i++)
#pragma unroll
        for(int j=0;j<4;j++) acc[i][j]=0.f;

    for(int k0=0;k0<K;k0+=16){
        float4 av = *(const float4*)&A[(size_t)(m0+lr)*lda + k0 + lc];
        float4 bv = *(const float4*)&B[(size_t)(n0+lr)*ldb + k0 + lc];
        As[lc+0][lr]=av.x; As[lc+1][lr]=av.y; As[lc+2][lr]=av.z; As[lc+3][lr]=av.w;
        Bs[lc+0][lr]=bv.x; Bs[lc+1][lr]=bv.y; Bs[lc+2][lr]=bv.z; Bs[lc+3][lr]=bv.w;
        __syncthreads();
#pragma unroll
        for(int k=0;k<16;k++){
            float4 a4 = *(const float4*)&As[k][ty*4];
            float4 b4 = *(const float4*)&Bs[k][tx*4];
            float a[4]={a4.x,a4.y,a4.z,a4.w};
            float b[4]={b4.x,b4.y,b4.z,b4.w};
#pragma unroll
            for(int i=0;i<4;i++)
#pragma unroll
                for(int j=0;j<4;j++) acc[i][j] += a[i]*b[j];
        }
        __syncthreads();
    }

#pragma unroll
    for(int i=0;i<4;i++){
        int row = m0 + ty*4 + i;
        float s = SCALE ? rowscale[row >> 6] : 1.f;   // rows-per-node == SEQ == 64
#pragma unroll
        for(int j=0;j<4;j++){
            float v = acc[i][j]*s;
            if(BIAS) v += bias[n0 + tx*4 + j];
            if(ACT==1) v = eluf(v);
            C[(size_t)row*ldc + n0 + tx*4 + j] = v;
        }
    }
}

// ---------------- edge combine: m1 = elu(P[src] + Q[dst] + b1) ----------------
__global__ void k_edge_combine(const int* __restrict__ src, const int* __restrict__ dst,
                               const float* __restrict__ b1){
    int row = blockIdx.x;       // e*SEQ + s
    int e = row >> 6, s = row & 63;
    int c = threadIdx.x;
    size_t sr = (size_t)(src[e]*SEQ + s)*256;
    size_t dr = (size_t)(dst[e]*SEQ + s)*256;
    float v = g_P[sr + c] + g_Q[dr + c] + b1[c];
    g_m1[(size_t)row*256 + c] = eluf(v);
}

// ---------------- zero agg (reuses g_x) ----------------
__global__ void k_zero_agg(){
    size_t idx = (size_t)blockIdx.x*blockDim.x + threadIdx.x;
    ((float4*)g_x)[idx] = make_float4(0.f,0.f,0.f,0.f);
}

// ---------------- scatter-add m2 into agg ----------------
__global__ void k_scatter(const int* __restrict__ dst){
    int row = blockIdx.x;       // e*SEQ + s
    int e = row >> 6, s = row & 63;
    int c = threadIdx.x;
    atomicAdd(&g_x[(size_t)(dst[e]*SEQ + s)*256 + c], g_m2[(size_t)row*256 + c]);
}

// ---------------- persistent LSTM (gates precomputed; recurrence only) ----------------
// 128 blocks x 256 threads; block b owns nodes [b*8, b*8+8). h,c live in smem.
__global__ void __launch_bounds__(256) k_lstm_all(const float* __restrict__ Whh){
    __shared__ float ws[8][516];     // Whh K-stage, [k][row], padded vs bank conflicts
    __shared__ float gs[8][512];     // gates for 8 nodes
    __shared__ float hs[8][128];
    __shared__ float cs[8][128];
    const int tid = threadIdx.x;
    const int nb = blockIdx.x*8;
    const int u = tid & 127;         // gate-row group: rows u*4..u*4+3
    const int v = tid >> 7;          // node group: nodes v*4..v*4+3

    for(int i=tid;i<8*128;i+=256){ hs[i>>7][i&127]=0.f; cs[i>>7][i&127]=0.f; }
    __syncthreads();

    for(int t=0;t<SEQ;t++){
        // load precomputed gates (x@Wih^T + bih + bhh) for this step
        for(int i=tid;i<8*512;i+=256){
            int n=i>>9, r=i&511;
            gs[n][r] = g_gates[((size_t)(nb+n)*SEQ + t)*512 + r];
        }
        __syncthreads();

        float acc[4][4];
#pragma unroll
        for(int i=0;i<4;i++)
#pragma unroll
            for(int m=0;m<4;m++) acc[i][m] = gs[v*4+m][u*4+i];

        for(int kc=0;kc<128;kc+=8){
            __syncthreads();                       // prev stage's ws reads done
            for(int i=tid;i<512*8;i+=256){
                int r=i>>3, c=i&7;
                ws[c][r] = Whh[r*128 + kc + c];
            }
            __syncthreads();
#pragma unroll
            for(int k=0;k<8;k++){
                float4 w4 = *(const float4*)&ws[k][u*4];
                float hv0 = hs[v*4+0][kc+k];
                float hv1 = hs[v*4+1][kc+k];
                float hv2 = hs[v*4+2][kc+k];
                float hv3 = hs[v*4+3][kc+k];
                acc[0][0]+=w4.x*hv0; acc[0][1]+=w4.x*hv1; acc[0][2]+=w4.x*hv2; acc[0][3]+=w4.x*hv3;
                acc[1][0]+=w4.y*hv0; acc[1][1]+=w4.y*hv1; acc[1][2]+=w4.y*hv2; acc[1][3]+=w4.y*hv3;
                acc[2][0]+=w4.z*hv0; acc[2][1]+=w4.z*hv1; acc[2][2]+=w4.z*hv2; acc[2][3]+=w4.z*hv3;
                acc[3][0]+=w4.w*hv0; acc[3][1]+=w4.w*hv1; acc[3][2]+=w4.w*hv2; acc[3][3]+=w4.w*hv3;
            }
        }
        __syncthreads();
#pragma unroll
        for(int i=0;i<4;i++)
#pragma unroll
            for(int m=0;m<4;m++) gs[v*4+m][u*4+i] = acc[i][m];
        __syncthreads();

        // cell update
        for(int i=tid;i<8*128;i+=256){
            int n=i>>7, j=i&127;
            float ig=gs[n][j], fg=gs[n][128+j], gg=gs[n][256+j], og=gs[n][384+j];
            float cn = sigf(fg)*cs[n][j] + sigf(ig)*tanhf(gg);
            cs[n][j]=cn;
            hs[n][j]=sigf(og)*tanhf(cn);
        }
        __syncthreads();
    }
    for(int i=tid;i<8*128;i+=256)
        g_h[(size_t)(nb + (i>>7))*128 + (i&127)] = hs[i>>7][i&127];
}

// ---------------- output heads: 3 dots per node ----------------
__global__ void k_heads(const float* __restrict__ Wm, const float* __restrict__ bm,
                        const float* __restrict__ Wt, const float* __restrict__ bt,
                        const float* __restrict__ We, const float* __restrict__ be,
                        float* __restrict__ out){
    int n = blockIdx.x;
    int l = threadIdx.x;            // 32
    float sm=0.f, st=0.f, se=0.f;
    for(int j=l;j<128;j+=32){
        float h = g_h[(size_t)n*128 + j];
        sm += h*Wm[j]; st += h*Wt[j]; se += h*We[j];
    }
#pragma unroll
    for(int o=16;o;o>>=1){
        sm += __shfl_down_sync(0xffffffffu, sm, o);
        st += __shfl_down_sync(0xffffffffu, st, o);
        se += __shfl_down_sync(0xffffffffu, se, o);
    }
    if(l==0){
        out[n]            = sm + bm[0];
        out[N_NODES + n]  = st + bt[0];
        out[2*N_NODES + n]= se + be[0];
    }
}

// ---------------- host launcher ----------------
extern "C" void kernel_launch(void* const* d_in, const int* in_sizes, int n_in,
                              void* d_out, int out_size)
{
    const int*   edge  = (const int*)  d_in[0];
    const float* itime = (const float*)d_in[1];
    const float* iev   = (const float*)d_in[2];
    const int*   ann   = (const int*)  d_in[3];
    const float* emb   = (const float*)d_in[4];
    const float* W_in  = (const float*)d_in[5];
    const float* b_in  = (const float*)d_in[6];
    const float* nW1   = (const float*)d_in[7];
    const float* nb1   = (const float*)d_in[8];
    const float* nW2   = (const float*)d_in[9];
    const float* nb2   = (const float*)d_in[10];
    const float* aW1   = (const float*)d_in[11];
    const float* ab1   = (const float*)d_in[12];
    const float* aW2   = (const float*)d_in[13];
    const float* ab2   = (const float*)d_in[14];
    const float* Wih   = (const float*)d_in[15];
    const float* Whh   = (const float*)d_in[16];
    const float* bih   = (const float*)d_in[17];
    const float* bhh   = (const float*)d_in[18];
    const float* Wm    = (const float*)d_in[19];
    const float* bm    = (const float*)d_in[20];
    const float* Wt    = (const float*)d_in[21];
    const float* bt    = (const float*)d_in[22];
    const float* We    = (const float*)d_in[23];
    const float* be    = (const float*)d_in[24];
    float* out = (float*)d_out;

    const int* src = edge;
    const int* dst = edge + NEDGE;

    float *px, *pnf, *ptmp, *pP, *pQ, *pm1, *pm2, *pgates, *pinvdeg, *pbsum;
    cudaGetSymbolAddress((void**)&px,     g_x);
    cudaGetSymbolAddress((void**)&pnf,    g_nf);
    cudaGetSymbolAddress((void**)&ptmp,   g_tmp);
    cudaGetSymbolAddress((void**)&pP,     g_P);
    cudaGetSymbolAddress((void**)&pQ,     g_Q);
    cudaGetSymbolAddress((void**)&pm1,    g_m1);
    cudaGetSymbolAddress((void**)&pm2,    g_m2);
    cudaGetSymbolAddress((void**)&pgates, g_gates);
    cudaGetSymbolAddress((void**)&pinvdeg,g_invdeg);
    cudaGetSymbolAddress((void**)&pbsum,  g_bsum);

    // degrees
    k_zero_deg<<<4,256>>>();
    k_deg<<<(NEDGE+255)/256,256>>>(dst);
    k_fin_deg<<<4,256>>>();

    // input embedding: x -> nf
    k_build_x<<<NS,256>>>(itime, iev, ann, emb);
    k_gemm<0,true,false><<<dim3(NS/64, 128/64),256>>>(px,256, W_in,256, b_in, nullptr, pnf,128, 256);

    for(int l=0; l<2; l++){
        const float* W1 = aW1 + (size_t)l*256*256;
        const float* B1 = ab1 + (size_t)l*256;
        const float* W2 = aW2 + (size_t)l*256*256;
        const float* B2 = ab2 + (size_t)l*256;
        const float* NW1= nW1 + (size_t)l*128*256;
        const float* NB1= nb1 + (size_t)l*128;
        const float* NW2= nW2 + (size_t)l*128*128;
        const float* NB2= nb2 + (size_t)l*128;

        // factored first attention GEMM: P = nf@W1[:, :128]^T, Q = nf@W1[:, 128:]^T
        k_gemm<0,false,false><<<dim3(NS/64, 256/64),256>>>(pnf,128, W1,     256, nullptr, nullptr, pP,256, 128);
        k_gemm<0,false,false><<<dim3(NS/64, 256/64),256>>>(pnf,128, W1+128, 256, nullptr, nullptr, pQ,256, 128);
        k_edge_combine<<<ES,256>>>(src, dst, B1);

        // second attention GEMM (the big one)
        k_gemm<1,true,false><<<dim3(ES/64, 256/64),256>>>(pm1,256, W2,256, B2, nullptr, pm2,256, 256);

        // mean aggregation
        k_zero_agg<<<NS*256/4/256,256>>>();
        k_scatter<<<ES,256>>>(dst);

        // node MLP (agg scaled by 1/deg folded into GEMM epilogue)
        k_gemm<1,true,true ><<<dim3(NS/64, 128/64),256>>>(px,  256, NW1,256, NB1, pinvdeg, ptmp,128, 256);
        k_gemm<1,true,false><<<dim3(NS/64, 128/64),256>>>(ptmp,128, NW2,128, NB2, nullptr, pnf,128, 128);
    }

    // LSTM: precompute input gates for all timesteps, then persistent recurrence
    k_bsum<<<2,256>>>(bih, bhh);
    k_gemm<0,true,false><<<dim3(NS/64, 512/64),256>>>(pnf,128, Wih,128, pbsum, nullptr, pgates,512, 128);
    k_lstm_all<<<128,256>>>(Whh);

    k_heads<<<N_NODES,32>>>(Wm,bm,Wt,bt,We,be,out);
}

// round 2
// speedup vs baseline: 1.6658x; 1.6658x over previous
#include <cuda_runtime.h>
#include <math.h>
#include <stdint.h>

#define N_NODES 1024
#define SEQ     64
#define HID     128
#define NEDGE   4096
#define NS      (N_NODES*SEQ)   /* 65536  */
#define ES      (NEDGE*SEQ)     /* 262144 */

// ---------------- scratch (device globals; no allocation allowed) ----------------
__device__ float g_x[NS*256];        // x, later reused as agg
__device__ float g_nf[NS*128];
__device__ float g_tmp[NS*128];
__device__ float g_P[NS*256];
__device__ float g_Q[NS*256];
__device__ float g_m1[ES*256];
__device__ float g_gates[NS*512];
__device__ float g_invdeg[N_NODES];
__device__ float g_h[N_NODES*HID];
__device__ float g_bsum[512];

// ---------------- small helpers ----------------
__device__ __forceinline__ float eluf(float v){ return v > 0.f ? v : expm1f(v); }
__device__ __forceinline__ float sigf(float v){ return 1.f/(1.f+expf(-v)); }
__device__ __forceinline__ uint32_t f2tf32(float f){
    uint32_t u; asm("cvt.rna.tf32.f32 %0, %1;" : "=r"(u) : "f"(f)); return u;
}
__device__ __forceinline__ void mma_tf32(float4 &d, const uint32_t a[4], const uint32_t b[2]){
    asm volatile("mma.sync.aligned.m16n8k8.row.col.f32.tf32.tf32.f32 "
        "{%0,%1,%2,%3}, {%4,%5,%6,%7}, {%8,%9}, {%0,%1,%2,%3};\n"
        : "+f"(d.x), "+f"(d.y), "+f"(d.z), "+f"(d.w)
        : "r"(a[0]), "r"(a[1]), "r"(a[2]), "r"(a[3]), "r"(b[0]), "r"(b[1]));
}

// ---------------- degree ----------------
__global__ void k_zero_deg(){
    int i = blockIdx.x*blockDim.x + threadIdx.x;
    if(i < N_NODES) g_invdeg[i] = 0.f;
}
__global__ void k_deg(const int* __restrict__ dst){
    int e = blockIdx.x*blockDim.x + threadIdx.x;
    if(e < NEDGE) atomicAdd(&g_invdeg[dst[e]], 1.f);
}
__global__ void k_fin_deg(){
    int i = blockIdx.x*blockDim.x + threadIdx.x;
    if(i < N_NODES){ float d = g_invdeg[i]; g_invdeg[i] = 1.f/fmaxf(d,1.f); }
}
__global__ void k_bsum(const float* __restrict__ bih, const float* __restrict__ bhh){
    int i = blockIdx.x*blockDim.x + threadIdx.x;
    if(i < 512) g_bsum[i] = bih[i] + bhh[i];
}

// ---------------- build x = [emb(127) | events(1) | te(128)] ----------------
__global__ void k_build_x(const float* __restrict__ itime, const float* __restrict__ iev,
                          const int* __restrict__ ann, const float* __restrict__ emb){
    int row = blockIdx.x;        // n*SEQ + s
    int c   = threadIdx.x;       // 0..255
    float t = itime[row];
    float e = iev[row];
    float v;
    if(c < 127){
        v = emb[ann[row]*127 + c];
    } else if(c == 127){
        v = e;
    } else {
        int j = c - 128;
        // 10000^(2*(j/2)/128) = exp2(log2(10000) * (j>>1)/64)
        float pos = exp2f(13.287712379549449f * (float)(j>>1) * (1.0f/64.0f));
        float r = t / pos;
        float te = (j & 1) ? cosf(r) : sinf(r);
        v = (e != 0.f) ? te : 0.f;
    }
    g_x[row*256 + c] = v;
}

// ================= TF32 tensor-core GEMM =================
// C[M,Nc] = act(scale * A@B^T + bias), optionally scatter-atomicAdd rows via dst.
// A [M,K] row-major lda; B [Nc,K] row-major ldb (so B^T is K-major per output col).
// grid = (M/128, Nc/128), block = 256 (8 warps; warp grid 4x2; warp tile 32x64).
// K multiple of 32.
template<int ACT, bool BIAS, bool SCALE, bool SCATTER>
__global__ void __launch_bounds__(256)
k_gemm_tc(const float* __restrict__ A, int lda,
          const float* __restrict__ B, int ldb,
          const float* __restrict__ bias,
          const float* __restrict__ rowscale,
          const int*   __restrict__ dstp,
          float* __restrict__ C, int ldc, int K)
{
    __shared__ uint32_t As[32][132];   // [k][m]
    __shared__ uint32_t Bs[32][132];   // [k][n]
    const int m0 = blockIdx.x*128, n0 = blockIdx.y*128;
    const int tid  = threadIdx.x;
    const int warp = tid >> 5, lane = tid & 31;
    const int wm = (warp >> 1)*32;       // 0,32,64,96
    const int wn = (warp &  1)*64;       // 0,64
    const int qr = lane >> 2, qc = lane & 3;

    float4 acc[2][8];
#pragma unroll
    for(int mi=0;mi<2;mi++)
#pragma unroll
        for(int ni=0;ni<8;ni++) acc[mi][ni] = make_float4(0.f,0.f,0.f,0.f);

    for(int k0=0;k0<K;k0+=32){
        // stage A tile 128x32 and B tile 128x32 (transposed into [k][row], tf32)
#pragma unroll
        for(int it=0;it<4;it++){
            int idx = tid + it*256;          // 0..1023
            int r = idx >> 3;                // 0..127
            int c = (idx & 7)*4;             // 0..28
            float4 va = *(const float4*)&A[(size_t)(m0+r)*lda + k0 + c];
            As[c+0][r]=f2tf32(va.x); As[c+1][r]=f2tf32(va.y);
            As[c+2][r]=f2tf32(va.z); As[c+3][r]=f2tf32(va.w);
            float4 vb = *(const float4*)&B[(size_t)(n0+r)*ldb + k0 + c];
            Bs[c+0][r]=f2tf32(vb.x); Bs[c+1][r]=f2tf32(vb.y);
            Bs[c+2][r]=f2tf32(vb.z); Bs[c+3][r]=f2tf32(vb.w);
        }
        __syncthreads();

#pragma unroll
        for(int kk=0;kk<32;kk+=8){
            uint32_t af[2][4], bf[8][2];
#pragma unroll
            for(int mi=0;mi<2;mi++){
                int mrow = wm + mi*16 + qr;
                af[mi][0] = As[kk+qc  ][mrow  ];
                af[mi][1] = As[kk+qc  ][mrow+8];
                af[mi][2] = As[kk+qc+4][mrow  ];
                af[mi][3] = As[kk+qc+4][mrow+8];
            }
#pragma unroll
            for(int ni=0;ni<8;ni++){
                int ncol = wn + ni*8 + qr;
                bf[ni][0] = Bs[kk+qc  ][ncol];
                bf[ni][1] = Bs[kk+qc+4][ncol];
            }
#pragma unroll
            for(int mi=0;mi<2;mi++)
#pragma unroll
                for(int ni=0;ni<8;ni++)
                    mma_tf32(acc[mi][ni], af[mi], bf[ni]);
        }
        __syncthreads();
    }

    // epilogue
#pragma unroll
    for(int mi=0;mi<2;mi++){
#pragma unroll
        for(int rr=0;rr<2;rr++){
            int row = m0 + wm + mi*16 + qr + rr*8;
            float s = SCALE ? rowscale[row >> 6] : 1.f;   // rows-per-node == SEQ == 64
            size_t crow;
            if(SCATTER){
                int e = row >> 6, ss = row & 63;
                crow = (size_t)(dstp[e]*SEQ + ss)*ldc;
            } else {
                crow = (size_t)row*ldc;
            }
#pragma unroll
            for(int ni=0;ni<8;ni++){
                int col = n0 + wn + ni*8 + qc*2;
                float v0 = (rr==0 ? acc[mi][ni].x : acc[mi][ni].z)*s;
                float v1 = (rr==0 ? acc[mi][ni].y : acc[mi][ni].w)*s;
                if(BIAS){ v0 += bias[col]; v1 += bias[col+1]; }
                if(ACT==1){ v0 = eluf(v0); v1 = eluf(v1); }
                if(SCATTER){
                    atomicAdd(&C[crow + col],   v0);
                    atomicAdd(&C[crow + col+1], v1);
                } else {
                    *(float2*)&C[crow + col] = make_float2(v0,v1);
                }
            }
        }
    }
}

// ---------------- edge combine: m1 = elu(P[src] + Q[dst] + b1) ----------------
__global__ void k_edge_combine(const int* __restrict__ src, const int* __restrict__ dst,
                               const float* __restrict__ b1){
    int row = blockIdx.x;       // e*SEQ + s
    int e = row >> 6, s = row & 63;
    int c = threadIdx.x;
    size_t sr = (size_t)(src[e]*SEQ + s)*256;
    size_t dr = (size_t)(dst[e]*SEQ + s)*256;
    float v = g_P[sr + c] + g_Q[dr + c] + b1[c];
    g_m1[(size_t)row*256 + c] = eluf(v);
}

// ---------------- zero agg (reuses g_x) ----------------
__global__ void k_zero_agg(){
    size_t idx = (size_t)blockIdx.x*blockDim.x + threadIdx.x;
    ((float4*)g_x)[idx] = make_float4(0.f,0.f,0.f,0.f);
}

// ---------------- persistent LSTM (gates precomputed; recurrence only) ----------------
__global__ void __launch_bounds__(256) k_lstm_all(const float* __restrict__ Whh){
    __shared__ float ws[8][516];
    __shared__ float gs[8][512];
    __shared__ float hs[8][128];
    __shared__ float cs[8][128];
    const int tid = threadIdx.x;
    const int nb = blockIdx.x*8;
    const int u = tid & 127;
    const int v = tid >> 7;

    for(int i=tid;i<8*128;i+=256){ hs[i>>7][i&127]=0.f; cs[i>>7][i&127]=0.f; }
    __syncthreads();

    for(int t=0;t<SEQ;t++){
        for(int i=tid;i<8*512;i+=256){
            int n=i>>9, r=i&511;
            gs[n][r] = g_gates[((size_t)(nb+n)*SEQ + t)*512 + r];
        }
        __syncthreads();

        float acc[4][4];
#pragma unroll
        for(int i=0;i<4;i++)
#pragma unroll
            for(int m=0;m<4;m++) acc[i][m] = gs[v*4+m][u*4+i];

        for(int kc=0;kc<128;kc+=8){
            __syncthreads();
            for(int i=tid;i<512*8;i+=256){
                int r=i>>3, c=i&7;
                ws[c][r] = Whh[r*128 + kc + c];
            }
            __syncthreads();
#pragma unroll
            for(int k=0;k<8;k++){
                float4 w4 = *(const float4*)&ws[k][u*4];
                float hv0 = hs[v*4+0][kc+k];
                float hv1 = hs[v*4+1][kc+k];
                float hv2 = hs[v*4+2][kc+k];
                float hv3 = hs[v*4+3][kc+k];
                acc[0][0]+=w4.x*hv0; acc[0][1]+=w4.x*hv1; acc[0][2]+=w4.x*hv2; acc[0][3]+=w4.x*hv3;
                acc[1][0]+=w4.y*hv0; acc[1][1]+=w4.y*hv1; acc[1][2]+=w4.y*hv2; acc[1][3]+=w4.y*hv3;
                acc[2][0]+=w4.z*hv0; acc[2][1]+=w4.z*hv1; acc[2][2]+=w4.z*hv2; acc[2][3]+=w4.z*hv3;
                acc[3][0]+=w4.w*hv0; acc[3][1]+=w4.w*hv1; acc[3][2]+=w4.w*hv2; acc[3][3]+=w4.w*hv3;
            }
        }
        __syncthreads();
#pragma unroll
        for(int i=0;i<4;i++)
#pragma unroll
            for(int m=0;m<4;m++) gs[v*4+m][u*4+i] = acc[i][m];
        __syncthreads();

        for(int i=tid;i<8*128;i+=256){
            int n=i>>7, j=i&127;
            float ig=gs[n][j], fg=gs[n][128+j], gg=gs[n][256+j], og=gs[n][384+j];
            float cn = sigf(fg)*cs[n][j] + sigf(ig)*tanhf(gg);
            cs[n][j]=cn;
            hs[n][j]=sigf(og)*tanhf(cn);
        }
        __syncthreads();
    }
    for(int i=tid;i<8*128;i+=256)
        g_h[(size_t)(nb + (i>>7))*128 + (i&127)] = hs[i>>7][i&127];
}

// ---------------- output heads ----------------
__global__ void k_heads(const float* __restrict__ Wm, const float* __restrict__ bm,
                        const float* __restrict__ Wt, const float* __restrict__ bt,
                        const float* __restrict__ We, const float* __restrict__ be,
                        float* __restrict__ out){
    int n = blockIdx.x;
    int l = threadIdx.x;
    float sm=0.f, st=0.f, se=0.f;
    for(int j=l;j<128;j+=32){
        float h = g_h[(size_t)n*128 + j];
        sm += h*Wm[j]; st += h*Wt[j]; se += h*We[j];
    }
#pragma unroll
    for(int o=16;o;o>>=1){
        sm += __shfl_down_sync(0xffffffffu, sm, o);
        st += __shfl_down_sync(0xffffffffu, st, o);
        se += __shfl_down_sync(0xffffffffu, se, o);
    }
    if(l==0){
        out[n]            = sm + bm[0];
        out[N_NODES + n]  = st + bt[0];
        out[2*N_NODES + n]= se + be[0];
    }
}

// ---------------- host launcher ----------------
extern "C" void kernel_launch(void* const* d_in, const int* in_sizes, int n_in,
                              void* d_out, int out_size)
{
    const int*   edge  = (const int*)  d_in[0];
    const float* itime = (const float*)d_in[1];
    const float* iev   = (const float*)d_in[2];
    const int*   ann   = (const int*)  d_in[3];
    const float* emb   = (const float*)d_in[4];
    const float* W_in  = (const float*)d_in[5];
    const float* b_in  = (const float*)d_in[6];
    const float* nW1   = (const float*)d_in[7];
    const float* nb1   = (const float*)d_in[8];
    const float* nW2   = (const float*)d_in[9];
    const float* nb2   = (const float*)d_in[10];
    const float* aW1   = (const float*)d_in[11];
    const float* ab1   = (const float*)d_in[12];
    const float* aW2   = (const float*)d_in[13];
    const float* ab2   = (const float*)d_in[14];
    const float* Wih   = (const float*)d_in[15];
    const float* Whh   = (const float*)d_in[16];
    const float* bih   = (const float*)d_in[17];
    const float* bhh   = (const float*)d_in[18];
    const float* Wm    = (const float*)d_in[19];
    const float* bm    = (const float*)d_in[20];
    const float* Wt    = (const float*)d_in[21];
    const float* bt    = (const float*)d_in[22];
    const float* We    = (const float*)d_in[23];
    const float* be    = (const float*)d_in[24];
    float* out = (float*)d_out;

    const int* src = edge;
    const int* dst = edge + NEDGE;

    float *px, *pnf, *ptmp, *pP, *pQ, *pm1, *pgates, *pinvdeg, *pbsum;
    cudaGetSymbolAddress((void**)&px,     g_x);
    cudaGetSymbolAddress((void**)&pnf,    g_nf);
    cudaGetSymbolAddress((void**)&ptmp,   g_tmp);
    cudaGetSymbolAddress((void**)&pP,     g_P);
    cudaGetSymbolAddress((void**)&pQ,     g_Q);
    cudaGetSymbolAddress((void**)&pm1,    g_m1);
    cudaGetSymbolAddress((void**)&pgates, g_gates);
    cudaGetSymbolAddress((void**)&pinvdeg,g_invdeg);
    cudaGetSymbolAddress((void**)&pbsum,  g_bsum);

    // degrees
    k_zero_deg<<<4,256>>>();
    k_deg<<<(NEDGE+255)/256,256>>>(dst);
    k_fin_deg<<<4,256>>>();

    // input embedding: x -> nf
    k_build_x<<<NS,256>>>(itime, iev, ann, emb);
    k_gemm_tc<0,true,false,false><<<dim3(NS/128, 1),256>>>(px,256, W_in,256, b_in, nullptr, nullptr, pnf,128, 256);

    for(int l=0; l<2; l++){
        const float* W1 = aW1 + (size_t)l*256*256;
        const float* B1 = ab1 + (size_t)l*256;
        const float* W2 = aW2 + (size_t)l*256*256;
        const float* B2 = ab2 + (size_t)l*256;
        const float* NW1= nW1 + (size_t)l*128*256;
        const float* NB1= nb1 + (size_t)l*128;
        const float* NW2= nW2 + (size_t)l*128*128;
        const float* NB2= nb2 + (size_t)l*128;

        // factored first attention GEMM: P = nf@W1[:, :128]^T, Q = nf@W1[:, 128:]^T
        k_gemm_tc<0,false,false,false><<<dim3(NS/128, 2),256>>>(pnf,128, W1,     256, nullptr, nullptr, nullptr, pP,256, 128);
        k_gemm_tc<0,false,false,false><<<dim3(NS/128, 2),256>>>(pnf,128, W1+128, 256, nullptr, nullptr, nullptr, pQ,256, 128);
        k_edge_combine<<<ES,256>>>(src, dst, B1);

        // zero agg, then big edge GEMM with fused elu + scatter-add into agg
        k_zero_agg<<<NS*256/4/256,256>>>();
        k_gemm_tc<1,true,false,true><<<dim3(ES/128, 2),256>>>(pm1,256, W2,256, B2, nullptr, dst, px,256, 256);

        // node MLP (mean scaling folded into GEMM epilogue)
        k_gemm_tc<1,true,true ,false><<<dim3(NS/128, 1),256>>>(px,  256, NW1,256, NB1, pinvdeg, nullptr, ptmp,128, 256);
        k_gemm_tc<1,true,false,false><<<dim3(NS/128, 1),256>>>(ptmp,128, NW2,128, NB2, nullptr, nullptr, pnf,128, 128);
    }

    // LSTM: precompute input gates for all timesteps, then persistent recurrence
    k_bsum<<<2,256>>>(bih, bhh);
    k_gemm_tc<0,true,false,false><<<dim3(NS/128, 4),256>>>(pnf,128, Wih,128, pbsum, nullptr, nullptr, pgates,512, 128);
    k_lstm_all<<<128,256>>>(Whh);

    k_heads<<<N_NODES,32>>>(Wm,bm,Wt,bt,We,be,out);
}

// round 3
// speedup vs baseline: 2.1228x; 1.2743x over previous
#include <cuda_runtime.h>
#include <cuda_fp16.h>
#include <math.h>
#include <stdint.h>

#define N_NODES 1024
#define SEQ     64
#define NEDGE   4096
#define NS      (N_NODES*SEQ)   /* 65536  */
#define ES      (NEDGE*SEQ)     /* 262144 */

// ---------------- scratch (device globals) ----------------
__device__ float g_x[NS*256];        // x, later reused as agg
__device__ float g_nf[NS*128];
__device__ float g_tmp[NS*128];
__device__ float g_PQ[NS*512];       // [P | Q] per row
__device__ float g_gates[NS*512];
__device__ float g_W1p[512*128];     // repacked attn W1
__device__ float g_invdeg[N_NODES];
__device__ float g_h[N_NODES*128];
__device__ float g_bsum[512];

// ---------------- helpers ----------------
__device__ __forceinline__ float eluf(float v){ return v > 0.f ? v : expm1f(v); }
__device__ __forceinline__ float sigf(float v){ return 1.f/(1.f+expf(-v)); }
__device__ __forceinline__ uint32_t f2h2(float lo, float hi){
    __half2 h = __floats2half2_rn(lo, hi);
    return *(uint32_t*)&h;
}
__device__ __forceinline__ void mma16(float4 &d, const uint32_t a[4], uint32_t b0, uint32_t b1){
    asm volatile("mma.sync.aligned.m16n8k16.row.col.f32.f16.f16.f32 "
        "{%0,%1,%2,%3}, {%4,%5,%6,%7}, {%8,%9}, {%0,%1,%2,%3};\n"
        : "+f"(d.x), "+f"(d.y), "+f"(d.z), "+f"(d.w)
        : "r"(a[0]), "r"(a[1]), "r"(a[2]), "r"(a[3]), "r"(b0), "r"(b1));
}
__device__ __forceinline__ void ldsm4(uint32_t &r0, uint32_t &r1, uint32_t &r2, uint32_t &r3, uint32_t addr){
    asm volatile("ldmatrix.sync.aligned.m8n8.x4.shared.b16 {%0,%1,%2,%3}, [%4];"
        : "=r"(r0), "=r"(r1), "=r"(r2), "=r"(r3) : "r"(addr));
}
// swizzled 16B-atom byte offset for a 128-row x 32-col fp16 tile packed 2 rows / 128B
__device__ __forceinline__ int swatom(int r, int katom){
    return (r>>1)*128 + ((((r&1)*4 + katom) ^ ((r>>1)&7))<<4);
}

// ---------------- degree / misc ----------------
__global__ void k_zero_deg(){
    int i = blockIdx.x*blockDim.x + threadIdx.x;
    if(i < N_NODES) g_invdeg[i] = 0.f;
}
__global__ void k_deg(const int* __restrict__ dst){
    int e = blockIdx.x*blockDim.x + threadIdx.x;
    if(e < NEDGE) atomicAdd(&g_invdeg[dst[e]], 1.f);
}
__global__ void k_fin_deg(){
    int i = blockIdx.x*blockDim.x + threadIdx.x;
    if(i < N_NODES){ float d = g_invdeg[i]; g_invdeg[i] = 1.f/fmaxf(d,1.f); }
}
__global__ void k_bsum(const float* __restrict__ bih, const float* __restrict__ bhh){
    int i = blockIdx.x*blockDim.x + threadIdx.x;
    if(i < 512) g_bsum[i] = bih[i] + bhh[i];
}
// repack W1 [256 out,256 in] -> [512,128]: rows 0..255 = W1[:, :128], rows 256..511 = W1[:, 128:]
__global__ void k_packW1(const float* __restrict__ W1){
    int i = blockIdx.x*256 + threadIdx.x;   // 0..65535
    int o = i >> 8, k = i & 255;
    float v = W1[i];
    if(k < 128) g_W1p[o*128 + k] = v;
    else        g_W1p[(256+o)*128 + (k-128)] = v;
}

// ---------------- build x = [emb(127) | events(1) | te(128)] ----------------
__global__ void k_build_x(const float* __restrict__ itime, const float* __restrict__ iev,
                          const int* __restrict__ ann, const float* __restrict__ emb){
    int row = blockIdx.x;        // n*SEQ + s
    int c   = threadIdx.x;       // 0..255
    float t = itime[row];
    float e = iev[row];
    float v;
    if(c < 127){
        v = emb[ann[row]*127 + c];
    } else if(c == 127){
        v = e;
    } else {
        int j = c - 128;
        float pos = exp2f(13.287712379549449f * (float)(j>>1) * (1.0f/64.0f));
        float r = t / pos;
        float te = (j & 1) ? cosf(r) : sinf(r);
        v = (e != 0.f) ? te : 0.f;
    }
    g_x[row*256 + c] = v;
}

// ================= FP16 tensor-core GEMM (ldmatrix + double buffer) =================
// C[M,Nc] = act(scale * A@B^T + bias); A rows optionally built on the fly from edges
// (EDGEA: A[e*64+s][k] = elu(P[src[e]*64+s][k] + Q[dst[e]*64+s][k] + b1[k])).
// A [M,K] lda; B [Nc,K] ldb. grid=(M/128, Nc/128), block=256 (8 warps, warp tile 32x64).
// K multiple of 32.

template<bool EDGEA>
__device__ __forceinline__ void load_tile(
    uint2 ra[4], uint2 rb[4], int tid, int m0, int n0, int k0,
    const float* __restrict__ A, int lda,
    const float* __restrict__ PQ, const int* __restrict__ srcp, const int* __restrict__ dstp,
    const float* __restrict__ b1,
    const float* __restrict__ B, int ldb)
{
#pragma unroll
    for(int it=0; it<4; it++){
        int idx = tid + it*256;
        int r = idx >> 3;            // 0..127
        int c = (idx & 7) * 4;       // 0..28
        float4 v;
        if(EDGEA){
            int grow = m0 + r;
            int e = grow >> 6, srow = grow & 63;
            int se = __ldg(&srcp[e]);
            int de = __ldg(&dstp[e]);
            float4 p  = *(const float4*)&PQ[((size_t)se*64 + srow)*512 + k0 + c];
            float4 q  = *(const float4*)&PQ[((size_t)de*64 + srow)*512 + 256 + k0 + c];
            float4 bb = *(const float4*)&b1[k0 + c];
            v.x = eluf(p.x + q.x + bb.x);
            v.y = eluf(p.y + q.y + bb.y);
            v.z = eluf(p.z + q.z + bb.z);
            v.w = eluf(p.w + q.w + bb.w);
        } else {
            v = *(const float4*)&A[(size_t)(m0 + r)*lda + k0 + c];
        }
        ra[it] = make_uint2(f2h2(v.x, v.y), f2h2(v.z, v.w));
        float4 w = *(const float4*)&B[(size_t)(n0 + r)*ldb + k0 + c];
        rb[it] = make_uint2(f2h2(w.x, w.y), f2h2(w.z, w.w));
    }
}

__device__ __forceinline__ void store_tile(char* sA, char* sB, int tid,
                                           const uint2 ra[4], const uint2 rb[4])
{
#pragma unroll
    for(int it=0; it<4; it++){
        int idx = tid + it*256;
        int r = idx >> 3;
        int c = (idx & 7) * 4;
        int off = swatom(r, c>>3) + ((c & 7) * 2);   // 8B-aligned
        *(uint2*)(sA + off) = ra[it];
        *(uint2*)(sB + off) = rb[it];
    }
}

template<int ACT, bool BIAS, bool SCALE, bool SCATTER, bool EDGEA>
__global__ void __launch_bounds__(256)
k_gemm(const float* __restrict__ A, int lda,
       const float* __restrict__ PQ, const int* __restrict__ srcp,
       const float* __restrict__ b1,
       const float* __restrict__ B, int ldb,
       const float* __restrict__ bias, const float* __restrict__ rowscale,
       const int*   __restrict__ dstp,
       float* __restrict__ C, int ldc, int K)
{
    __shared__ __align__(16) char sm[2*16384];   // [stage][A 8KB | B 8KB]
    const int m0 = blockIdx.x*128, n0 = blockIdx.y*128;
    const int tid  = threadIdx.x;
    const int warp = tid >> 5, lane = tid & 31;
    const int wm = (warp >> 1)*32;       // 0,32,64,96
    const int wn = (warp &  1)*64;       // 0,64
    const int qr = lane >> 2, qc = lane & 3;
    const uint32_t smbase = (uint32_t)__cvta_generic_to_shared(sm);

    // per-lane ldmatrix address components
    const int j  = lane >> 3, rl = lane & 7;
    const int aj = j >> 1;               // A k-atom offset from matrix id
    const int bj = j & 1;                // B k-atom offset from matrix id
    int abase[2], asw[2], amb[2];
#pragma unroll
    for(int mi=0; mi<2; mi++){
        int m = wm + mi*16 + (j&1)*8 + rl;
        abase[mi] = (m>>1)*128; asw[mi] = (m>>1)&7; amb[mi] = (m&1)*4;
    }
    int bbase[4], bsw[4], bmb[4];
#pragma unroll
    for(int p=0; p<4; p++){
        int n = wn + p*16 + (j>>1)*8 + rl;
        bbase[p] = (n>>1)*128; bsw[p] = (n>>1)&7; bmb[p] = (n&1)*4;
    }

    float4 acc[2][8];
#pragma unroll
    for(int mi=0;mi<2;mi++)
#pragma unroll
        for(int ni=0;ni<8;ni++) acc[mi][ni] = make_float4(0.f,0.f,0.f,0.f);

    const int S = K >> 5;
    uint2 ra[4], rb[4];
    load_tile<EDGEA>(ra, rb, tid, m0, n0, 0, A, lda, PQ, srcp, dstp, b1, B, ldb);
    store_tile(sm, sm+8192, tid, ra, rb);
    __syncthreads();

    for(int s=0; s<S; s++){
        if(s+1 < S)
            load_tile<EDGEA>(ra, rb, tid, m0, n0, (s+1)<<5, A, lda, PQ, srcp, dstp, b1, B, ldb);

        uint32_t sAa = smbase + (s&1)*16384;
        uint32_t sBa = sAa + 8192;
#pragma unroll
        for(int kh=0; kh<2; kh++){
            int ka = kh*2;   // k-atom base for this 16-K step
            uint32_t a[2][4];
#pragma unroll
            for(int mi=0; mi<2; mi++){
                uint32_t addr = sAa + abase[mi] + ((((amb[mi] + ka + aj) ^ asw[mi]))<<4);
                ldsm4(a[mi][0], a[mi][1], a[mi][2], a[mi][3], addr);
            }
#pragma unroll
            for(int p=0; p<4; p++){
                uint32_t b0,b1r,b2,b3;
                uint32_t addr = sBa + bbase[p] + ((((bmb[p] + ka + bj) ^ bsw[p]))<<4);
                ldsm4(b0, b1r, b2, b3, addr);
                mma16(acc[0][2*p  ], a[0], b0, b1r);
                mma16(acc[0][2*p+1], a[0], b2, b3);
                mma16(acc[1][2*p  ], a[1], b0, b1r);
                mma16(acc[1][2*p+1], a[1], b2, b3);
            }
        }
        if(s+1 < S){
            store_tile(sm + ((s+1)&1)*16384, sm + ((s+1)&1)*16384 + 8192, tid, ra, rb);
            __syncthreads();
        }
    }

    // epilogue
#pragma unroll
    for(int mi=0; mi<2; mi++){
#pragma unroll
        for(int rr=0; rr<2; rr++){
            int row = m0 + wm + mi*16 + qr + rr*8;
            float sc = SCALE ? rowscale[row >> 6] : 1.f;   // rows-per-node == SEQ == 64
            size_t crow;
            if(SCATTER){
                int e = row >> 6, ss = row & 63;
                crow = (size_t)(dstp[e]*SEQ + ss)*ldc;
            } else {
                crow = (size_t)row*ldc;
            }
#pragma unroll
            for(int ni=0; ni<8; ni++){
                int col = n0 + wn + ni*8 + qc*2;
                float v0 = (rr==0 ? acc[mi][ni].x : acc[mi][ni].z)*sc;
                float v1 = (rr==0 ? acc[mi][ni].y : acc[mi][ni].w)*sc;
                if(BIAS){ v0 += bias[col]; v1 += bias[col+1]; }
                if(ACT==1){ v0 = eluf(v0); v1 = eluf(v1); }
                if(SCATTER){
                    atomicAdd(&C[crow + col],   v0);
                    atomicAdd(&C[crow + col+1], v1);
                } else {
                    *(float2*)&C[crow + col] = make_float2(v0, v1);
                }
            }
        }
    }
}

// ---------------- persistent LSTM (gates precomputed; recurrence only) ----------------
__global__ void __launch_bounds__(256) k_lstm_all(const float* __restrict__ Whh){
    __shared__ float ws[8][516];
    __shared__ float gs[8][512];
    __shared__ float hs[8][128];
    __shared__ float cs[8][128];
    const int tid = threadIdx.x;
    const int nb = blockIdx.x*8;
    const int u = tid & 127;
    const int v = tid >> 7;

    for(int i=tid;i<8*128;i+=256){ hs[i>>7][i&127]=0.f; cs[i>>7][i&127]=0.f; }
    __syncthreads();

    for(int t=0;t<SEQ;t++){
        for(int i=tid;i<8*512;i+=256){
            int n=i>>9, r=i&511;
            gs[n][r] = g_gates[((size_t)(nb+n)*SEQ + t)*512 + r];
        }
        __syncthreads();

        float acc[4][4];
#pragma unroll
        for(int i=0;i<4;i++)
#pragma unroll
            for(int m=0;m<4;m++) acc[i][m] = gs[v*4+m][u*4+i];

        for(int kc=0;kc<128;kc+=8){
            __syncthreads();
            for(int i=tid;i<512*8;i+=256){
                int r=i>>3, c=i&7;
                ws[c][r] = Whh[r*128 + kc + c];
            }
            __syncthreads();
#pragma unroll
            for(int k=0;k<8;k++){
                float4 w4 = *(const float4*)&ws[k][u*4];
                float hv0 = hs[v*4+0][kc+k];
                float hv1 = hs[v*4+1][kc+k];
                float hv2 = hs[v*4+2][kc+k];
                float hv3 = hs[v*4+3][kc+k];
                acc[0][0]+=w4.x*hv0; acc[0][1]+=w4.x*hv1; acc[0][2]+=w4.x*hv2; acc[0][3]+=w4.x*hv3;
                acc[1][0]+=w4.y*hv0; acc[1][1]+=w4.y*hv1; acc[1][2]+=w4.y*hv2; acc[1][3]+=w4.y*hv3;
                acc[2][0]+=w4.z*hv0; acc[2][1]+=w4.z*hv1; acc[2][2]+=w4.z*hv2; acc[2][3]+=w4.z*hv3;
                acc[3][0]+=w4.w*hv0; acc[3][1]+=w4.w*hv1; acc[3][2]+=w4.w*hv2; acc[3][3]+=w4.w*hv3;
            }
        }
        __syncthreads();
#pragma unroll
        for(int i=0;i<4;i++)
#pragma unroll
            for(int m=0;m<4;m++) gs[v*4+m][u*4+i] = acc[i][m];
        __syncthreads();

        for(int i=tid;i<8*128;i+=256){
            int n=i>>7, jj=i&127;
            float ig=gs[n][jj], fg=gs[n][128+jj], gg=gs[n][256+jj], og=gs[n][384+jj];
            float cn = sigf(fg)*cs[n][jj] + sigf(ig)*tanhf(gg);
            cs[n][jj]=cn;
            hs[n][jj]=sigf(og)*tanhf(cn);
        }
        __syncthreads();
    }
    for(int i=tid;i<8*128;i+=256)
        g_h[(size_t)(nb + (i>>7))*128 + (i&127)] = hs[i>>7][i&127];
}

// ---------------- output heads ----------------
__global__ void k_heads(const float* __restrict__ Wm, const float* __restrict__ bm,
                        const float* __restrict__ Wt, const float* __restrict__ bt,
                        const float* __restrict__ We, const float* __restrict__ be,
                        float* __restrict__ out){
    int n = blockIdx.x;
    int l = threadIdx.x;
    float sm=0.f, st=0.f, se=0.f;
    for(int jj=l;jj<128;jj+=32){
        float h = g_h[(size_t)n*128 + jj];
        sm += h*Wm[jj]; st += h*Wt[jj]; se += h*We[jj];
    }
#pragma unroll
    for(int o=16;o;o>>=1){
        sm += __shfl_down_sync(0xffffffffu, sm, o);
        st += __shfl_down_sync(0xffffffffu, st, o);
        se += __shfl_down_sync(0xffffffffu, se, o);
    }
    if(l==0){
        out[n]            = sm + bm[0];
        out[N_NODES + n]  = st + bt[0];
        out[2*N_NODES + n]= se + be[0];
    }
}

// ---------------- host launcher ----------------
extern "C" void kernel_launch(void* const* d_in, const int* in_sizes, int n_in,
                              void* d_out, int out_size)
{
    const int*   edge  = (const int*)  d_in[0];
    const float* itime = (const float*)d_in[1];
    const float* iev   = (const float*)d_in[2];
    const int*   ann   = (const int*)  d_in[3];
    const float* emb   = (const float*)d_in[4];
    const float* W_in  = (const float*)d_in[5];
    const float* b_in  = (const float*)d_in[6];
    const float* nW1   = (const float*)d_in[7];
    const float* nb1   = (const float*)d_in[8];
    const float* nW2   = (const float*)d_in[9];
    const float* nb2   = (const float*)d_in[10];
    const float* aW1   = (const float*)d_in[11];
    const float* ab1   = (const float*)d_in[12];
    const float* aW2   = (const float*)d_in[13];
    const float* ab2   = (const float*)d_in[14];
    const float* Wih   = (const float*)d_in[15];
    const float* Whh   = (const float*)d_in[16];
    const float* bih   = (const float*)d_in[17];
    const float* bhh   = (const float*)d_in[18];
    const float* Wm    = (const float*)d_in[19];
    const float* bm    = (const float*)d_in[20];
    const float* Wt    = (const float*)d_in[21];
    const float* bt    = (const float*)d_in[22];
    const float* We    = (const float*)d_in[23];
    const float* be    = (const float*)d_in[24];
    float* out = (float*)d_out;

    const int* src = edge;
    const int* dst = edge + NEDGE;

    float *px, *pnf, *ptmp, *pPQ, *pW1p, *pgates, *pinvdeg, *pbsum;
    cudaGetSymbolAddress((void**)&px,     g_x);
    cudaGetSymbolAddress((void**)&pnf,    g_nf);
    cudaGetSymbolAddress((void**)&ptmp,   g_tmp);
    cudaGetSymbolAddress((void**)&pPQ,    g_PQ);
    cudaGetSymbolAddress((void**)&pW1p,   g_W1p);
    cudaGetSymbolAddress((void**)&pgates, g_gates);
    cudaGetSymbolAddress((void**)&pinvdeg,g_invdeg);
    cudaGetSymbolAddress((void**)&pbsum,  g_bsum);

    // degrees
    k_zero_deg<<<4,256>>>();
    k_deg<<<(NEDGE+255)/256,256>>>(dst);
    k_fin_deg<<<4,256>>>();

    // input embedding: x -> nf
    k_build_x<<<NS,256>>>(itime, iev, ann, emb);
    k_gemm<0,true,false,false,false><<<dim3(NS/128,1),256>>>(
        px,256, nullptr,nullptr,nullptr, W_in,256, b_in, nullptr, nullptr, pnf,128, 256);

    for(int l=0; l<2; l++){
        const float* W1 = aW1 + (size_t)l*256*256;
        const float* B1 = ab1 + (size_t)l*256;
        const float* W2 = aW2 + (size_t)l*256*256;
        const float* B2 = ab2 + (size_t)l*256;
        const float* NW1= nW1 + (size_t)l*128*256;
        const float* NB1= nb1 + (size_t)l*128;
        const float* NW2= nW2 + (size_t)l*128*128;
        const float* NB2= nb2 + (size_t)l*128;

        // repack W1, then one GEMM producing [P|Q] = nf @ W1p^T  -> [NS,512]
        k_packW1<<<256,256>>>(W1);
        k_gemm<0,false,false,false,false><<<dim3(NS/128,4),256>>>(
            pnf,128, nullptr,nullptr,nullptr, pW1p,128, nullptr, nullptr, nullptr, pPQ,512, 128);

        // zero agg, then fused edge GEMM:
        // A built on the fly = elu(P[src]+Q[dst]+b1); epilogue elu + scatter-add into agg
        cudaMemsetAsync(px, 0, (size_t)NS*256*sizeof(float));
        k_gemm<1,true,false,true,true><<<dim3(ES/128,2),256>>>(
            nullptr,0, pPQ, src, B1, W2,256, B2, nullptr, dst, px,256, 256);

        // node MLP (mean scaling folded into GEMM epilogue)
        k_gemm<1,true,true,false,false><<<dim3(NS/128,1),256>>>(
            px,256, nullptr,nullptr,nullptr, NW1,256, NB1, pinvdeg, nullptr, ptmp,128, 256);
        k_gemm<1,true,false,false,false><<<dim3(NS/128,1),256>>>(
            ptmp,128, nullptr,nullptr,nullptr, NW2,128, NB2, nullptr, nullptr, pnf,128, 128);
    }

    // LSTM: precompute input gates for all timesteps, then persistent recurrence
    k_bsum<<<2,256>>>(bih, bhh);
    k_gemm<0,true,false,false,false><<<dim3(NS/128,4),256>>>(
        pnf,128, nullptr,nullptr,nullptr, Wih,128, pbsum, nullptr, nullptr, pgates,512, 128);
    k_lstm_all<<<128,256>>>(Whh);

    k_heads<<<N_NODES,32>>>(Wm,bm,Wt,bt,We,be,out);
}

// round 4
// speedup vs baseline: 2.3424x; 1.1035x over previous
#include <cuda_runtime.h>
#include <cuda_fp16.h>
#include <math.h>
#include <stdint.h>

#define N_NODES 1024
#define SEQ     64
#define NEDGE   4096
#define NS      (N_NODES*SEQ)   /* 65536  */
#define ES      (NEDGE*SEQ)     /* 262144 */

// ---------------- scratch (device globals) ----------------
__device__ float  g_x[NS*256];        // x, later reused as agg
__device__ float  g_nf[NS*128];
__device__ float  g_tmp[NS*128];
__device__ __half g_PQh[NS*512];      // [P | Q] per row, fp16
__device__ float  g_gates[NS*512];
__device__ float  g_W1p[512*128];     // repacked attn W1
__device__ float  g_invdeg[N_NODES];
__device__ float  g_h[N_NODES*128];
__device__ float  g_bsum[512];

// ---------------- helpers ----------------
__device__ __forceinline__ float eluf(float v){ return v > 0.f ? v : (__expf(v) - 1.f); }
__device__ __forceinline__ float sigf(float v){ return 1.f/(1.f+__expf(-v)); }
__device__ __forceinline__ float tanhfast(float v){
    // tanh(x) = 1 - 2/(exp(2x)+1)
    return 1.f - 2.f/(__expf(2.f*v)+1.f);
}
__device__ __forceinline__ uint32_t f2h2(float lo, float hi){
    __half2 h = __floats2half2_rn(lo, hi);
    return *(uint32_t*)&h;
}
__device__ __forceinline__ void mma16(float4 &d, const uint32_t a[4], uint32_t b0, uint32_t b1){
    asm volatile("mma.sync.aligned.m16n8k16.row.col.f32.f16.f16.f32 "
        "{%0,%1,%2,%3}, {%4,%5,%6,%7}, {%8,%9}, {%0,%1,%2,%3};\n"
        : "+f"(d.x), "+f"(d.y), "+f"(d.z), "+f"(d.w)
        : "r"(a[0]), "r"(a[1]), "r"(a[2]), "r"(a[3]), "r"(b0), "r"(b1));
}
__device__ __forceinline__ void ldsm4(uint32_t &r0, uint32_t &r1, uint32_t &r2, uint32_t &r3, uint32_t addr){
    asm volatile("ldmatrix.sync.aligned.m8n8.x4.shared.b16 {%0,%1,%2,%3}, [%4];"
        : "=r"(r0), "=r"(r1), "=r"(r2), "=r"(r3) : "r"(addr));
}
// swizzled 16B-atom byte offset, 2 rows per 128B line, 4 k-atoms (16B) per row
__device__ __forceinline__ int swatom(int r, int katom){
    return (r>>1)*128 + ((((r&1)*4 + katom) ^ ((r>>1)&7))<<4);
}

// ---------------- degree / misc ----------------
__global__ void k_zero_deg(){
    int i = blockIdx.x*blockDim.x + threadIdx.x;
    if(i < N_NODES) g_invdeg[i] = 0.f;
}
__global__ void k_deg(const int* __restrict__ dst){
    int e = blockIdx.x*blockDim.x + threadIdx.x;
    if(e < NEDGE) atomicAdd(&g_invdeg[dst[e]], 1.f);
}
__global__ void k_fin_deg(){
    int i = blockIdx.x*blockDim.x + threadIdx.x;
    if(i < N_NODES){ float d = g_invdeg[i]; g_invdeg[i] = 1.f/fmaxf(d,1.f); }
}
__global__ void k_bsum(const float* __restrict__ bih, const float* __restrict__ bhh){
    int i = blockIdx.x*blockDim.x + threadIdx.x;
    if(i < 512) g_bsum[i] = bih[i] + bhh[i];
}
// repack W1 [256,256] -> [512,128]
__global__ void k_packW1(const float* __restrict__ W1){
    int i = blockIdx.x*256 + threadIdx.x;
    int o = i >> 8, k = i & 255;
    float v = W1[i];
    if(k < 128) g_W1p[o*128 + k] = v;
    else        g_W1p[(256+o)*128 + (k-128)] = v;
}

// ---------------- build x = [emb(127) | events(1) | te(128)] ----------------
__global__ void k_build_x(const float* __restrict__ itime, const float* __restrict__ iev,
                          const int* __restrict__ ann, const float* __restrict__ emb){
    int row = blockIdx.x;
    int c   = threadIdx.x;
    float t = itime[row];
    float e = iev[row];
    float v;
    if(c < 127){
        v = emb[ann[row]*127 + c];
    } else if(c == 127){
        v = e;
    } else {
        int j = c - 128;
        float pos = exp2f(13.287712379549449f * (float)(j>>1) * (1.0f/64.0f));
        float r = t / pos;
        float te = (j & 1) ? __cosf(r) : __sinf(r);
        v = (e != 0.f) ? te : 0.f;
    }
    g_x[row*256 + c] = v;
}

// ================= generic FP16 tensor-core GEMM =================
// C[M,Nc] = act(scale * A@B^T + bias). grid=(M/128, Nc/128), 256 thr, warp tile 32x64.
__device__ __forceinline__ void load_tile_g(
    uint2 ra[4], uint2 rb[4], int tid, int m0, int n0, int k0,
    const float* __restrict__ A, int lda,
    const float* __restrict__ B, int ldb)
{
#pragma unroll
    for(int it=0; it<4; it++){
        int idx = tid + it*256;
        int r = idx >> 3;            // 0..127
        int c = (idx & 7) * 4;       // 0..28
        float4 v = *(const float4*)&A[(size_t)(m0 + r)*lda + k0 + c];
        ra[it] = make_uint2(f2h2(v.x, v.y), f2h2(v.z, v.w));
        float4 w = *(const float4*)&B[(size_t)(n0 + r)*ldb + k0 + c];
        rb[it] = make_uint2(f2h2(w.x, w.y), f2h2(w.z, w.w));
    }
}
__device__ __forceinline__ void store_tile_g(char* sA, char* sB, int tid,
                                             const uint2 ra[4], const uint2 rb[4])
{
#pragma unroll
    for(int it=0; it<4; it++){
        int idx = tid + it*256;
        int r = idx >> 3;
        int c = (idx & 7) * 4;
        int off = swatom(r, c>>3) + ((c & 7) * 2);
        *(uint2*)(sA + off) = ra[it];
        *(uint2*)(sB + off) = rb[it];
    }
}

template<int ACT, bool BIAS, bool SCALE, bool OUTH>
__global__ void __launch_bounds__(256)
k_gemm(const float* __restrict__ A, int lda,
       const float* __restrict__ B, int ldb,
       const float* __restrict__ bias, const float* __restrict__ rowscale,
       float* __restrict__ C, int ldc, int K)
{
    __shared__ __align__(16) char sm[2*16384];
    const int m0 = blockIdx.x*128, n0 = blockIdx.y*128;
    const int tid  = threadIdx.x;
    const int warp = tid >> 5, lane = tid & 31;
    const int wm = (warp >> 1)*32;
    const int wn = (warp &  1)*64;
    const int qr = lane >> 2, qc = lane & 3;
    const uint32_t smbase = (uint32_t)__cvta_generic_to_shared(sm);

    const int j  = lane >> 3, rl = lane & 7;
    const int aj = j >> 1;
    const int bj = j & 1;
    int abase[2], asw[2], amb[2];
#pragma unroll
    for(int mi=0; mi<2; mi++){
        int m = wm + mi*16 + (j&1)*8 + rl;
        abase[mi] = (m>>1)*128; asw[mi] = (m>>1)&7; amb[mi] = (m&1)*4;
    }
    int bbase[4], bsw[4], bmb[4];
#pragma unroll
    for(int p=0; p<4; p++){
        int n = wn + p*16 + (j>>1)*8 + rl;
        bbase[p] = (n>>1)*128; bsw[p] = (n>>1)&7; bmb[p] = (n&1)*4;
    }

    float4 acc[2][8];
#pragma unroll
    for(int mi=0;mi<2;mi++)
#pragma unroll
        for(int ni=0;ni<8;ni++) acc[mi][ni] = make_float4(0.f,0.f,0.f,0.f);

    const int S = K >> 5;
    uint2 ra[4], rb[4];
    load_tile_g(ra, rb, tid, m0, n0, 0, A, lda, B, ldb);
    store_tile_g(sm, sm+8192, tid, ra, rb);
    __syncthreads();

    for(int s=0; s<S; s++){
        if(s+1 < S)
            load_tile_g(ra, rb, tid, m0, n0, (s+1)<<5, A, lda, B, ldb);

        uint32_t sAa = smbase + (s&1)*16384;
        uint32_t sBa = sAa + 8192;
#pragma unroll
        for(int kh=0; kh<2; kh++){
            int ka = kh*2;
            uint32_t a[2][4];
#pragma unroll
            for(int mi=0; mi<2; mi++){
                uint32_t addr = sAa + abase[mi] + ((((amb[mi] + ka + aj) ^ asw[mi]))<<4);
                ldsm4(a[mi][0], a[mi][1], a[mi][2], a[mi][3], addr);
            }
#pragma unroll
            for(int p=0; p<4; p++){
                uint32_t b0,b1r,b2,b3;
                uint32_t addr = sBa + bbase[p] + ((((bmb[p] + ka + bj) ^ bsw[p]))<<4);
                ldsm4(b0, b1r, b2, b3, addr);
                mma16(acc[0][2*p  ], a[0], b0, b1r);
                mma16(acc[0][2*p+1], a[0], b2, b3);
                mma16(acc[1][2*p  ], a[1], b0, b1r);
                mma16(acc[1][2*p+1], a[1], b2, b3);
            }
        }
        if(s+1 < S){
            store_tile_g(sm + ((s+1)&1)*16384, sm + ((s+1)&1)*16384 + 8192, tid, ra, rb);
            __syncthreads();
        }
    }

#pragma unroll
    for(int mi=0; mi<2; mi++){
#pragma unroll
        for(int rr=0; rr<2; rr++){
            int row = m0 + wm + mi*16 + qr + rr*8;
            float sc = SCALE ? rowscale[row >> 6] : 1.f;
            size_t crow = (size_t)row*ldc;
#pragma unroll
            for(int ni=0; ni<8; ni++){
                int col = n0 + wn + ni*8 + qc*2;
                float v0 = (rr==0 ? acc[mi][ni].x : acc[mi][ni].z)*sc;
                float v1 = (rr==0 ? acc[mi][ni].y : acc[mi][ni].w)*sc;
                if(BIAS){ v0 += bias[col]; v1 += bias[col+1]; }
                if(ACT==1){ v0 = eluf(v0); v1 = eluf(v1); }
                if(OUTH){
                    *(__half2*)&(((__half*)C)[crow + col]) = __floats2half2_rn(v0, v1);
                } else {
                    *(float2*)&C[crow + col] = make_float2(v0, v1);
                }
            }
        }
    }
}

// ================= fused edge GEMM =================
// A[128 rows = 2 edges x 64 steps][K=256] built on the fly:
//   A[e*64+s][k] = elu(Ph[src[e]*64+s][k] + Qh[dst[e]*64+s][k] + b1[k])  (PQ in fp16)
// Block tile 128x256 (full N). 256 thr, 8 warps, warp tile 32x128.
// Epilogue: elu(acc + b2) atomically scattered into agg[dst[e]*64+s][col].
__global__ void __launch_bounds__(256)
k_edge_gemm(const __half* __restrict__ PQ,
            const int* __restrict__ srcp, const int* __restrict__ dstp,
            const float* __restrict__ b1,
            const float* __restrict__ W2, const float* __restrict__ b2,
            float* __restrict__ agg)
{
    __shared__ __align__(16) char smA[2*8192];    // 128x32 fp16
    __shared__ __align__(16) char smB[2*16384];   // 256x32 fp16
    const int m0 = blockIdx.x*128;
    const int tid  = threadIdx.x;
    const int warp = tid >> 5, lane = tid & 31;
    const int wm = (warp >> 1)*32;       // 0,32,64,96
    const int wn = (warp &  1)*128;      // 0,128
    const int qr = lane >> 2, qc = lane & 3;
    const uint32_t smAb = (uint32_t)__cvta_generic_to_shared(smA);
    const uint32_t smBb = (uint32_t)__cvta_generic_to_shared(smB);

    const int j  = lane >> 3, rl = lane & 7;
    const int aj = j >> 1;
    const int bj = j & 1;
    int abase[2], asw[2], amb[2];
#pragma unroll
    for(int mi=0; mi<2; mi++){
        int m = wm + mi*16 + (j&1)*8 + rl;
        abase[mi] = (m>>1)*128; asw[mi] = (m>>1)&7; amb[mi] = (m&1)*4;
    }
    int bbase[8], bsw[8], bmb[8];
#pragma unroll
    for(int p=0; p<8; p++){
        int n = wn + p*16 + (j>>1)*8 + rl;
        bbase[p] = (n>>1)*128; bsw[p] = (n>>1)&7; bmb[p] = (n&1)*4;
    }

    // A-load indexing (2 slots/thread, 8 halves each)
    int ar[2], ac[2]; const __half *ap[2], *aq[2];
#pragma unroll
    for(int it=0; it<2; it++){
        int idx = tid + it*256;          // 0..511
        ar[it] = idx >> 2;               // 0..127
        ac[it] = (idx & 3) * 8;          // 0,8,16,24
        int grow = m0 + ar[it];
        int e = grow >> 6, srow = grow & 63;
        int se = __ldg(&srcp[e]);
        int de = __ldg(&dstp[e]);
        ap[it] = PQ + ((size_t)se*64 + srow)*512;
        aq[it] = PQ + ((size_t)de*64 + srow)*512 + 256;
    }

    float4 acc[2][16];
#pragma unroll
    for(int mi=0;mi<2;mi++)
#pragma unroll
        for(int ni=0;ni<16;ni++) acc[mi][ni] = make_float4(0.f,0.f,0.f,0.f);

    uint4 ra[2]; uint2 rb[8];

    auto load_stage = [&](int k0){
#pragma unroll
        for(int it=0; it<2; it++){
            int kc = k0 + ac[it];
            uint4 pv = *(const uint4*)(ap[it] + kc);
            uint4 qv = *(const uint4*)(aq[it] + kc);
            float4 bb0 = *(const float4*)&b1[kc];
            float4 bb1 = *(const float4*)&b1[kc+4];
            const __half2* ph = (const __half2*)&pv;
            const __half2* qh = (const __half2*)&qv;
            uint32_t o[4];
#pragma unroll
            for(int w=0; w<4; w++){
                float2 pf = __half22float2(ph[w]);
                float2 qf = __half22float2(qh[w]);
                float bx = (w<2) ? ((w&1)? bb0.z : bb0.x) : ((w&1)? bb1.z : bb1.x);
                float by = (w<2) ? ((w&1)? bb0.w : bb0.y) : ((w&1)? bb1.w : bb1.y);
                o[w] = f2h2(eluf(pf.x+qf.x+bx), eluf(pf.y+qf.y+by));
            }
            ra[it] = make_uint4(o[0],o[1],o[2],o[3]);
        }
#pragma unroll
        for(int it=0; it<8; it++){
            int idx = tid + it*256;      // 0..2047
            int r = idx >> 3;            // 0..255
            int c = (idx & 7) * 4;       // 0..28
            float4 w = *(const float4*)&W2[(size_t)r*256 + k0 + c];
            rb[it] = make_uint2(f2h2(w.x,w.y), f2h2(w.z,w.w));
        }
    };
    auto store_stage = [&](int st){
#pragma unroll
        for(int it=0; it<2; it++)
            *(uint4*)(smA + st*8192 + swatom(ar[it], ac[it]>>3)) = ra[it];
#pragma unroll
        for(int it=0; it<8; it++){
            int idx = tid + it*256;
            int r = idx >> 3;
            int c = (idx & 7) * 4;
            *(uint2*)(smB + st*16384 + swatom(r, c>>3) + ((c&7)*2)) = rb[it];
        }
    };

    load_stage(0);
    store_stage(0);
    __syncthreads();

    for(int s=0; s<8; s++){
        if(s+1 < 8) load_stage((s+1)<<5);

        uint32_t sAa = smAb + (s&1)*8192;
        uint32_t sBa = smBb + (s&1)*16384;
#pragma unroll
        for(int kh=0; kh<2; kh++){
            int ka = kh*2;
            uint32_t a[2][4];
#pragma unroll
            for(int mi=0; mi<2; mi++){
                uint32_t addr = sAa + abase[mi] + ((((amb[mi] + ka + aj) ^ asw[mi]))<<4);
                ldsm4(a[mi][0], a[mi][1], a[mi][2], a[mi][3], addr);
            }
#pragma unroll
            for(int p=0; p<8; p++){
                uint32_t b0,b1r,b2,b3;
                uint32_t addr = sBa + bbase[p] + ((((bmb[p] + ka + bj) ^ bsw[p]))<<4);
                ldsm4(b0, b1r, b2, b3, addr);
                mma16(acc[0][2*p  ], a[0], b0, b1r);
                mma16(acc[0][2*p+1], a[0], b2, b3);
                mma16(acc[1][2*p  ], a[1], b0, b1r);
                mma16(acc[1][2*p+1], a[1], b2, b3);
            }
        }
        if(s+1 < 8){
            store_stage((s+1)&1);
            __syncthreads();
        }
    }

    // epilogue: elu + scatter-add
#pragma unroll
    for(int mi=0; mi<2; mi++){
#pragma unroll
        for(int rr=0; rr<2; rr++){
            int row = m0 + wm + mi*16 + qr + rr*8;
            int e = row >> 6, ss = row & 63;
            size_t crow = (size_t)(__ldg(&dstp[e])*64 + ss)*256;
#pragma unroll
            for(int ni=0; ni<16; ni++){
                int col = wn + ni*8 + qc*2;
                float v0 = (rr==0 ? acc[mi][ni].x : acc[mi][ni].z);
                float v1 = (rr==0 ? acc[mi][ni].y : acc[mi][ni].w);
                v0 = eluf(v0 + b2[col]);
                v1 = eluf(v1 + b2[col+1]);
                atomicAdd(&agg[crow + col],   v0);
                atomicAdd(&agg[crow + col+1], v1);
            }
        }
    }
}

// ---------------- persistent LSTM ----------------
__global__ void __launch_bounds__(256) k_lstm_all(const float* __restrict__ Whh){
    __shared__ float ws[8][516];
    __shared__ float gs[8][512];
    __shared__ float hs[8][128];
    __shared__ float cs[8][128];
    const int tid = threadIdx.x;
    const int nb = blockIdx.x*8;
    const int u = tid & 127;
    const int v = tid >> 7;

    for(int i=tid;i<8*128;i+=256){ hs[i>>7][i&127]=0.f; cs[i>>7][i&127]=0.f; }
    __syncthreads();

    for(int t=0;t<SEQ;t++){
        for(int i=tid;i<8*512;i+=256){
            int n=i>>9, r=i&511;
            gs[n][r] = g_gates[((size_t)(nb+n)*SEQ + t)*512 + r];
        }
        __syncthreads();

        float acc[4][4];
#pragma unroll
        for(int i=0;i<4;i++)
#pragma unroll
            for(int m=0;m<4;m++) acc[i][m] = gs[v*4+m][u*4+i];

        for(int kc=0;kc<128;kc+=8){
            __syncthreads();
            for(int i=tid;i<512*8;i+=256){
                int r=i>>3, c=i&7;
                ws[c][r] = Whh[r*128 + kc + c];
            }
            __syncthreads();
#pragma unroll
            for(int k=0;k<8;k++){
                float4 w4 = *(const float4*)&ws[k][u*4];
                float hv0 = hs[v*4+0][kc+k];
                float hv1 = hs[v*4+1][kc+k];
                float hv2 = hs[v*4+2][kc+k];
                float hv3 = hs[v*4+3][kc+k];
                acc[0][0]+=w4.x*hv0; acc[0][1]+=w4.x*hv1; acc[0][2]+=w4.x*hv2; acc[0][3]+=w4.x*hv3;
                acc[1][0]+=w4.y*hv0; acc[1][1]+=w4.y*hv1; acc[1][2]+=w4.y*hv2; acc[1][3]+=w4.y*hv3;
                acc[2][0]+=w4.z*hv0; acc[2][1]+=w4.z*hv1; acc[2][2]+=w4.z*hv2; acc[2][3]+=w4.z*hv3;
                acc[3][0]+=w4.w*hv0; acc[3][1]+=w4.w*hv1; acc[3][2]+=w4.w*hv2; acc[3][3]+=w4.w*hv3;
            }
        }
        __syncthreads();
#pragma unroll
        for(int i=0;i<4;i++)
#pragma unroll
            for(int m=0;m<4;m++) gs[v*4+m][u*4+i] = acc[i][m];
        __syncthreads();

        for(int i=tid;i<8*128;i+=256){
            int n=i>>7, jj=i&127;
            float ig=gs[n][jj], fg=gs[n][128+jj], gg=gs[n][256+jj], og=gs[n][384+jj];
            float cn = sigf(fg)*cs[n][jj] + sigf(ig)*tanhfast(gg);
            cs[n][jj]=cn;
            hs[n][jj]=sigf(og)*tanhfast(cn);
        }
        __syncthreads();
    }
    for(int i=tid;i<8*128;i+=256)
        g_h[(size_t)(nb + (i>>7))*128 + (i&127)] = hs[i>>7][i&127];
}

// ---------------- output heads ----------------
__global__ void k_heads(const float* __restrict__ Wm, const float* __restrict__ bm,
                        const float* __restrict__ Wt, const float* __restrict__ bt,
                        const float* __restrict__ We, const float* __restrict__ be,
                        float* __restrict__ out){
    int n = blockIdx.x;
    int l = threadIdx.x;
    float sm=0.f, st=0.f, se=0.f;
    for(int jj=l;jj<128;jj+=32){
        float h = g_h[(size_t)n*128 + jj];
        sm += h*Wm[jj]; st += h*Wt[jj]; se += h*We[jj];
    }
#pragma unroll
    for(int o=16;o;o>>=1){
        sm += __shfl_down_sync(0xffffffffu, sm, o);
        st += __shfl_down_sync(0xffffffffu, st, o);
        se += __shfl_down_sync(0xffffffffu, se, o);
    }
    if(l==0){
        out[n]            = sm + bm[0];
        out[N_NODES + n]  = st + bt[0];
        out[2*N_NODES + n]= se + be[0];
    }
}

// ---------------- host launcher ----------------
extern "C" void kernel_launch(void* const* d_in, const int* in_sizes, int n_in,
                              void* d_out, int out_size)
{
    const int*   edge  = (const int*)  d_in[0];
    const float* itime = (const float*)d_in[1];
    const float* iev   = (const float*)d_in[2];
    const int*   ann   = (const int*)  d_in[3];
    const float* emb   = (const float*)d_in[4];
    const float* W_in  = (const float*)d_in[5];
    const float* b_in  = (const float*)d_in[6];
    const float* nW1   = (const float*)d_in[7];
    const float* nb1   = (const float*)d_in[8];
    const float* nW2   = (const float*)d_in[9];
    const float* nb2   = (const float*)d_in[10];
    const float* aW1   = (const float*)d_in[11];
    const float* ab1   = (const float*)d_in[12];
    const float* aW2   = (const float*)d_in[13];
    const float* ab2   = (const float*)d_in[14];
    const float* Wih   = (const float*)d_in[15];
    const float* Whh   = (const float*)d_in[16];
    const float* bih   = (const float*)d_in[17];
    const float* bhh   = (const float*)d_in[18];
    const float* Wm    = (const float*)d_in[19];
    const float* bm    = (const float*)d_in[20];
    const float* Wt    = (const float*)d_in[21];
    const float* bt    = (const float*)d_in[22];
    const float* We    = (const float*)d_in[23];
    const float* be    = (const float*)d_in[24];
    float* out = (float*)d_out;

    const int* src = edge;
    const int* dst = edge + NEDGE;

    float *px, *pnf, *ptmp, *pW1p, *pgates, *pinvdeg, *pbsum;
    __half *pPQh;
    cudaGetSymbolAddress((void**)&px,     g_x);
    cudaGetSymbolAddress((void**)&pnf,    g_nf);
    cudaGetSymbolAddress((void**)&ptmp,   g_tmp);
    cudaGetSymbolAddress((void**)&pPQh,   g_PQh);
    cudaGetSymbolAddress((void**)&pW1p,   g_W1p);
    cudaGetSymbolAddress((void**)&pgates, g_gates);
    cudaGetSymbolAddress((void**)&pinvdeg,g_invdeg);
    cudaGetSymbolAddress((void**)&pbsum,  g_bsum);

    // degrees
    k_zero_deg<<<4,256>>>();
    k_deg<<<(NEDGE+255)/256,256>>>(dst);
    k_fin_deg<<<4,256>>>();

    // input embedding: x -> nf
    k_build_x<<<NS,256>>>(itime, iev, ann, emb);
    k_gemm<0,true,false,false><<<dim3(NS/128,1),256>>>(
        px,256, W_in,256, b_in, nullptr, pnf,128, 256);

    for(int l=0; l<2; l++){
        const float* W1 = aW1 + (size_t)l*256*256;
        const float* B1 = ab1 + (size_t)l*256;
        const float* W2 = aW2 + (size_t)l*256*256;
        const float* B2 = ab2 + (size_t)l*256;
        const float* NW1= nW1 + (size_t)l*128*256;
        const float* NB1= nb1 + (size_t)l*128;
        const float* NW2= nW2 + (size_t)l*128*128;
        const float* NB2= nb2 + (size_t)l*128;

        // repack W1, then one GEMM producing [P|Q] = nf @ W1p^T -> fp16 [NS,512]
        k_packW1<<<256,256>>>(W1);
        k_gemm<0,false,false,true><<<dim3(NS/128,4),256>>>(
            pnf,128, pW1p,128, nullptr, nullptr, (float*)pPQh,512, 128);

        // zero agg, then fused single-pass edge GEMM (build A + elu + scatter-add)
        cudaMemsetAsync(px, 0, (size_t)NS*256*sizeof(float));
        k_edge_gemm<<<ES/128,256>>>(pPQh, src, dst, B1, W2, B2, px);

        // node MLP (mean scaling folded into GEMM epilogue)
        k_gemm<1,true,true,false><<<dim3(NS/128,1),256>>>(
            px,256, NW1,256, NB1, pinvdeg, ptmp,128, 256);
        k_gemm<1,true,false,false><<<dim3(NS/128,1),256>>>(
            ptmp,128, NW2,128, NB2, nullptr, pnf,128, 128);
    }

    // LSTM: precompute input gates, then persistent recurrence
    k_bsum<<<2,256>>>(bih, bhh);
    k_gemm<0,true,false,false><<<dim3(NS/128,4),256>>>(
        pnf,128, Wih,128, pbsum, nullptr, pgates,512, 128);
    k_lstm_all<<<128,256>>>(Whh);

    k_heads<<<N_NODES,32>>>(Wm,bm,Wt,bt,We,be,out);
}

// round 6
// speedup vs baseline: 4.8956x; 2.0900x over previous
#include <cuda_runtime.h>
#include <cuda_fp16.h>
#include <math.h>
#include <stdint.h>

#define N_NODES 1024
#define SEQ     64
#define NEDGE   4096
#define NS      (N_NODES*SEQ)   /* 65536  */
#define ES      (NEDGE*SEQ)     /* 262144 */

// ---------------- scratch (device globals) ----------------
__device__ __half g_xh[NS*256];
__device__ __half g_nfh[NS*128];
__device__ __half g_tmph[NS*128];
__device__ __half g_PQh[NS*512];
__device__ float  g_agg[NS*256];
__device__ __half g_gatesh[NS*512];
__device__ __half g_Winh[128*256];
__device__ __half g_W1ph[512*128];
__device__ __half g_W2h[256*256];
__device__ __half g_NW1h[128*256];
__device__ __half g_NW2h[128*128];
__device__ __half g_Wihh[512*128];
__device__ __half g_Whhh[512*128];
__device__ float  g_invdeg[N_NODES];
__device__ float  g_h[N_NODES*128];
__device__ float  g_bsum[512];

// ---------------- helpers ----------------
__device__ __forceinline__ float eluf(float v){ return v > 0.f ? v : (__expf(v) - 1.f); }
__device__ __forceinline__ float sigf(float v){ return 1.f/(1.f+__expf(-v)); }
__device__ __forceinline__ float tanhfast(float v){ return 1.f - 2.f/(__expf(2.f*v)+1.f); }
__device__ __forceinline__ uint32_t f2h2(float lo, float hi){
    __half2 h = __floats2half2_rn(lo, hi);
    return *(uint32_t*)&h;
}
__device__ __forceinline__ void mma16(float4 &d, const uint32_t a[4], uint32_t b0, uint32_t b1){
    asm volatile("mma.sync.aligned.m16n8k16.row.col.f32.f16.f16.f32 "
        "{%0,%1,%2,%3}, {%4,%5,%6,%7}, {%8,%9}, {%0,%1,%2,%3};\n"
        : "+f"(d.x), "+f"(d.y), "+f"(d.z), "+f"(d.w)
        : "r"(a[0]), "r"(a[1]), "r"(a[2]), "r"(a[3]), "r"(b0), "r"(b1));
}
__device__ __forceinline__ void ldsm4(uint32_t &r0, uint32_t &r1, uint32_t &r2, uint32_t &r3, uint32_t addr){
    asm volatile("ldmatrix.sync.aligned.m8n8.x4.shared.b16 {%0,%1,%2,%3}, [%4];"
        : "=r"(r0), "=r"(r1), "=r"(r2), "=r"(r3) : "r"(addr));
}
__device__ __forceinline__ void redv2(float* p, float v0, float v1){
    asm volatile("red.global.add.v2.f32 [%0], {%1, %2};" :: "l"(p), "f"(v0), "f"(v1) : "memory");
}
// swizzled 16B-atom byte offset, 2 rows per 128B line, 4 k-atoms per row
__device__ __forceinline__ int swatom(int r, int katom){
    return (r>>1)*128 + ((((r&1)*4 + katom) ^ ((r>>1)&7))<<4);
}

// ---------------- degree / misc / weight prep ----------------
__global__ void k_zero_deg(){
    int i = blockIdx.x*blockDim.x + threadIdx.x;
    if(i < N_NODES) g_invdeg[i] = 0.f;
}
__global__ void k_deg(const int* __restrict__ dst){
    int e = blockIdx.x*blockDim.x + threadIdx.x;
    if(e < NEDGE) atomicAdd(&g_invdeg[dst[e]], 1.f);
}
__global__ void k_fin_deg(){
    int i = blockIdx.x*blockDim.x + threadIdx.x;
    if(i < N_NODES){ float d = g_invdeg[i]; g_invdeg[i] = 1.f/fmaxf(d,1.f); }
}
__global__ void k_bsum(const float* __restrict__ bih, const float* __restrict__ bhh){
    int i = blockIdx.x*blockDim.x + threadIdx.x;
    if(i < 512) g_bsum[i] = bih[i] + bhh[i];
}
__global__ void k_prep_global(const float* __restrict__ W_in, const float* __restrict__ Wih,
                              const float* __restrict__ Whh){
    int i = blockIdx.x*256 + threadIdx.x;   // 0..65535
    if(i < 128*256) g_Winh[i] = __float2half(W_in[i]);
    if(i < 512*128){ g_Wihh[i] = __float2half(Wih[i]); g_Whhh[i] = __float2half(Whh[i]); }
}
__global__ void k_prep_layer(const float* __restrict__ W1, const float* __restrict__ W2,
                             const float* __restrict__ NW1, const float* __restrict__ NW2){
    int i = blockIdx.x*256 + threadIdx.x;   // 0..65535
    {
        int o = i >> 8, k = i & 255;
        __half v = __float2half(W1[i]);
        if(k < 128) g_W1ph[o*128 + k] = v;
        else        g_W1ph[(256+o)*128 + (k-128)] = v;
        g_W2h[i] = __float2half(W2[i]);
    }
    if(i < 128*256) g_NW1h[i] = __float2half(NW1[i]);
    if(i < 128*128) g_NW2h[i] = __float2half(NW2[i]);
}

// ---------------- build x = [emb(127) | events(1) | te(128)], fp16 ----------------
__global__ void k_build_x(const float* __restrict__ itime, const float* __restrict__ iev,
                          const int* __restrict__ ann, const float* __restrict__ emb){
    int row = blockIdx.x;
    int c   = threadIdx.x;
    float t = itime[row];
    float e = iev[row];
    float v;
    if(c < 127){
        v = emb[ann[row]*127 + c];
    } else if(c == 127){
        v = e;
    } else {
        int j = c - 128;
        float pos = exp2f(13.287712379549449f * (float)(j>>1) * (1.0f/64.0f));
        float r = t / pos;
        float te = (j & 1) ? __cosf(r) : __sinf(r);
        v = (e != 0.f) ? te : 0.f;
    }
    g_xh[row*256 + c] = __float2half(v);
}

// ================= generic FP16 tensor-core GEMM =================
// C[M,Nc] = act(scale * A@B^T + bias). A fp16 or fp32 (AF32), B fp16.
// grid=(M/128, Nc/128), 256 thr, warp tile 32x64. K mult of 32.
template<int ACT, bool BIAS, bool SCALE, bool OUTH, bool AF32>
__global__ void __launch_bounds__(256)
k_gemm(const void* __restrict__ Ap, int lda,
       const __half* __restrict__ B, int ldb,
       const float* __restrict__ bias, const float* __restrict__ rowscale,
       void* __restrict__ Cp, int ldc, int K)
{
    __shared__ __align__(16) char sm[2*16384];
    const int m0 = blockIdx.x*128, n0 = blockIdx.y*128;
    const int tid  = threadIdx.x;
    const int warp = tid >> 5, lane = tid & 31;
    const int wm = (warp >> 1)*32;
    const int wn = (warp &  1)*64;
    const int qr = lane >> 2, qc = lane & 3;
    const uint32_t smbase = (uint32_t)__cvta_generic_to_shared(sm);

    const int j  = lane >> 3, rl = lane & 7;
    const int aj = j >> 1;
    const int bj = j & 1;
    int abase[2], asw[2], amb[2];
#pragma unroll
    for(int mi=0; mi<2; mi++){
        int m = wm + mi*16 + (j&1)*8 + rl;
        abase[mi] = (m>>1)*128; asw[mi] = (m>>1)&7; amb[mi] = (m&1)*4;
    }
    int bbase[4], bsw[4], bmb[4];
#pragma unroll
    for(int p=0; p<4; p++){
        int n = wn + p*16 + (j>>1)*8 + rl;
        bbase[p] = (n>>1)*128; bsw[p] = (n>>1)&7; bmb[p] = (n&1)*4;
    }

    float4 acc[2][8];
#pragma unroll
    for(int mi=0;mi<2;mi++)
#pragma unroll
        for(int ni=0;ni<8;ni++) acc[mi][ni] = make_float4(0.f,0.f,0.f,0.f);

    uint4 ra16[2]; uint2 ra32[4]; uint4 rbv[2];

    auto load_stage = [&](int k0){
        if(AF32){
            const float* A = (const float*)Ap;
#pragma unroll
            for(int it=0; it<4; it++){
                int idx = tid + it*256;
                int r = idx >> 3, c = (idx & 7)*4;
                float4 v = *(const float4*)&A[(size_t)(m0+r)*lda + k0 + c];
                ra32[it] = make_uint2(f2h2(v.x,v.y), f2h2(v.z,v.w));
            }
        } else {
            const __half* A = (const __half*)Ap;
#pragma unroll
            for(int it=0; it<2; it++){
                int idx = tid + it*256;
                int r = idx >> 2, c = (idx & 3)*8;
                ra16[it] = *(const uint4*)&A[(size_t)(m0+r)*lda + k0 + c];
            }
        }
#pragma unroll
        for(int it=0; it<2; it++){
            int idx = tid + it*256;
            int r = idx >> 2, c = (idx & 3)*8;
            rbv[it] = *(const uint4*)&B[(size_t)(n0+r)*ldb + k0 + c];
        }
    };
    auto store_stage = [&](int st){
        char* sA = sm + st*16384;
        char* sB = sA + 8192;
        if(AF32){
#pragma unroll
            for(int it=0; it<4; it++){
                int idx = tid + it*256;
                int r = idx >> 3, c = (idx & 7)*4;
                *(uint2*)(sA + swatom(r, c>>3) + ((c&7)*2)) = ra32[it];
            }
        } else {
#pragma unroll
            for(int it=0; it<2; it++){
                int idx = tid + it*256;
                int r = idx >> 2;
                *(uint4*)(sA + swatom(r, idx&3)) = ra16[it];
            }
        }
#pragma unroll
        for(int it=0; it<2; it++){
            int idx = tid + it*256;
            int r = idx >> 2;
            *(uint4*)(sB + swatom(r, idx&3)) = rbv[it];
        }
    };

    const int S = K >> 5;
    load_stage(0);
    store_stage(0);
    __syncthreads();

    for(int s=0; s<S; s++){
        if(s+1 < S) load_stage((s+1)<<5);

        uint32_t sAa = smbase + (s&1)*16384;
        uint32_t sBa = sAa + 8192;
#pragma unroll
        for(int kh=0; kh<2; kh++){
            int ka = kh*2;
            uint32_t a[2][4];
#pragma unroll
            for(int mi=0; mi<2; mi++){
                uint32_t addr = sAa + abase[mi] + ((((amb[mi] + ka + aj) ^ asw[mi]))<<4);
                ldsm4(a[mi][0], a[mi][1], a[mi][2], a[mi][3], addr);
            }
#pragma unroll
            for(int p=0; p<4; p++){
                uint32_t b0,b1r,b2,b3;
                uint32_t addr = sBa + bbase[p] + ((((bmb[p] + ka + bj) ^ bsw[p]))<<4);
                ldsm4(b0, b1r, b2, b3, addr);
                mma16(acc[0][2*p  ], a[0], b0, b1r);
                mma16(acc[0][2*p+1], a[0], b2, b3);
                mma16(acc[1][2*p  ], a[1], b0, b1r);
                mma16(acc[1][2*p+1], a[1], b2, b3);
            }
        }
        if(s+1 < S){
            store_stage((s+1)&1);
            __syncthreads();
        }
    }

#pragma unroll
    for(int mi=0; mi<2; mi++){
#pragma unroll
        for(int rr=0; rr<2; rr++){
            int row = m0 + wm + mi*16 + qr + rr*8;
            float sc = SCALE ? rowscale[row >> 6] : 1.f;
            size_t crow = (size_t)row*ldc;
#pragma unroll
            for(int ni=0; ni<8; ni++){
                int col = n0 + wn + ni*8 + qc*2;
                float v0 = (rr==0 ? acc[mi][ni].x : acc[mi][ni].z)*sc;
                float v1 = (rr==0 ? acc[mi][ni].y : acc[mi][ni].w)*sc;
                if(BIAS){ v0 += bias[col]; v1 += bias[col+1]; }
                if(ACT==1){ v0 = eluf(v0); v1 = eluf(v1); }
                if(OUTH){
                    *(__half2*)&(((__half*)Cp)[crow + col]) = __floats2half2_rn(v0, v1);
                } else {
                    *(float2*)&(((float*)Cp)[crow + col]) = make_float2(v0, v1);
                }
            }
        }
    }
}

// ================= fused edge GEMM =================
// A[128 rows = 2 edges x 64 steps][K=256] built on the fly from fp16 PQ.
// Epilogue: elu(acc + b2) red.v2-scattered into agg[dst[e]*64+s][col].
__global__ void __launch_bounds__(256)
k_edge_gemm(const __half* __restrict__ PQ,
            const int* __restrict__ srcp, const int* __restrict__ dstp,
            const float* __restrict__ b1,
            const __half* __restrict__ W2h, const float* __restrict__ b2,
            float* __restrict__ agg)
{
    __shared__ __align__(16) char smA[2*8192];
    __shared__ __align__(16) char smB[2*16384];
    const int m0 = blockIdx.x*128;
    const int tid  = threadIdx.x;
    const int warp = tid >> 5, lane = tid & 31;
    const int wm = (warp >> 1)*32;
    const int wn = (warp &  1)*128;
    const int qr = lane >> 2, qc = lane & 3;
    const uint32_t smAb = (uint32_t)__cvta_generic_to_shared(smA);
    const uint32_t smBb = (uint32_t)__cvta_generic_to_shared(smB);

    const int j  = lane >> 3, rl = lane & 7;
    const int aj = j >> 1;
    const int bj = j & 1;
    int abase[2], asw[2], amb[2];
#pragma unroll
    for(int mi=0; mi<2; mi++){
        int m = wm + mi*16 + (j&1)*8 + rl;
        abase[mi] = (m>>1)*128; asw[mi] = (m>>1)&7; amb[mi] = (m&1)*4;
    }
    int bbase[8], bsw[8], bmb[8];
#pragma unroll
    for(int p=0; p<8; p++){
        int n = wn + p*16 + (j>>1)*8 + rl;
        bbase[p] = (n>>1)*128; bsw[p] = (n>>1)&7; bmb[p] = (n&1)*4;
    }

    // A-build indexing (2 slots/thread, 8 halves each)
    int ar[2], ac[2]; const __half *ap[2], *aq[2];
#pragma unroll
    for(int it=0; it<2; it++){
        int idx = tid + it*256;
        ar[it] = idx >> 2;
        ac[it] = (idx & 3) * 8;
        int grow = m0 + ar[it];
        int e = grow >> 6, srow = grow & 63;
        int se = __ldg(&srcp[e]);
        int de = __ldg(&dstp[e]);
        ap[it] = PQ + ((size_t)se*64 + srow)*512;
        aq[it] = PQ + ((size_t)de*64 + srow)*512 + 256;
    }

    float4 acc[2][16];
#pragma unroll
    for(int mi=0;mi<2;mi++)
#pragma unroll
        for(int ni=0;ni<16;ni++) acc[mi][ni] = make_float4(0.f,0.f,0.f,0.f);

    uint4 ra[2]; uint4 rb[4];

    auto load_stage = [&](int k0){
#pragma unroll
        for(int it=0; it<2; it++){
            int kc = k0 + ac[it];
            uint4 pv = *(const uint4*)(ap[it] + kc);
            uint4 qv = *(const uint4*)(aq[it] + kc);
            float4 bb0 = *(const float4*)&b1[kc];
            float4 bb1 = *(const float4*)&b1[kc+4];
            const __half2* ph = (const __half2*)&pv;
            const __half2* qh = (const __half2*)&qv;
            uint32_t o[4];
#pragma unroll
            for(int w=0; w<4; w++){
                float2 pf = __half22float2(ph[w]);
                float2 qf = __half22float2(qh[w]);
                float bx = (w<2) ? ((w&1)? bb0.z : bb0.x) : ((w&1)? bb1.z : bb1.x);
                float by = (w<2) ? ((w&1)? bb0.w : bb0.y) : ((w&1)? bb1.w : bb1.y);
                o[w] = f2h2(eluf(pf.x+qf.x+bx), eluf(pf.y+qf.y+by));
            }
            ra[it] = make_uint4(o[0],o[1],o[2],o[3]);
        }
#pragma unroll
        for(int it=0; it<4; it++){
            int idx = tid + it*256;      // 0..1023
            int r = idx >> 2, c = (idx & 3)*8;
            rb[it] = *(const uint4*)&W2h[(size_t)r*256 + k0 + c];
        }
    };
    auto store_stage = [&](int st){
#pragma unroll
        for(int it=0; it<2; it++)
            *(uint4*)(smA + st*8192 + swatom(ar[it], ac[it]>>3)) = ra[it];
#pragma unroll
        for(int it=0; it<4; it++){
            int idx = tid + it*256;
            int r = idx >> 2;
            *(uint4*)(smB + st*16384 + swatom(r, idx&3)) = rb[it];
        }
    };

    load_stage(0);
    store_stage(0);
    __syncthreads();

    for(int s=0; s<8; s++){
        if(s+1 < 8) load_stage((s+1)<<5);

        uint32_t sAa = smAb + (s&1)*8192;
        uint32_t sBa = smBb + (s&1)*16384;
#pragma unroll
        for(int kh=0; kh<2; kh++){
            int ka = kh*2;
            uint32_t a[2][4];
#pragma unroll
            for(int mi=0; mi<2; mi++){
                uint32_t addr = sAa + abase[mi] + ((((amb[mi] + ka + aj) ^ asw[mi]))<<4);
                ldsm4(a[mi][0], a[mi][1], a[mi][2], a[mi][3], addr);
            }
#pragma unroll
            for(int p=0; p<8; p++){
                uint32_t b0,b1r,b2,b3;
                uint32_t addr = sBa + bbase[p] + ((((bmb[p] + ka + bj) ^ bsw[p]))<<4);
                ldsm4(b0, b1r, b2, b3, addr);
                mma16(acc[0][2*p  ], a[0], b0, b1r);
                mma16(acc[0][2*p+1], a[0], b2, b3);
                mma16(acc[1][2*p  ], a[1], b0, b1r);
                mma16(acc[1][2*p+1], a[1], b2, b3);
            }
        }
        if(s+1 < 8){
            store_stage((s+1)&1);
            __syncthreads();
        }
    }

    // epilogue: elu + vector red scatter
#pragma unroll
    for(int mi=0; mi<2; mi++){
#pragma unroll
        for(int rr=0; rr<2; rr++){
            int row = m0 + wm + mi*16 + qr + rr*8;
            int e = row >> 6, ss = row & 63;
            size_t crow = (size_t)(__ldg(&dstp[e])*64 + ss)*256;
#pragma unroll
            for(int ni=0; ni<16; ni++){
                int col = wn + ni*8 + qc*2;
                float v0 = (rr==0 ? acc[mi][ni].x : acc[mi][ni].z);
                float v1 = (rr==0 ? acc[mi][ni].y : acc[mi][ni].w);
                v0 = eluf(v0 + b2[col]);
                v1 = eluf(v1 + b2[col+1]);
                redv2(&agg[crow + col], v0, v1);
            }
        }
    }
}

// ================= tensor-core persistent LSTM =================
// 128 blocks x 256 thr; block owns 8 nodes (padded to M=16). Whh B-frags live in
// registers for the whole kernel; h lives in padded smem for ldmatrix.
__global__ void __launch_bounds__(256,1)
k_lstm_mma(const __half* __restrict__ Whh, const __half* __restrict__ gates){
    __shared__ __align__(16) __half hA[16*136];   // row stride 272B (conflict-free ldsm)
    __shared__ float G[8][512];
    const int tid = threadIdx.x, warp = tid>>5, lane = tid&31;
    const int nb = blockIdx.x*8;
    const int wn = warp*64;
    const uint32_t hAb = (uint32_t)__cvta_generic_to_shared(hA);

    float cst[4] = {0.f,0.f,0.f,0.f};
    for(int i=tid; i<16*136; i+=256) hA[i] = __float2half(0.f);

    // preload Whh B-fragments into registers (canonical m16n8k16 B mapping)
    uint32_t bf[8][8][2];
    {
        int bn = lane>>2, bk = (lane&3)*2;
#pragma unroll
        for(int nt=0; nt<8; nt++)
#pragma unroll
        for(int kt=0; kt<8; kt++){
            const __half* p = Whh + (size_t)(wn + nt*8 + bn)*128 + kt*16 + bk;
            bf[nt][kt][0] = *(const uint32_t*)p;
            bf[nt][kt][1] = *(const uint32_t*)(p + 8);
        }
    }
    __syncthreads();

    const int j = lane>>3, rl = lane&7;
    const int arow = (j&1)*8 + rl;
    const int cr = lane>>2, cc = (lane&3)*2;

    for(int t=0; t<64; t++){
        // A-frags for h (rows 8..15 are zero padding)
        uint32_t a[8][4];
#pragma unroll
        for(int kt=0; kt<8; kt++){
            uint32_t addr = hAb + arow*272 + (uint32_t)((kt*2 + (j>>1))*16);
            ldsm4(a[kt][0], a[kt][1], a[kt][2], a[kt][3], addr);
        }
        float4 acc[8];
#pragma unroll
        for(int nt=0; nt<8; nt++) acc[nt] = make_float4(0.f,0.f,0.f,0.f);
#pragma unroll
        for(int kt=0; kt<8; kt++)
#pragma unroll
            for(int nt=0; nt<8; nt++)
                mma16(acc[nt], a[kt], bf[nt][kt][0], bf[nt][kt][1]);

        // store real rows (0..7) + add precomputed input gates
#pragma unroll
        for(int nt=0; nt<8; nt++){
            int col = wn + nt*8 + cc;
            __half2 gv = *(const __half2*)&gates[((size_t)(nb+cr)*64 + t)*512 + col];
            float2 gf = __half22float2(gv);
            G[cr][col]   = acc[nt].x + gf.x;
            G[cr][col+1] = acc[nt].y + gf.y;
        }
        __syncthreads();

        // cell update: 4 (node,j) slots per thread
#pragma unroll
        for(int q=0; q<4; q++){
            int idx = q*256 + tid;
            int n = idx>>7, jj = idx&127;
            float ig=G[n][jj], fg=G[n][128+jj], gg=G[n][256+jj], og=G[n][384+jj];
            float cn = sigf(fg)*cst[q] + sigf(ig)*tanhfast(gg);
            cst[q] = cn;
            float h = sigf(og)*tanhfast(cn);
            hA[n*136 + jj] = __float2half(h);
            if(t==63) g_h[(size_t)(nb+n)*128 + jj] = h;
        }
        __syncthreads();
    }
}

// ---------------- output heads ----------------
__global__ void k_heads(const float* __restrict__ Wm, const float* __restrict__ bm,
                        const float* __restrict__ Wt, const float* __restrict__ bt,
                        const float* __restrict__ We, const float* __restrict__ be,
                        float* __restrict__ out){
    int n = blockIdx.x;
    int l = threadIdx.x;
    float sm=0.f, st=0.f, se=0.f;
    for(int jj=l;jj<128;jj+=32){
        float h = g_h[(size_t)n*128 + jj];
        sm += h*Wm[jj]; st += h*Wt[jj]; se += h*We[jj];
    }
#pragma unroll
    for(int o=16;o;o>>=1){
        sm += __shfl_down_sync(0xffffffffu, sm, o);
        st += __shfl_down_sync(0xffffffffu, st, o);
        se += __shfl_down_sync(0xffffffffu, se, o);
    }
    if(l==0){
        out[n]            = sm + bm[0];
        out[N_NODES + n]  = st + bt[0];
        out[2*N_NODES + n]= se + be[0];
    }
}

// ---------------- host launcher ----------------
extern "C" void kernel_launch(void* const* d_in, const int* in_sizes, int n_in,
                              void* d_out, int out_size)
{
    const int*   edge  = (const int*)  d_in[0];
    const float* itime = (const float*)d_in[1];
    const float* iev   = (const float*)d_in[2];
    const int*   ann   = (const int*)  d_in[3];
    const float* emb   = (const float*)d_in[4];
    const float* W_in  = (const float*)d_in[5];
    const float* b_in  = (const float*)d_in[6];
    const float* nW1   = (const float*)d_in[7];
    const float* nb1   = (const float*)d_in[8];
    const float* nW2   = (const float*)d_in[9];
    const float* nb2   = (const float*)d_in[10];
    const float* aW1   = (const float*)d_in[11];
    const float* ab1   = (const float*)d_in[12];
    const float* aW2   = (const float*)d_in[13];
    const float* ab2   = (const float*)d_in[14];
    const float* Wih   = (const float*)d_in[15];
    const float* Whh   = (const float*)d_in[16];
    const float* bih   = (const float*)d_in[17];
    const float* bhh   = (const float*)d_in[18];
    const float* Wm    = (const float*)d_in[19];
    const float* bm    = (const float*)d_in[20];
    const float* Wt    = (const float*)d_in[21];
    const float* bt    = (const float*)d_in[22];
    const float* We    = (const float*)d_in[23];
    const float* be    = (const float*)d_in[24];
    float* out = (float*)d_out;

    const int* src = edge;
    const int* dst = edge + NEDGE;

    __half *pxh, *pnfh, *ptmph, *pPQh, *pgatesh;
    __half *pWinh, *pW1ph, *pW2h, *pNW1h, *pNW2h, *pWihh, *pWhhh;
    float *pagg, *pinvdeg, *pbsum;
    cudaGetSymbolAddress((void**)&pxh,    g_xh);
    cudaGetSymbolAddress((void**)&pnfh,   g_nfh);
    cudaGetSymbolAddress((void**)&ptmph,  g_tmph);
    cudaGetSymbolAddress((void**)&pPQh,   g_PQh);
    cudaGetSymbolAddress((void**)&pgatesh,g_gatesh);
    cudaGetSymbolAddress((void**)&pWinh,  g_Winh);
    cudaGetSymbolAddress((void**)&pW1ph,  g_W1ph);
    cudaGetSymbolAddress((void**)&pW2h,   g_W2h);
    cudaGetSymbolAddress((void**)&pNW1h,  g_NW1h);
    cudaGetSymbolAddress((void**)&pNW2h,  g_NW2h);
    cudaGetSymbolAddress((void**)&pWihh,  g_Wihh);
    cudaGetSymbolAddress((void**)&pWhhh,  g_Whhh);
    cudaGetSymbolAddress((void**)&pagg,   g_agg);
    cudaGetSymbolAddress((void**)&pinvdeg,g_invdeg);
    cudaGetSymbolAddress((void**)&pbsum,  g_bsum);

    // degrees + weight prep
    k_zero_deg<<<4,256>>>();
    k_deg<<<(NEDGE+255)/256,256>>>(dst);
    k_fin_deg<<<4,256>>>();
    k_prep_global<<<256,256>>>(W_in, Wih, Whh);
    k_bsum<<<2,256>>>(bih, bhh);

    // input embedding: x -> nf
    k_build_x<<<NS,256>>>(itime, iev, ann, emb);
    k_gemm<0,true,false,true,false><<<dim3(NS/128,1),256>>>(
        pxh,256, pWinh,256, b_in, nullptr, pnfh,128, 256);

    for(int l=0; l<2; l++){
        const float* W1 = aW1 + (size_t)l*256*256;
        const float* B1 = ab1 + (size_t)l*256;
        const float* W2 = aW2 + (size_t)l*256*256;
        const float* B2 = ab2 + (size_t)l*256;
        const float* NW1= nW1 + (size_t)l*128*256;
        const float* NB1= nb1 + (size_t)l*128;
        const float* NW2= nW2 + (size_t)l*128*128;
        const float* NB2= nb2 + (size_t)l*128;

        k_prep_layer<<<256,256>>>(W1, W2, NW1, NW2);

        // [P|Q] = nf @ W1p^T -> fp16 [NS,512]
        k_gemm<0,false,false,true,false><<<dim3(NS/128,4),256>>>(
            pnfh,128, pW1ph,128, nullptr, nullptr, pPQh,512, 128);

        // zero agg, fused single-pass edge GEMM (build A + elu + red.v2 scatter)
        cudaMemsetAsync(pagg, 0, (size_t)NS*256*sizeof(float));
        k_edge_gemm<<<ES/128,256>>>(pPQh, src, dst, B1, pW2h, B2, pagg);

        // node MLP (mean scaling folded into epilogue)
        k_gemm<1,true,true,true,true><<<dim3(NS/128,1),256>>>(
            pagg,256, pNW1h,256, NB1, pinvdeg, ptmph,128, 256);
        k_gemm<1,true,false,true,false><<<dim3(NS/128,1),256>>>(
            ptmph,128, pNW2h,128, NB2, nullptr, pnfh,128, 128);
    }

    // LSTM: input gates for all timesteps, then tensor-core recurrence
    k_gemm<0,true,false,true,false><<<dim3(NS/128,4),256>>>(
        pnfh,128, pWihh,128, pbsum, nullptr, pgatesh,512, 128);
    k_lstm_mma<<<128,256>>>(pWhhh, pgatesh);

    k_heads<<<N_NODES,32>>>(Wm,bm,Wt,bt,We,be,out);
}

// round 9
// speedup vs baseline: 5.2254x; 1.0674x over previous
#include <cuda_runtime.h>
#include <cuda_fp16.h>
#include <math.h>
#include <stdint.h>

#define N_NODES 1024
#define SEQ     64
#define NEDGE   4096
#define NS      (N_NODES*SEQ)   /* 65536  */
#define ES      (NEDGE*SEQ)     /* 262144 */

// ---------------- scratch (device globals) ----------------
__device__ __half g_xh[NS*256];
__device__ __half g_nfh[NS*128];
__device__ __half g_tmph[NS*128];
__device__ __half g_PQh[NS*512];
__device__ float  g_agg[NS*128];      // post-NW1 aggregate (128-wide now)
__device__ __half g_gatesh[NS*512];
__device__ __half g_Winh[128*256];
__device__ __half g_W1ph[512*128];
__device__ __half g_W2h[256*256];
__device__ __half g_NW1h[128*256];
__device__ __half g_NW2h[128*128];
__device__ __half g_Wihh[512*128];
__device__ __half g_Whhh[512*128];
__device__ float  g_invdeg[N_NODES];
__device__ float  g_h[N_NODES*128];
__device__ float  g_bsum[512];

// ---------------- helpers ----------------
__device__ __forceinline__ float eluf(float v){ return v > 0.f ? v : (__expf(v) - 1.f); }
__device__ __forceinline__ float sigf(float v){ return 1.f/(1.f+__expf(-v)); }
__device__ __forceinline__ float tanhfast(float v){ return 1.f - 2.f/(__expf(2.f*v)+1.f); }
__device__ __forceinline__ uint32_t f2h2(float lo, float hi){
    __half2 h = __floats2half2_rn(lo, hi);
    return *(uint32_t*)&h;
}
__device__ __forceinline__ void mma16(float4 &d, const uint32_t a[4], uint32_t b0, uint32_t b1){
    asm volatile("mma.sync.aligned.m16n8k16.row.col.f32.f16.f16.f32 "
        "{%0,%1,%2,%3}, {%4,%5,%6,%7}, {%8,%9}, {%0,%1,%2,%3};\n"
        : "+f"(d.x), "+f"(d.y), "+f"(d.z), "+f"(d.w)
        : "r"(a[0]), "r"(a[1]), "r"(a[2]), "r"(a[3]), "r"(b0), "r"(b1));
}
__device__ __forceinline__ void ldsm4(uint32_t &r0, uint32_t &r1, uint32_t &r2, uint32_t &r3, uint32_t addr){
    asm volatile("ldmatrix.sync.aligned.m8n8.x4.shared.b16 {%0,%1,%2,%3}, [%4];"
        : "=r"(r0), "=r"(r1), "=r"(r2), "=r"(r3) : "r"(addr));
}
__device__ __forceinline__ void redv2(float* p, float v0, float v1){
    asm volatile("red.global.add.v2.f32 [%0], {%1, %2};" :: "l"(p), "f"(v0), "f"(v1) : "memory");
}
// swizzled 16B-atom byte offset, 2 rows per 128B line, 4 k-atoms per row
__device__ __forceinline__ int swatom(int r, int katom){
    return (r>>1)*128 + ((((r&1)*4 + katom) ^ ((r>>1)&7))<<4);
}

// ---------------- degree / misc / weight prep ----------------
__global__ void k_zero_deg(){
    int i = blockIdx.x*blockDim.x + threadIdx.x;
    if(i < N_NODES) g_invdeg[i] = 0.f;
}
__global__ void k_deg(const int* __restrict__ dst){
    int e = blockIdx.x*blockDim.x + threadIdx.x;
    if(e < NEDGE) atomicAdd(&g_invdeg[dst[e]], 1.f);
}
__global__ void k_fin_deg(){
    int i = blockIdx.x*blockDim.x + threadIdx.x;
    if(i < N_NODES){ float d = g_invdeg[i]; g_invdeg[i] = 1.f/fmaxf(d,1.f); }
}
__global__ void k_bsum(const float* __restrict__ bih, const float* __restrict__ bhh){
    int i = blockIdx.x*blockDim.x + threadIdx.x;
    if(i < 512) g_bsum[i] = bih[i] + bhh[i];
}
__global__ void k_prep_global(const float* __restrict__ W_in, const float* __restrict__ Wih,
                              const float* __restrict__ Whh){
    int i = blockIdx.x*256 + threadIdx.x;
    if(i < 128*256) g_Winh[i] = __float2half(W_in[i]);
    if(i < 512*128){ g_Wihh[i] = __float2half(Wih[i]); g_Whhh[i] = __float2half(Whh[i]); }
}
__global__ void k_prep_layer(const float* __restrict__ W1, const float* __restrict__ W2,
                             const float* __restrict__ NW1, const float* __restrict__ NW2){
    int i = blockIdx.x*256 + threadIdx.x;
    {
        int o = i >> 8, k = i & 255;
        __half v = __float2half(W1[i]);
        if(k < 128) g_W1ph[o*128 + k] = v;
        else        g_W1ph[(256+o)*128 + (k-128)] = v;
        g_W2h[i] = __float2half(W2[i]);
    }
    if(i < 128*256) g_NW1h[i] = __float2half(NW1[i]);
    if(i < 128*128) g_NW2h[i] = __float2half(NW2[i]);
}

// ---------------- build x, vectorized half2 ----------------
__global__ void k_build_x2(const float* __restrict__ itime, const float* __restrict__ iev,
                           const int* __restrict__ ann, const float* __restrict__ emb){
    int idx = blockIdx.x*blockDim.x + threadIdx.x;   // over NS*128 half2
    int row = idx >> 7, cp = idx & 127;
    float e = __ldg(&iev[row]);
    __half2 o;
    if(cp < 63){
        const float* ep = emb + (size_t)__ldg(&ann[row])*127 + cp*2;
        o = __floats2half2_rn(__ldg(ep), __ldg(ep+1));
    } else if(cp == 63){
        o = __floats2half2_rn(__ldg(&emb[(size_t)__ldg(&ann[row])*127 + 126]), e);
    } else {
        int j = cp - 64;
        float pos = exp2f(13.287712379549449f * (float)j * (1.0f/64.0f));
        float r = __ldg(&itime[row]) / pos;
        float sv = __sinf(r), cv = __cosf(r);
        if(e == 0.f){ sv = 0.f; cv = 0.f; }
        o = __floats2half2_rn(sv, cv);
    }
    *(__half2*)&g_xh[(size_t)idx*2] = o;
}

// ---------------- node bias+elu after aggregation ----------------
__global__ void k_node1(const float* __restrict__ agg2, const float* __restrict__ invdeg,
                        const float* __restrict__ nb1, __half* __restrict__ tmph){
    int i = blockIdx.x*256 + threadIdx.x;   // over NS*64 half2
    int row = i >> 6, cp = (i & 63)*2;
    float sc = __ldg(&invdeg[row >> 6]);
    float v0 = eluf(agg2[(size_t)row*128 + cp    ]*sc + __ldg(&nb1[cp    ]));
    float v1 = eluf(agg2[(size_t)row*128 + cp + 1]*sc + __ldg(&nb1[cp + 1]));
    *(__half2*)&tmph[(size_t)row*128 + cp] = __floats2half2_rn(v0, v1);
}

// ================= generic FP16 tensor-core GEMM (mma.sync) =================
template<int ACT, bool BIAS, bool OUTH>
__global__ void __launch_bounds__(256)
k_gemm(const __half* __restrict__ A, int lda,
       const __half* __restrict__ B, int ldb,
       const float* __restrict__ bias,
       void* __restrict__ Cp, int ldc, int K)
{
    __shared__ __align__(16) char sm[2*16384];
    const int m0 = blockIdx.x*128, n0 = blockIdx.y*128;
    const int tid  = threadIdx.x;
    const int warp = tid >> 5, lane = tid & 31;
    const int wm = (warp >> 1)*32;
    const int wn = (warp &  1)*64;
    const int qr = lane >> 2, qc = lane & 3;
    const uint32_t smbase = (uint32_t)__cvta_generic_to_shared(sm);

    const int j  = lane >> 3, rl = lane & 7;
    const int aj = j >> 1;
    const int bj = j & 1;
    int abase[2], asw[2], amb[2];
#pragma unroll
    for(int mi=0; mi<2; mi++){
        int m = wm + mi*16 + (j&1)*8 + rl;
        abase[mi] = (m>>1)*128; asw[mi] = (m>>1)&7; amb[mi] = (m&1)*4;
    }
    int bbase[4], bsw[4], bmb[4];
#pragma unroll
    for(int p=0; p<4; p++){
        int n = wn + p*16 + (j>>1)*8 + rl;
        bbase[p] = (n>>1)*128; bsw[p] = (n>>1)&7; bmb[p] = (n&1)*4;
    }

    float4 acc[2][8];
#pragma unroll
    for(int mi=0;mi<2;mi++)
#pragma unroll
        for(int ni=0;ni<8;ni++) acc[mi][ni] = make_float4(0.f,0.f,0.f,0.f);

    uint4 ra16[2]; uint4 rbv[2];

    auto load_stage = [&](int k0){
#pragma unroll
        for(int it=0; it<2; it++){
            int idx = tid + it*256;
            int r = idx >> 2, c = (idx & 3)*8;
            ra16[it] = *(const uint4*)&A[(size_t)(m0+r)*lda + k0 + c];
            rbv[it]  = *(const uint4*)&B[(size_t)(n0+r)*ldb + k0 + c];
        }
    };
    auto store_stage = [&](int st){
        char* sA = sm + st*16384;
        char* sB = sA + 8192;
#pragma unroll
        for(int it=0; it<2; it++){
            int idx = tid + it*256;
            int r = idx >> 2;
            *(uint4*)(sA + swatom(r, idx&3)) = ra16[it];
            *(uint4*)(sB + swatom(r, idx&3)) = rbv[it];
        }
    };

    const int S = K >> 5;
    load_stage(0);
    store_stage(0);
    __syncthreads();

    for(int s=0; s<S; s++){
        if(s+1 < S) load_stage((s+1)<<5);

        uint32_t sAa = smbase + (s&1)*16384;
        uint32_t sBa = sAa + 8192;
#pragma unroll
        for(int kh=0; kh<2; kh++){
            int ka = kh*2;
            uint32_t a[2][4];
#pragma unroll
            for(int mi=0; mi<2; mi++){
                uint32_t addr = sAa + abase[mi] + ((((amb[mi] + ka + aj) ^ asw[mi]))<<4);
                ldsm4(a[mi][0], a[mi][1], a[mi][2], a[mi][3], addr);
            }
#pragma unroll
            for(int p=0; p<4; p++){
                uint32_t b0,b1r,b2,b3;
                uint32_t addr = sBa + bbase[p] + ((((bmb[p] + ka + bj) ^ bsw[p]))<<4);
                ldsm4(b0, b1r, b2, b3, addr);
                mma16(acc[0][2*p  ], a[0], b0, b1r);
                mma16(acc[0][2*p+1], a[0], b2, b3);
                mma16(acc[1][2*p  ], a[1], b0, b1r);
                mma16(acc[1][2*p+1], a[1], b2, b3);
            }
        }
        if(s+1 < S){
            store_stage((s+1)&1);
            __syncthreads();
        }
    }

#pragma unroll
    for(int mi=0; mi<2; mi++){
#pragma unroll
        for(int rr=0; rr<2; rr++){
            int row = m0 + wm + mi*16 + qr + rr*8;
            size_t crow = (size_t)row*ldc;
#pragma unroll
            for(int ni=0; ni<8; ni++){
                int col = n0 + wn + ni*8 + qc*2;
                float v0 = (rr==0 ? acc[mi][ni].x : acc[mi][ni].z);
                float v1 = (rr==0 ? acc[mi][ni].y : acc[mi][ni].w);
                if(BIAS){ v0 += bias[col]; v1 += bias[col+1]; }
                if(ACT==1){ v0 = eluf(v0); v1 = eluf(v1); }
                if(OUTH){
                    *(__half2*)&(((__half*)Cp)[crow + col]) = __floats2half2_rn(v0, v1);
                } else {
                    *(float2*)&(((float*)Cp)[crow + col]) = make_float2(v0, v1);
                }
            }
        }
    }
}

// ================= fused edge GEMM + NW1 GEMM =================
// Phase 1: m2pre = (elu(P[src]+Q[dst]+b1)) @ W2^T   [128 x 256]
// Phase 2: z = elu(m2pre + b2) @ NW1^T              [128 x 128]
// Epilogue: red.v2 scatter z into agg2[dst*64+s][col]  (bias/elu of node MLP applied later)
// Dynamic smem 80KB: phase1 A 2x8KB @0, B 2x16KB @16384; phase2 m2 8x8KB @0 (overlay),
// NW1 stage 2x8KB @65536.
__global__ void __launch_bounds__(256,1)
k_edge_fused(const __half* __restrict__ PQ,
             const int* __restrict__ srcp, const int* __restrict__ dstp,
             const float* __restrict__ b1,
             const __half* __restrict__ W2h, const float* __restrict__ b2,
             const __half* __restrict__ NW1h,
             float* __restrict__ agg2)
{
    extern __shared__ __align__(16) char esm[];
    const int m0 = blockIdx.x*128;
    const int tid  = threadIdx.x;
    const int warp = tid >> 5, lane = tid & 31;
    const int wm  = (warp >> 1)*32;
    const int wn  = (warp &  1)*128;    // phase 1 (N=256)
    const int wn2 = (warp &  1)*64;     // phase 2 (N=128)
    const int qr = lane >> 2, qc = lane & 3;
    const uint32_t smbase = (uint32_t)__cvta_generic_to_shared(esm);
    const uint32_t AOFF = 0, BOFF = 16384, MOFF = 0, NOFF = 65536;

    const int j  = lane >> 3, rl = lane & 7;
    const int aj = j >> 1;
    const int bj = j & 1;
    int abase[2], asw[2], amb[2];
#pragma unroll
    for(int mi=0; mi<2; mi++){
        int m = wm + mi*16 + (j&1)*8 + rl;
        abase[mi] = (m>>1)*128; asw[mi] = (m>>1)&7; amb[mi] = (m&1)*4;
    }
    int bbase[8], bsw[8], bmb[8];           // phase 1 B groups (128 cols)
#pragma unroll
    for(int p=0; p<8; p++){
        int n = wn + p*16 + (j>>1)*8 + rl;
        bbase[p] = (n>>1)*128; bsw[p] = (n>>1)&7; bmb[p] = (n&1)*4;
    }
    int cbase[4], csw[4], cmb[4];           // phase 2 B groups (64 cols)
#pragma unroll
    for(int p=0; p<4; p++){
        int n = wn2 + p*16 + (j>>1)*8 + rl;
        cbase[p] = (n>>1)*128; csw[p] = (n>>1)&7; cmb[p] = (n&1)*4;
    }

    // A-build indexing (2 slots/thread, 8 halves each)
    int ar[2], ac[2]; const __half *ap[2], *aq[2];
#pragma unroll
    for(int it=0; it<2; it++){
        int idx = tid + it*256;
        ar[it] = idx >> 2;
        ac[it] = (idx & 3) * 8;
        int grow = m0 + ar[it];
        int e = grow >> 6, srow = grow & 63;
        int se = __ldg(&srcp[e]);
        int de = __ldg(&dstp[e]);
        ap[it] = PQ + ((size_t)se*64 + srow)*512;
        aq[it] = PQ + ((size_t)de*64 + srow)*512 + 256;
    }

    float4 acc[2][16];
#pragma unroll
    for(int mi=0;mi<2;mi++)
#pragma unroll
        for(int ni=0;ni<16;ni++) acc[mi][ni] = make_float4(0.f,0.f,0.f,0.f);

    uint4 ra[2]; uint4 rb[4];

    auto load_stage = [&](int k0){
#pragma unroll
        for(int it=0; it<2; it++){
            int kc = k0 + ac[it];
            uint4 pv = *(const uint4*)(ap[it] + kc);
            uint4 qv = *(const uint4*)(aq[it] + kc);
            float4 bb0 = *(const float4*)&b1[kc];
            float4 bb1 = *(const float4*)&b1[kc+4];
            const __half2* phh = (const __half2*)&pv;
            const __half2* qhh = (const __half2*)&qv;
            float bl[8] = {bb0.x,bb0.y,bb0.z,bb0.w,bb1.x,bb1.y,bb1.z,bb1.w};
            uint32_t o[4];
#pragma unroll
            for(int w=0; w<4; w++){
                float2 pf = __half22float2(phh[w]);
                float2 qf = __half22float2(qhh[w]);
                o[w] = f2h2(eluf(pf.x+qf.x+bl[2*w]), eluf(pf.y+qf.y+bl[2*w+1]));
            }
            ra[it] = make_uint4(o[0],o[1],o[2],o[3]);
        }
#pragma unroll
        for(int it=0; it<4; it++){
            int idx = tid + it*256;      // 0..1023
            int r = idx >> 2, c = (idx & 3)*8;
            rb[it] = *(const uint4*)&W2h[(size_t)r*256 + k0 + c];
        }
    };
    auto store_stage = [&](int st){
#pragma unroll
        for(int it=0; it<2; it++)
            *(uint4*)(esm + AOFF + st*8192 + swatom(ar[it], ac[it]>>3)) = ra[it];
#pragma unroll
        for(int it=0; it<4; it++){
            int idx = tid + it*256;
            int r = idx >> 2;
            *(uint4*)(esm + BOFF + st*16384 + swatom(r, idx&3)) = rb[it];
        }
    };

    load_stage(0);
    store_stage(0);
    __syncthreads();

    for(int s=0; s<8; s++){
        if(s+1 < 8) load_stage((s+1)<<5);

        uint32_t sAa = smbase + AOFF + (s&1)*8192;
        uint32_t sBa = smbase + BOFF + (s&1)*16384;
#pragma unroll
        for(int kh=0; kh<2; kh++){
            int ka = kh*2;
            uint32_t a[2][4];
#pragma unroll
            for(int mi=0; mi<2; mi++){
                uint32_t addr = sAa + abase[mi] + ((((amb[mi] + ka + aj) ^ asw[mi]))<<4);
                ldsm4(a[mi][0], a[mi][1], a[mi][2], a[mi][3], addr);
            }
#pragma unroll
            for(int p=0; p<8; p++){
                uint32_t b0,b1r,b2r,b3;
                uint32_t addr = sBa + bbase[p] + ((((bmb[p] + ka + bj) ^ bsw[p]))<<4);
                ldsm4(b0, b1r, b2r, b3, addr);
                mma16(acc[0][2*p  ], a[0], b0, b1r);
                mma16(acc[0][2*p+1], a[0], b2r, b3);
                mma16(acc[1][2*p  ], a[1], b0, b1r);
                mma16(acc[1][2*p+1], a[1], b2r, b3);
            }
        }
        if(s+1 < 8){
            store_stage((s+1)&1);
            __syncthreads();
        }
    }

    // ---- phase 1 -> phase 2 handoff: m2 = elu(acc + b2) into smem (fp16, sliced) ----
    __syncthreads();   // all warps done reading phase-1 buffers before overlay
#pragma unroll
    for(int mi=0; mi<2; mi++){
#pragma unroll
        for(int rr=0; rr<2; rr++){
            int row = wm + mi*16 + qr + rr*8;
#pragma unroll
            for(int ni=0; ni<16; ni++){
                int col = wn + ni*8 + qc*2;
                float v0 = (rr==0 ? acc[mi][ni].x : acc[mi][ni].z) + __ldg(&b2[col]);
                float v1 = (rr==0 ? acc[mi][ni].y : acc[mi][ni].w) + __ldg(&b2[col+1]);
                v0 = eluf(v0); v1 = eluf(v1);
                int ksl = col >> 5, c = col & 31;
                uint32_t off = MOFF + (uint32_t)ksl*8192 + swatom(row, c>>3) + (c&7)*2;
                *(__half2*)(esm + off) = __floats2half2_rn(v0, v1);
            }
        }
    }
    __syncthreads();

    // ---- phase 2: z = m2 @ NW1^T (128x128x256), NW1 tiles double-buffered ----
    float4 acc2[2][8];
#pragma unroll
    for(int mi=0;mi<2;mi++)
#pragma unroll
        for(int ni=0;ni<8;ni++) acc2[mi][ni] = make_float4(0.f,0.f,0.f,0.f);

    uint4 nr[2];
    auto loadN = [&](int k0){
#pragma unroll
        for(int it=0; it<2; it++){
            int idx = tid + it*256;
            int n = idx >> 2, kc = (idx & 3)*8;
            nr[it] = *(const uint4*)&NW1h[(size_t)n*256 + k0 + kc];
        }
    };
    auto storeN = [&](int st){
#pragma unroll
        for(int it=0; it<2; it++){
            int idx = tid + it*256;
            int n = idx >> 2;
            *(uint4*)(esm + NOFF + st*8192 + swatom(n, idx&3)) = nr[it];
        }
    };
    loadN(0); storeN(0); __syncthreads();

    for(int s2=0; s2<8; s2++){
        if(s2+1 < 8) loadN((s2+1)<<5);

        uint32_t sAa = smbase + MOFF + s2*8192;
        uint32_t sBa = smbase + NOFF + (s2&1)*8192;
#pragma unroll
        for(int kh=0; kh<2; kh++){
            int ka = kh*2;
            uint32_t a[2][4];
#pragma unroll
            for(int mi=0; mi<2; mi++){
                uint32_t addr = sAa + abase[mi] + ((((amb[mi] + ka + aj) ^ asw[mi]))<<4);
                ldsm4(a[mi][0], a[mi][1], a[mi][2], a[mi][3], addr);
            }
#pragma unroll
            for(int p=0; p<4; p++){
                uint32_t b0,b1r,b2r,b3;
                uint32_t addr = sBa + cbase[p] + ((((cmb[p] + ka + bj) ^ csw[p]))<<4);
                ldsm4(b0, b1r, b2r, b3, addr);
                mma16(acc2[0][2*p  ], a[0], b0, b1r);
                mma16(acc2[0][2*p+1], a[0], b2r, b3);
                mma16(acc2[1][2*p  ], a[1], b0, b1r);
                mma16(acc2[1][2*p+1], a[1], b2r, b3);
            }
        }
        if(s2+1 < 8){
            storeN((s2+1)&1);
            __syncthreads();
        }
    }

    // ---- epilogue: scatter z (raw, pre-bias) into agg2 ----
#pragma unroll
    for(int mi=0; mi<2; mi++){
#pragma unroll
        for(int rr=0; rr<2; rr++){
            int row = m0 + wm + mi*16 + qr + rr*8;
            int e = row >> 6, s = row & 63;
            size_t crow = (size_t)(__ldg(&dstp[e])*64 + s)*128;
#pragma unroll
            for(int ni=0; ni<8; ni++){
                int col = wn2 + ni*8 + qc*2;
                float v0 = (rr==0 ? acc2[mi][ni].x : acc2[mi][ni].z);
                float v1 = (rr==0 ? acc2[mi][ni].y : acc2[mi][ni].w);
                redv2(&agg2[crow + col], v0, v1);
            }
        }
    }
}

// ================= tensor-core persistent LSTM =================
__global__ void __launch_bounds__(256,1)
k_lstm_mma(const __half* __restrict__ Whh, const __half* __restrict__ gates){
    __shared__ __align__(16) __half hA[16*136];
    __shared__ float G[8][512];
    const int tid = threadIdx.x, warp = tid>>5, lane = tid&31;
    const int nb = blockIdx.x*8;
    const int wn = warp*64;
    const uint32_t hAb = (uint32_t)__cvta_generic_to_shared(hA);

    float cst[4] = {0.f,0.f,0.f,0.f};
    for(int i=tid; i<16*136; i+=256) hA[i] = __float2half(0.f);

    uint32_t bf[8][8][2];
    {
        int bn = lane>>2, bk = (lane&3)*2;
#pragma unroll
        for(int nt=0; nt<8; nt++)
#pragma unroll
        for(int kt=0; kt<8; kt++){
            const __half* p = Whh + (size_t)(wn + nt*8 + bn)*128 + kt*16 + bk;
            bf[nt][kt][0] = *(const uint32_t*)p;
            bf[nt][kt][1] = *(const uint32_t*)(p + 8);
        }
    }
    __syncthreads();

    const int j = lane>>3, rl = lane&7;
    const int arow = (j&1)*8 + rl;
    const int cr = lane>>2, cc = (lane&3)*2;

    for(int t=0; t<64; t++){
        uint32_t a[8][4];
#pragma unroll
        for(int kt=0; kt<8; kt++){
            uint32_t addr = hAb + arow*272 + (uint32_t)((kt*2 + (j>>1))*16);
            ldsm4(a[kt][0], a[kt][1], a[kt][2], a[kt][3], addr);
        }
        float4 acc[8];
#pragma unroll
        for(int nt=0; nt<8; nt++) acc[nt] = make_float4(0.f,0.f,0.f,0.f);
#pragma unroll
        for(int kt=0; kt<8; kt++)
#pragma unroll
            for(int nt=0; nt<8; nt++)
                mma16(acc[nt], a[kt], bf[nt][kt][0], bf[nt][kt][1]);

#pragma unroll
        for(int nt=0; nt<8; nt++){
            int col = wn + nt*8 + cc;
            __half2 gv = *(const __half2*)&gates[((size_t)(nb+cr)*64 + t)*512 + col];
            float2 gf = __half22float2(gv);
            G[cr][col]   = acc[nt].x + gf.x;
            G[cr][col+1] = acc[nt].y + gf.y;
        }
        __syncthreads();

#pragma unroll
        for(int q=0; q<4; q++){
            int idx = q*256 + tid;
            int n = idx>>7, jj = idx&127;
            float ig=G[n][jj], fg=G[n][128+jj], gg=G[n][256+jj], og=G[n][384+jj];
            float cn = sigf(fg)*cst[q] + sigf(ig)*tanhfast(gg);
            cst[q] = cn;
            float h = sigf(og)*tanhfast(cn);
            hA[n*136 + jj] = __float2half(h);
            if(t==63) g_h[(size_t)(nb+n)*128 + jj] = h;
        }
        __syncthreads();
    }
}

// ---------------- output heads ----------------
__global__ void k_heads(const float* __restrict__ Wm, const float* __restrict__ bm,
                        const float* __restrict__ Wt, const float* __restrict__ bt,
                        const float* __restrict__ We, const float* __restrict__ be,
                        float* __restrict__ out){
    int n = blockIdx.x;
    int l = threadIdx.x;
    float sm=0.f, st=0.f, se=0.f;
    for(int jj=l;jj<128;jj+=32){
        float h = g_h[(size_t)n*128 + jj];
        sm += h*Wm[jj]; st += h*Wt[jj]; se += h*We[jj];
    }
#pragma unroll
    for(int o=16;o;o>>=1){
        sm += __shfl_down_sync(0xffffffffu, sm, o);
        st += __shfl_down_sync(0xffffffffu, st, o);
        se += __shfl_down_sync(0xffffffffu, se, o);
    }
    if(l==0){
        out[n]            = sm + bm[0];
        out[N_NODES + n]  = st + bt[0];
        out[2*N_NODES + n]= se + be[0];
    }
}

// ---------------- host launcher ----------------
extern "C" void kernel_launch(void* const* d_in, const int* in_sizes, int n_in,
                              void* d_out, int out_size)
{
    const int*   edge  = (const int*)  d_in[0];
    const float* itime = (const float*)d_in[1];
    const float* iev   = (const float*)d_in[2];
    const int*   ann   = (const int*)  d_in[3];
    const float* emb   = (const float*)d_in[4];
    const float* W_in  = (const float*)d_in[5];
    const float* b_in  = (const float*)d_in[6];
    const float* nW1   = (const float*)d_in[7];
    const float* nb1   = (const float*)d_in[8];
    const float* nW2   = (const float*)d_in[9];
    const float* nb2   = (const float*)d_in[10];
    const float* aW1   = (const float*)d_in[11];
    const float* ab1   = (const float*)d_in[12];
    const float* aW2   = (const float*)d_in[13];
    const float* ab2   = (const float*)d_in[14];
    const float* Wih   = (const float*)d_in[15];
    const float* Whh   = (const float*)d_in[16];
    const float* bih   = (const float*)d_in[17];
    const float* bhh   = (const float*)d_in[18];
    const float* Wm    = (const float*)d_in[19];
    const float* bm    = (const float*)d_in[20];
    const float* Wt    = (const float*)d_in[21];
    const float* bt    = (const float*)d_in[22];
    const float* We    = (const float*)d_in[23];
    const float* be    = (const float*)d_in[24];
    float* out = (float*)d_out;

    const int* src = edge;
    const int* dst = edge + NEDGE;

    __half *pxh, *pnfh, *ptmph, *pPQh, *pgatesh;
    __half *pWinh, *pW1ph, *pW2h, *pNW1h, *pNW2h, *pWihh, *pWhhh;
    float *pagg, *pinvdeg, *pbsum;
    cudaGetSymbolAddress((void**)&pxh,    g_xh);
    cudaGetSymbolAddress((void**)&pnfh,   g_nfh);
    cudaGetSymbolAddress((void**)&ptmph,  g_tmph);
    cudaGetSymbolAddress((void**)&pPQh,   g_PQh);
    cudaGetSymbolAddress((void**)&pgatesh,g_gatesh);
    cudaGetSymbolAddress((void**)&pWinh,  g_Winh);
    cudaGetSymbolAddress((void**)&pW1ph,  g_W1ph);
    cudaGetSymbolAddress((void**)&pW2h,   g_W2h);
    cudaGetSymbolAddress((void**)&pNW1h,  g_NW1h);
    cudaGetSymbolAddress((void**)&pNW2h,  g_NW2h);
    cudaGetSymbolAddress((void**)&pWihh,  g_Wihh);
    cudaGetSymbolAddress((void**)&pWhhh,  g_Whhh);
    cudaGetSymbolAddress((void**)&pagg,   g_agg);
    cudaGetSymbolAddress((void**)&pinvdeg,g_invdeg);
    cudaGetSymbolAddress((void**)&pbsum,  g_bsum);

    cudaFuncSetAttribute(k_edge_fused, cudaFuncAttributeMaxDynamicSharedMemorySize, 81920);

    // degrees + weight prep
    k_zero_deg<<<4,256>>>();
    k_deg<<<(NEDGE+255)/256,256>>>(dst);
    k_fin_deg<<<4,256>>>();
    k_prep_global<<<256,256>>>(W_in, Wih, Whh);
    k_bsum<<<2,256>>>(bih, bhh);

    // input embedding: x -> nf
    k_build_x2<<<NS*128/256,256>>>(itime, iev, ann, emb);
    k_gemm<0,true,true><<<dim3(NS/128,1),256>>>(
        pxh,256, pWinh,256, b_in, pnfh,128, 256);

    for(int l=0; l<2; l++){
        const float* W1 = aW1 + (size_t)l*256*256;
        const float* B1 = ab1 + (size_t)l*256;
        const float* W2 = aW2 + (size_t)l*256*256;
        const float* B2 = ab2 + (size_t)l*256;
        const float* NW1= nW1 + (size_t)l*128*256;
        const float* NB1= nb1 + (size_t)l*128;
        const float* NW2= nW2 + (size_t)l*128*128;
        const float* NB2= nb2 + (size_t)l*128;

        k_prep_layer<<<256,256>>>(W1, W2, NW1, NW2);

        // [P|Q] = nf @ W1p^T -> fp16 [NS,512]
        k_gemm<0,false,true><<<dim3(NS/128,4),256>>>(
            pnfh,128, pW1ph,128, nullptr, pPQh,512, 128);

        // zero agg2 (128-wide), fused edge+NW1 GEMM with red.v2 scatter
        cudaMemsetAsync(pagg, 0, (size_t)NS*128*sizeof(float));
        k_edge_fused<<<ES/128,256,81920>>>(pPQh, src, dst, B1, pW2h, B2, pNW1h, pagg);

        // node bias+elu, then NW2 GEMM
        k_node1<<<NS*64/256,256>>>(pagg, pinvdeg, NB1, ptmph);
        k_gemm<1,true,true><<<dim3(NS/128,1),256>>>(
            ptmph,128, pNW2h,128, NB2, pnfh,128, 128);
    }

    // LSTM: input gates for all timesteps, then tensor-core recurrence
    k_gemm<0,true,true><<<dim3(NS/128,4),256>>>(
        pnfh,128, pWihh,128, pbsum, pgatesh,512, 128);
    k_lstm_mma<<<128,256>>>(pWhhh, pgatesh);

    k_heads<<<N_NODES,32>>>(Wm,bm,Wt,bt,We,be,out);
}

// round 10
// speedup vs baseline: 5.5419x; 1.0606x over previous
#include <cuda_runtime.h>
#include <cuda_fp16.h>
#include <math.h>
#include <stdint.h>

#define N_NODES 1024
#define SEQ     64
#define NEDGE   4096
#define NS      (N_NODES*SEQ)   /* 65536  */
#define ES      (NEDGE*SEQ)     /* 262144 */

// ---------------- scratch (device globals) ----------------
__device__ __half g_xh[NS*256];
__device__ __half g_nfh[NS*128];
__device__ __half g_tmph[NS*128];
__device__ __half g_PQh[NS*512];
__device__ float  g_agg[NS*128];      // post-NW1 aggregate (128-wide)
__device__ __half g_gatesh[NS*512];
__device__ __half g_Winh[128*256];
__device__ __half g_W1ph[512*128];
__device__ __half g_W2h[256*256];
__device__ __half g_NW1h[128*256];
__device__ __half g_NW2h[128*128];
__device__ __half g_Wihh[512*128];
__device__ __half g_Whhh[512*128];
__device__ float  g_invdeg[N_NODES];
__device__ float  g_h[N_NODES*128];
__device__ float  g_bsum[512];

// ---------------- helpers ----------------
__device__ __forceinline__ float eluf(float v){ return v > 0.f ? v : (__expf(v) - 1.f); }
__device__ __forceinline__ float sigf(float v){ return 1.f/(1.f+__expf(-v)); }
__device__ __forceinline__ float tanhfast(float v){ return 1.f - 2.f/(__expf(2.f*v)+1.f); }
__device__ __forceinline__ uint32_t f2h2(float lo, float hi){
    __half2 h = __floats2half2_rn(lo, hi);
    return *(uint32_t*)&h;
}
__device__ __forceinline__ void mma16(float4 &d, const uint32_t a[4], uint32_t b0, uint32_t b1){
    asm volatile("mma.sync.aligned.m16n8k16.row.col.f32.f16.f16.f32 "
        "{%0,%1,%2,%3}, {%4,%5,%6,%7}, {%8,%9}, {%0,%1,%2,%3};\n"
        : "+f"(d.x), "+f"(d.y), "+f"(d.z), "+f"(d.w)
        : "r"(a[0]), "r"(a[1]), "r"(a[2]), "r"(a[3]), "r"(b0), "r"(b1));
}
__device__ __forceinline__ void ldsm4(uint32_t &r0, uint32_t &r1, uint32_t &r2, uint32_t &r3, uint32_t addr){
    asm volatile("ldmatrix.sync.aligned.m8n8.x4.shared.b16 {%0,%1,%2,%3}, [%4];"
        : "=r"(r0), "=r"(r1), "=r"(r2), "=r"(r3) : "r"(addr));
}
__device__ __forceinline__ void redv2(float* p, float v0, float v1){
    asm volatile("red.global.add.v2.f32 [%0], {%1, %2};" :: "l"(p), "f"(v0), "f"(v1) : "memory");
}
__device__ __forceinline__ void cpa16(uint32_t dst, const void* src){
    asm volatile("cp.async.cg.shared.global [%0], [%1], 16;" :: "r"(dst), "l"(src));
}
#define CP_COMMIT() asm volatile("cp.async.commit_group;" ::: "memory")
#define CP_WAIT(n)  asm volatile("cp.async.wait_group %0;" :: "n"(n) : "memory")
// swizzled 16B-atom byte offset, 2 rows per 128B line, 4 k-atoms per row
__device__ __forceinline__ int swatom(int r, int katom){
    return (r>>1)*128 + ((((r&1)*4 + katom) ^ ((r>>1)&7))<<4);
}

// ---------------- degree / misc / weight prep ----------------
__global__ void k_zero_deg(){
    int i = blockIdx.x*blockDim.x + threadIdx.x;
    if(i < N_NODES) g_invdeg[i] = 0.f;
}
__global__ void k_deg(const int* __restrict__ dst){
    int e = blockIdx.x*blockDim.x + threadIdx.x;
    if(e < NEDGE) atomicAdd(&g_invdeg[dst[e]], 1.f);
}
__global__ void k_fin_deg(){
    int i = blockIdx.x*blockDim.x + threadIdx.x;
    if(i < N_NODES){ float d = g_invdeg[i]; g_invdeg[i] = 1.f/fmaxf(d,1.f); }
}
__global__ void k_bsum(const float* __restrict__ bih, const float* __restrict__ bhh){
    int i = blockIdx.x*blockDim.x + threadIdx.x;
    if(i < 512) g_bsum[i] = bih[i] + bhh[i];
}
__global__ void k_prep_global(const float* __restrict__ W_in, const float* __restrict__ Wih,
                              const float* __restrict__ Whh){
    int i = blockIdx.x*256 + threadIdx.x;
    if(i < 128*256) g_Winh[i] = __float2half(W_in[i]);
    if(i < 512*128){ g_Wihh[i] = __float2half(Wih[i]); g_Whhh[i] = __float2half(Whh[i]); }
}
__global__ void k_prep_layer(const float* __restrict__ W1, const float* __restrict__ W2,
                             const float* __restrict__ NW1, const float* __restrict__ NW2){
    int i = blockIdx.x*256 + threadIdx.x;
    {
        int o = i >> 8, k = i & 255;
        __half v = __float2half(W1[i]);
        if(k < 128) g_W1ph[o*128 + k] = v;
        else        g_W1ph[(256+o)*128 + (k-128)] = v;
        g_W2h[i] = __float2half(W2[i]);
    }
    if(i < 128*256) g_NW1h[i] = __float2half(NW1[i]);
    if(i < 128*128) g_NW2h[i] = __float2half(NW2[i]);
}

// ---------------- build x, vectorized half2 ----------------
__global__ void k_build_x2(const float* __restrict__ itime, const float* __restrict__ iev,
                           const int* __restrict__ ann, const float* __restrict__ emb){
    int idx = blockIdx.x*blockDim.x + threadIdx.x;   // over NS*128 half2
    int row = idx >> 7, cp = idx & 127;
    float e = __ldg(&iev[row]);
    __half2 o;
    if(cp < 63){
        const float* ep = emb + (size_t)__ldg(&ann[row])*127 + cp*2;
        o = __floats2half2_rn(__ldg(ep), __ldg(ep+1));
    } else if(cp == 63){
        o = __floats2half2_rn(__ldg(&emb[(size_t)__ldg(&ann[row])*127 + 126]), e);
    } else {
        int j = cp - 64;
        float pos = exp2f(13.287712379549449f * (float)j * (1.0f/64.0f));
        float r = __ldg(&itime[row]) / pos;
        float sv = __sinf(r), cv = __cosf(r);
        if(e == 0.f){ sv = 0.f; cv = 0.f; }
        o = __floats2half2_rn(sv, cv);
    }
    *(__half2*)&g_xh[(size_t)idx*2] = o;
}

// ---------------- node bias+elu after aggregation ----------------
__global__ void k_node1(const float* __restrict__ agg2, const float* __restrict__ invdeg,
                        const float* __restrict__ nb1, __half* __restrict__ tmph){
    int i = blockIdx.x*256 + threadIdx.x;   // over NS*64 half2
    int row = i >> 6, cp = (i & 63)*2;
    float sc = __ldg(&invdeg[row >> 6]);
    float v0 = eluf(agg2[(size_t)row*128 + cp    ]*sc + __ldg(&nb1[cp    ]));
    float v1 = eluf(agg2[(size_t)row*128 + cp + 1]*sc + __ldg(&nb1[cp + 1]));
    *(__half2*)&tmph[(size_t)row*128 + cp] = __floats2half2_rn(v0, v1);
}

// ================= generic FP16 tensor-core GEMM (mma.sync) =================
template<int ACT, bool BIAS, bool OUTH>
__global__ void __launch_bounds__(256)
k_gemm(const __half* __restrict__ A, int lda,
       const __half* __restrict__ B, int ldb,
       const float* __restrict__ bias,
       void* __restrict__ Cp, int ldc, int K)
{
    __shared__ __align__(16) char sm[2*16384];
    const int m0 = blockIdx.x*128, n0 = blockIdx.y*128;
    const int tid  = threadIdx.x;
    const int warp = tid >> 5, lane = tid & 31;
    const int wm = (warp >> 1)*32;
    const int wn = (warp &  1)*64;
    const int qr = lane >> 2, qc = lane & 3;
    const uint32_t smbase = (uint32_t)__cvta_generic_to_shared(sm);

    const int j  = lane >> 3, rl = lane & 7;
    const int aj = j >> 1;
    const int bj = j & 1;
    int abase[2], asw[2], amb[2];
#pragma unroll
    for(int mi=0; mi<2; mi++){
        int m = wm + mi*16 + (j&1)*8 + rl;
        abase[mi] = (m>>1)*128; asw[mi] = (m>>1)&7; amb[mi] = (m&1)*4;
    }
    int bbase[4], bsw[4], bmb[4];
#pragma unroll
    for(int p=0; p<4; p++){
        int n = wn + p*16 + (j>>1)*8 + rl;
        bbase[p] = (n>>1)*128; bsw[p] = (n>>1)&7; bmb[p] = (n&1)*4;
    }

    float4 acc[2][8];
#pragma unroll
    for(int mi=0;mi<2;mi++)
#pragma unroll
        for(int ni=0;ni<8;ni++) acc[mi][ni] = make_float4(0.f,0.f,0.f,0.f);

    uint4 ra16[2]; uint4 rbv[2];

    auto load_stage = [&](int k0){
#pragma unroll
        for(int it=0; it<2; it++){
            int idx = tid + it*256;
            int r = idx >> 2, c = (idx & 3)*8;
            ra16[it] = *(const uint4*)&A[(size_t)(m0+r)*lda + k0 + c];
            rbv[it]  = *(const uint4*)&B[(size_t)(n0+r)*ldb + k0 + c];
        }
    };
    auto store_stage = [&](int st){
        char* sA = sm + st*16384;
        char* sB = sA + 8192;
#pragma unroll
        for(int it=0; it<2; it++){
            int idx = tid + it*256;
            int r = idx >> 2;
            *(uint4*)(sA + swatom(r, idx&3)) = ra16[it];
            *(uint4*)(sB + swatom(r, idx&3)) = rbv[it];
        }
    };

    const int S = K >> 5;
    load_stage(0);
    store_stage(0);
    __syncthreads();

    for(int s=0; s<S; s++){
        if(s+1 < S) load_stage((s+1)<<5);

        uint32_t sAa = smbase + (s&1)*16384;
        uint32_t sBa = sAa + 8192;
#pragma unroll
        for(int kh=0; kh<2; kh++){
            int ka = kh*2;
            uint32_t a[2][4];
#pragma unroll
            for(int mi=0; mi<2; mi++){
                uint32_t addr = sAa + abase[mi] + ((((amb[mi] + ka + aj) ^ asw[mi]))<<4);
                ldsm4(a[mi][0], a[mi][1], a[mi][2], a[mi][3], addr);
            }
#pragma unroll
            for(int p=0; p<4; p++){
                uint32_t b0,b1r,b2,b3;
                uint32_t addr = sBa + bbase[p] + ((((bmb[p] + ka + bj) ^ bsw[p]))<<4);
                ldsm4(b0, b1r, b2, b3, addr);
                mma16(acc[0][2*p  ], a[0], b0, b1r);
                mma16(acc[0][2*p+1], a[0], b2, b3);
                mma16(acc[1][2*p  ], a[1], b0, b1r);
                mma16(acc[1][2*p+1], a[1], b2, b3);
            }
        }
        if(s+1 < S){
            store_stage((s+1)&1);
            __syncthreads();
        }
    }

#pragma unroll
    for(int mi=0; mi<2; mi++){
#pragma unroll
        for(int rr=0; rr<2; rr++){
            int row = m0 + wm + mi*16 + qr + rr*8;
            size_t crow = (size_t)row*ldc;
#pragma unroll
            for(int ni=0; ni<8; ni++){
                int col = n0 + wn + ni*8 + qc*2;
                float v0 = (rr==0 ? acc[mi][ni].x : acc[mi][ni].z);
                float v1 = (rr==0 ? acc[mi][ni].y : acc[mi][ni].w);
                if(BIAS){ v0 += bias[col]; v1 += bias[col+1]; }
                if(ACT==1){ v0 = eluf(v0); v1 = eluf(v1); }
                if(OUTH){
                    *(__half2*)&(((__half*)Cp)[crow + col]) = __floats2half2_rn(v0, v1);
                } else {
                    *(float2*)&(((float*)Cp)[crow + col]) = make_float2(v0, v1);
                }
            }
        }
    }
}

// ================= fused edge GEMM + NW1 GEMM, 512 threads =================
// Phase 1: m2pre = (elu(P[src]+Q[dst]+b1)) @ W2^T   [128 x 256]
// Phase 2: z = elu(m2pre + b2) @ NW1^T              [128 x 128]
// Epilogue: red.v2 scatter z into agg2[dst*64+s][col].
// 16 warps: phase1 warp tile 32x64 (4x4 grid), phase2 32x32.
// Smem 80KB: A 2x8KB @0, W2 2x16KB @16384; m2 8x8KB @0 (overlay), NW1 2x8KB @65536.
// W2/NW1 streamed via cp.async.
__global__ void __launch_bounds__(512,1)
k_edge_fused(const __half* __restrict__ PQ,
             const int* __restrict__ srcp, const int* __restrict__ dstp,
             const float* __restrict__ b1,
             const __half* __restrict__ W2h, const float* __restrict__ b2,
             const __half* __restrict__ NW1h,
             float* __restrict__ agg2)
{
    extern __shared__ __align__(16) char esm[];
    const int m0 = blockIdx.x*128;
    const int tid  = threadIdx.x;
    const int warp = tid >> 5, lane = tid & 31;
    const int wm  = (warp >> 2)*32;     // 0,32,64,96
    const int wn  = (warp &  3)*64;     // phase 1: 0,64,128,192
    const int wn2 = (warp &  3)*32;     // phase 2: 0,32,64,96
    const int qr = lane >> 2, qc = lane & 3;
    const uint32_t smbase = (uint32_t)__cvta_generic_to_shared(esm);
    const uint32_t AOFF = 0, BOFF = 16384, MOFF = 0, NOFF = 65536;

    const int j  = lane >> 3, rl = lane & 7;
    const int aj = j >> 1;
    const int bj = j & 1;
    int abase[2], asw[2], amb[2];
#pragma unroll
    for(int mi=0; mi<2; mi++){
        int m = wm + mi*16 + (j&1)*8 + rl;
        abase[mi] = (m>>1)*128; asw[mi] = (m>>1)&7; amb[mi] = (m&1)*4;
    }
    int bbase[4], bsw[4], bmb[4];           // phase 1 B groups (64 cols)
#pragma unroll
    for(int p=0; p<4; p++){
        int n = wn + p*16 + (j>>1)*8 + rl;
        bbase[p] = (n>>1)*128; bsw[p] = (n>>1)&7; bmb[p] = (n&1)*4;
    }
    int cbase[2], csw[2], cmb[2];           // phase 2 B groups (32 cols)
#pragma unroll
    for(int p=0; p<2; p++){
        int n = wn2 + p*16 + (j>>1)*8 + rl;
        cbase[p] = (n>>1)*128; csw[p] = (n>>1)&7; cmb[p] = (n&1)*4;
    }

    // A-build indexing: one uint4 slot per thread (128 rows x 4 chunks)
    const int ar = tid >> 2;            // 0..127
    const int ac = (tid & 3) * 8;       // 0,8,16,24
    const __half *ap, *aq;
    {
        int grow = m0 + ar;
        int e = grow >> 6, srow = grow & 63;
        ap = PQ + ((size_t)__ldg(&srcp[e])*64 + srow)*512;
        aq = PQ + ((size_t)__ldg(&dstp[e])*64 + srow)*512 + 256;
    }
    const uint32_t aslot = (uint32_t)(swatom(ar, (tid&3)));   // katom = ac>>3 = tid&3

    float4 acc[2][8];
#pragma unroll
    for(int mi=0;mi<2;mi++)
#pragma unroll
        for(int ni=0;ni<8;ni++) acc[mi][ni] = make_float4(0.f,0.f,0.f,0.f);

    uint4 ra;

    auto buildA = [&](int k0){
        int kc = k0 + ac;
        uint4 pv = *(const uint4*)(ap + kc);
        uint4 qv = *(const uint4*)(aq + kc);
        float4 bb0 = *(const float4*)&b1[kc];
        float4 bb1 = *(const float4*)&b1[kc+4];
        const __half2* phh = (const __half2*)&pv;
        const __half2* qhh = (const __half2*)&qv;
        float bl[8] = {bb0.x,bb0.y,bb0.z,bb0.w,bb1.x,bb1.y,bb1.z,bb1.w};
        uint32_t o[4];
#pragma unroll
        for(int w=0; w<4; w++){
            float2 pf = __half22float2(phh[w]);
            float2 qf = __half22float2(qhh[w]);
            o[w] = f2h2(eluf(pf.x+qf.x+bl[2*w]), eluf(pf.y+qf.y+bl[2*w+1]));
        }
        ra = make_uint4(o[0],o[1],o[2],o[3]);
    };
    auto storeA = [&](int st){
        *(uint4*)(esm + AOFF + st*8192 + aslot) = ra;
    };
    auto cpW2 = [&](int s, int st){
        int k0 = s << 5;
#pragma unroll
        for(int it=0; it<2; it++){
            int idx = tid + it*512;     // 0..1023
            int r = idx >> 2, c = (idx & 3)*8;
            cpa16(smbase + BOFF + st*16384 + swatom(r, idx&3),
                  &W2h[(size_t)r*256 + k0 + c]);
        }
        CP_COMMIT();
    };

    // ---- phase 1 mainloop ----
    buildA(0); storeA(0);
    cpW2(0, 0);

    for(int s=0; s<8; s++){
        if(s+1 < 8){
            cpW2(s+1, (s+1)&1);
            buildA((s+1)<<5);
        }
        if(s+1 < 8){ CP_WAIT(1); } else { CP_WAIT(0); }
        __syncthreads();

        uint32_t sAa = smbase + AOFF + (s&1)*8192;
        uint32_t sBa = smbase + BOFF + (s&1)*16384;
#pragma unroll
        for(int kh=0; kh<2; kh++){
            int ka = kh*2;
            uint32_t a[2][4];
#pragma unroll
            for(int mi=0; mi<2; mi++){
                uint32_t addr = sAa + abase[mi] + ((((amb[mi] + ka + aj) ^ asw[mi]))<<4);
                ldsm4(a[mi][0], a[mi][1], a[mi][2], a[mi][3], addr);
            }
#pragma unroll
            for(int p=0; p<4; p++){
                uint32_t b0,b1r,b2r,b3;
                uint32_t addr = sBa + bbase[p] + ((((bmb[p] + ka + bj) ^ bsw[p]))<<4);
                ldsm4(b0, b1r, b2r, b3, addr);
                mma16(acc[0][2*p  ], a[0], b0, b1r);
                mma16(acc[0][2*p+1], a[0], b2r, b3);
                mma16(acc[1][2*p  ], a[1], b0, b1r);
                mma16(acc[1][2*p+1], a[1], b2r, b3);
            }
        }
        __syncthreads();
        if(s+1 < 8) storeA((s+1)&1);
    }

    // ---- handoff: m2 = elu(acc + b2) into smem slices (overlay) ----
#pragma unroll
    for(int mi=0; mi<2; mi++){
#pragma unroll
        for(int rr=0; rr<2; rr++){
            int row = wm + mi*16 + qr + rr*8;
#pragma unroll
            for(int ni=0; ni<8; ni++){
                int col = wn + ni*8 + qc*2;
                float v0 = (rr==0 ? acc[mi][ni].x : acc[mi][ni].z) + __ldg(&b2[col]);
                float v1 = (rr==0 ? acc[mi][ni].y : acc[mi][ni].w) + __ldg(&b2[col+1]);
                v0 = eluf(v0); v1 = eluf(v1);
                int ksl = col >> 5, c = col & 31;
                uint32_t off = MOFF + (uint32_t)ksl*8192 + swatom(row, c>>3) + (c&7)*2;
                *(__half2*)(esm + off) = __floats2half2_rn(v0, v1);
            }
        }
    }
    __syncthreads();

    // ---- phase 2: z = m2 @ NW1^T (128x128x256) ----
    float4 acc2[2][4];
#pragma unroll
    for(int mi=0;mi<2;mi++)
#pragma unroll
        for(int ni=0;ni<4;ni++) acc2[mi][ni] = make_float4(0.f,0.f,0.f,0.f);

    auto cpN = [&](int s, int st){
        int k0 = s << 5;
        int idx = tid;                  // 0..511
        int n = idx >> 2, kc = (idx & 3)*8;
        cpa16(smbase + NOFF + st*8192 + swatom(n, idx&3),
              &NW1h[(size_t)n*256 + k0 + kc]);
        CP_COMMIT();
    };
    cpN(0, 0);

    for(int s2=0; s2<8; s2++){
        if(s2+1 < 8){ cpN(s2+1, (s2+1)&1); CP_WAIT(1); } else { CP_WAIT(0); }
        __syncthreads();

        uint32_t sAa = smbase + MOFF + s2*8192;
        uint32_t sBa = smbase + NOFF + (s2&1)*8192;
#pragma unroll
        for(int kh=0; kh<2; kh++){
            int ka = kh*2;
            uint32_t a[2][4];
#pragma unroll
            for(int mi=0; mi<2; mi++){
                uint32_t addr = sAa + abase[mi] + ((((amb[mi] + ka + aj) ^ asw[mi]))<<4);
                ldsm4(a[mi][0], a[mi][1], a[mi][2], a[mi][3], addr);
            }
#pragma unroll
            for(int p=0; p<2; p++){
                uint32_t b0,b1r,b2r,b3;
                uint32_t addr = sBa + cbase[p] + ((((cmb[p] + ka + bj) ^ csw[p]))<<4);
                ldsm4(b0, b1r, b2r, b3, addr);
                mma16(acc2[0][2*p  ], a[0], b0, b1r);
                mma16(acc2[0][2*p+1], a[0], b2r, b3);
                mma16(acc2[1][2*p  ], a[1], b0, b1r);
                mma16(acc2[1][2*p+1], a[1], b2r, b3);
            }
        }
        __syncthreads();
    }

    // ---- epilogue: scatter z (raw, pre-bias) into agg2 ----
#pragma unroll
    for(int mi=0; mi<2; mi++){
#pragma unroll
        for(int rr=0; rr<2; rr++){
            int row = m0 + wm + mi*16 + qr + rr*8;
            int e = row >> 6, s = row & 63;
            size_t crow = (size_t)(__ldg(&dstp[e])*64 + s)*128;
#pragma unroll
            for(int ni=0; ni<4; ni++){
                int col = wn2 + ni*8 + qc*2;
                float v0 = (rr==0 ? acc2[mi][ni].x : acc2[mi][ni].z);
                float v1 = (rr==0 ? acc2[mi][ni].y : acc2[mi][ni].w);
                redv2(&agg2[crow + col], v0, v1);
            }
        }
    }
}

// ================= tensor-core persistent LSTM =================
__global__ void __launch_bounds__(256,1)
k_lstm_mma(const __half* __restrict__ Whh, const __half* __restrict__ gates){
    __shared__ __align__(16) __half hA[16*136];
    __shared__ float G[8][512];
    const int tid = threadIdx.x, warp = tid>>5, lane = tid&31;
    const int nb = blockIdx.x*8;
    const int wn = warp*64;
    const uint32_t hAb = (uint32_t)__cvta_generic_to_shared(hA);

    float cst[4] = {0.f,0.f,0.f,0.f};
    for(int i=tid; i<16*136; i+=256) hA[i] = __float2half(0.f);

    uint32_t bf[8][8][2];
    {
        int bn = lane>>2, bk = (lane&3)*2;
#pragma unroll
        for(int nt=0; nt<8; nt++)
#pragma unroll
        for(int kt=0; kt<8; kt++){
            const __half* p = Whh + (size_t)(wn + nt*8 + bn)*128 + kt*16 + bk;
            bf[nt][kt][0] = *(const uint32_t*)p;
            bf[nt][kt][1] = *(const uint32_t*)(p + 8);
        }
    }
    __syncthreads();

    const int j = lane>>3, rl = lane&7;
    const int arow = (j&1)*8 + rl;
    const int cr = lane>>2, cc = (lane&3)*2;

    for(int t=0; t<64; t++){
        uint32_t a[8][4];
#pragma unroll
        for(int kt=0; kt<8; kt++){
            uint32_t addr = hAb + arow*272 + (uint32_t)((kt*2 + (j>>1))*16);
            ldsm4(a[kt][0], a[kt][1], a[kt][2], a[kt][3], addr);
        }
        float4 acc[8];
#pragma unroll
        for(int nt=0; nt<8; nt++) acc[nt] = make_float4(0.f,0.f,0.f,0.f);
#pragma unroll
        for(int kt=0; kt<8; kt++)
#pragma unroll
            for(int nt=0; nt<8; nt++)
                mma16(acc[nt], a[kt], bf[nt][kt][0], bf[nt][kt][1]);

#pragma unroll
        for(int nt=0; nt<8; nt++){
            int col = wn + nt*8 + cc;
            __half2 gv = *(const __half2*)&gates[((size_t)(nb+cr)*64 + t)*512 + col];
            float2 gf = __half22float2(gv);
            G[cr][col]   = acc[nt].x + gf.x;
            G[cr][col+1] = acc[nt].y + gf.y;
        }
        __syncthreads();

#pragma unroll
        for(int q=0; q<4; q++){
            int idx = q*256 + tid;
            int n = idx>>7, jj = idx&127;
            float ig=G[n][jj], fg=G[n][128+jj], gg=G[n][256+jj], og=G[n][384+jj];
            float cn = sigf(fg)*cst[q] + sigf(ig)*tanhfast(gg);
            cst[q] = cn;
            float h = sigf(og)*tanhfast(cn);
            hA[n*136 + jj] = __float2half(h);
            if(t==63) g_h[(size_t)(nb+n)*128 + jj] = h;
        }
        __syncthreads();
    }
}

// ---------------- output heads ----------------
__global__ void k_heads(const float* __restrict__ Wm, const float* __restrict__ bm,
                        const float* __restrict__ Wt, const float* __restrict__ bt,
                        const float* __restrict__ We, const float* __restrict__ be,
                        float* __restrict__ out){
    int n = blockIdx.x;
    int l = threadIdx.x;
    float sm=0.f, st=0.f, se=0.f;
    for(int jj=l;jj<128;jj+=32){
        float h = g_h[(size_t)n*128 + jj];
        sm += h*Wm[jj]; st += h*Wt[jj]; se += h*We[jj];
    }
#pragma unroll
    for(int o=16;o;o>>=1){
        sm += __shfl_down_sync(0xffffffffu, sm, o);
        st += __shfl_down_sync(0xffffffffu, st, o);
        se += __shfl_down_sync(0xffffffffu, se, o);
    }
    if(l==0){
        out[n]            = sm + bm[0];
        out[N_NODES + n]  = st + bt[0];
        out[2*N_NODES + n]= se + be[0];
    }
}

// ---------------- host launcher ----------------
extern "C" void kernel_launch(void* const* d_in, const int* in_sizes, int n_in,
                              void* d_out, int out_size)
{
    const int*   edge  = (const int*)  d_in[0];
    const float* itime = (const float*)d_in[1];
    const float* iev   = (const float*)d_in[2];
    const int*   ann   = (const int*)  d_in[3];
    const float* emb   = (const float*)d_in[4];
    const float* W_in  = (const float*)d_in[5];
    const float* b_in  = (const float*)d_in[6];
    const float* nW1   = (const float*)d_in[7];
    const float* nb1   = (const float*)d_in[8];
    const float* nW2   = (const float*)d_in[9];
    const float* nb2   = (const float*)d_in[10];
    const float* aW1   = (const float*)d_in[11];
    const float* ab1   = (const float*)d_in[12];
    const float* aW2   = (const float*)d_in[13];
    const float* ab2   = (const float*)d_in[14];
    const float* Wih   = (const float*)d_in[15];
    const float* Whh   = (const float*)d_in[16];
    const float* bih   = (const float*)d_in[17];
    const float* bhh   = (const float*)d_in[18];
    const float* Wm    = (const float*)d_in[19];
    const float* bm    = (const float*)d_in[20];
    const float* Wt    = (const float*)d_in[21];
    const float* bt    = (const float*)d_in[22];
    const float* We    = (const float*)d_in[23];
    const float* be    = (const float*)d_in[24];
    float* out = (float*)d_out;

    const int* src = edge;
    const int* dst = edge + NEDGE;

    __half *pxh, *pnfh, *ptmph, *pPQh, *pgatesh;
    __half *pWinh, *pW1ph, *pW2h, *pNW1h, *pNW2h, *pWihh, *pWhhh;
    float *pagg, *pinvdeg, *pbsum;
    cudaGetSymbolAddress((void**)&pxh,    g_xh);
    cudaGetSymbolAddress((void**)&pnfh,   g_nfh);
    cudaGetSymbolAddress((void**)&ptmph,  g_tmph);
    cudaGetSymbolAddress((void**)&pPQh,   g_PQh);
    cudaGetSymbolAddress((void**)&pgatesh,g_gatesh);
    cudaGetSymbolAddress((void**)&pWinh,  g_Winh);
    cudaGetSymbolAddress((void**)&pW1ph,  g_W1ph);
    cudaGetSymbolAddress((void**)&pW2h,   g_W2h);
    cudaGetSymbolAddress((void**)&pNW1h,  g_NW1h);
    cudaGetSymbolAddress((void**)&pNW2h,  g_NW2h);
    cudaGetSymbolAddress((void**)&pWihh,  g_Wihh);
    cudaGetSymbolAddress((void**)&pWhhh,  g_Whhh);
    cudaGetSymbolAddress((void**)&pagg,   g_agg);
    cudaGetSymbolAddress((void**)&pinvdeg,g_invdeg);
    cudaGetSymbolAddress((void**)&pbsum,  g_bsum);

    cudaFuncSetAttribute(k_edge_fused, cudaFuncAttributeMaxDynamicSharedMemorySize, 81920);

    // degrees + weight prep
    k_zero_deg<<<4,256>>>();
    k_deg<<<(NEDGE+255)/256,256>>>(dst);
    k_fin_deg<<<4,256>>>();
    k_prep_global<<<256,256>>>(W_in, Wih, Whh);
    k_bsum<<<2,256>>>(bih, bhh);

    // input embedding: x -> nf
    k_build_x2<<<NS*128/256,256>>>(itime, iev, ann, emb);
    k_gemm<0,true,true><<<dim3(NS/128,1),256>>>(
        pxh,256, pWinh,256, b_in, pnfh,128, 256);

    for(int l=0; l<2; l++){
        const float* W1 = aW1 + (size_t)l*256*256;
        const float* B1 = ab1 + (size_t)l*256;
        const float* W2 = aW2 + (size_t)l*256*256;
        const float* B2 = ab2 + (size_t)l*256;
        const float* NW1= nW1 + (size_t)l*128*256;
        const float* NB1= nb1 + (size_t)l*128;
        const float* NW2= nW2 + (size_t)l*128*128;
        const float* NB2= nb2 + (size_t)l*128;

        k_prep_layer<<<256,256>>>(W1, W2, NW1, NW2);

        // [P|Q] = nf @ W1p^T -> fp16 [NS,512]
        k_gemm<0,false,true><<<dim3(NS/128,4),256>>>(
            pnfh,128, pW1ph,128, nullptr, pPQh,512, 128);

        // zero agg2 (128-wide), fused edge+NW1 GEMM with red.v2 scatter
        cudaMemsetAsync(pagg, 0, (size_t)NS*128*sizeof(float));
        k_edge_fused<<<ES/128,512,81920>>>(pPQh, src, dst, B1, pW2h, B2, pNW1h, pagg);

        // node bias+elu, then NW2 GEMM
        k_node1<<<NS*64/256,256>>>(pagg, pinvdeg, NB1, ptmph);
        k_gemm<1,true,true><<<dim3(NS/128,1),256>>>(
            ptmph,128, pNW2h,128, NB2, pnfh,128, 128);
    }

    // LSTM: input gates for all timesteps, then tensor-core recurrence
    k_gemm<0,true,true><<<dim3(NS/128,4),256>>>(
        pnfh,128, pWihh,128, pbsum, pgatesh,512, 128);
    k_lstm_mma<<<128,256>>>(pWhhh, pgatesh);

    k_heads<<<N_NODES,32>>>(Wm,bm,Wt,bt,We,be,out);
}

// round 11
// speedup vs baseline: 5.5611x; 1.0035x over previous
#include <cuda_runtime.h>
#include <cuda_fp16.h>
#include <math.h>
#include <stdint.h>

#define N_NODES 1024
#define SEQ     64
#define NEDGE   4096
#define NS      (N_NODES*SEQ)   /* 65536  */
#define ES      (NEDGE*SEQ)     /* 262144 */

// ---------------- scratch (device globals) ----------------
__device__ __half g_xh[NS*256];
__device__ __half g_nfh[NS*128];
__device__ __half g_PQh[NS*512];
__device__ float  g_agg[NS*128];      // post-NW1 aggregate (128-wide)
__device__ __half g_gatesh[NS*512];
__device__ __half g_Winh[128*256];
__device__ __half g_W1ph[512*128];
__device__ __half g_W2h[256*256];
__device__ __half g_NW1h[128*256];
__device__ __half g_NW2h[128*128];
__device__ __half g_Wihh[512*128];
__device__ __half g_Whhh[512*128];
__device__ float  g_invdeg[N_NODES];
__device__ float  g_h[N_NODES*128];
__device__ float  g_bsum[512];

// ---------------- helpers ----------------
__device__ __forceinline__ float eluf(float v){ return v > 0.f ? v : (__expf(v) - 1.f); }
__device__ __forceinline__ float sigf(float v){ return 1.f/(1.f+__expf(-v)); }
__device__ __forceinline__ float tanhfast(float v){ return 1.f - 2.f/(__expf(2.f*v)+1.f); }
__device__ __forceinline__ uint32_t f2h2(float lo, float hi){
    __half2 h = __floats2half2_rn(lo, hi);
    return *(uint32_t*)&h;
}
__device__ __forceinline__ void mma16(float4 &d, const uint32_t a[4], uint32_t b0, uint32_t b1){
    asm volatile("mma.sync.aligned.m16n8k16.row.col.f32.f16.f16.f32 "
        "{%0,%1,%2,%3}, {%4,%5,%6,%7}, {%8,%9}, {%0,%1,%2,%3};\n"
        : "+f"(d.x), "+f"(d.y), "+f"(d.z), "+f"(d.w)
        : "r"(a[0]), "r"(a[1]), "r"(a[2]), "r"(a[3]), "r"(b0), "r"(b1));
}
__device__ __forceinline__ void ldsm4(uint32_t &r0, uint32_t &r1, uint32_t &r2, uint32_t &r3, uint32_t addr){
    asm volatile("ldmatrix.sync.aligned.m8n8.x4.shared.b16 {%0,%1,%2,%3}, [%4];"
        : "=r"(r0), "=r"(r1), "=r"(r2), "=r"(r3) : "r"(addr));
}
__device__ __forceinline__ void redv2(float* p, float v0, float v1){
    asm volatile("red.global.add.v2.f32 [%0], {%1, %2};" :: "l"(p), "f"(v0), "f"(v1) : "memory");
}
__device__ __forceinline__ void cpa16(uint32_t dst, const void* src){
    asm volatile("cp.async.cg.shared.global [%0], [%1], 16;" :: "r"(dst), "l"(src));
}
#define CP_COMMIT() asm volatile("cp.async.commit_group;" ::: "memory")
#define CP_WAIT0()  asm volatile("cp.async.wait_group 0;" ::: "memory")
// swizzled 16B-atom byte offset, 2 rows per 128B line, 4 k-atoms per row
__device__ __forceinline__ int swatom(int r, int katom){
    return (r>>1)*128 + ((((r&1)*4 + katom) ^ ((r>>1)&7))<<4);
}

// ---------------- degree / misc / weight prep ----------------
__global__ void k_zero_deg(){
    int i = blockIdx.x*blockDim.x + threadIdx.x;
    if(i < N_NODES) g_invdeg[i] = 0.f;
}
__global__ void k_deg(const int* __restrict__ dst){
    int e = blockIdx.x*blockDim.x + threadIdx.x;
    if(e < NEDGE) atomicAdd(&g_invdeg[dst[e]], 1.f);
}
__global__ void k_fin_deg(){
    int i = blockIdx.x*blockDim.x + threadIdx.x;
    if(i < N_NODES){ float d = g_invdeg[i]; g_invdeg[i] = 1.f/fmaxf(d,1.f); }
}
__global__ void k_bsum(const float* __restrict__ bih, const float* __restrict__ bhh){
    int i = blockIdx.x*blockDim.x + threadIdx.x;
    if(i < 512) g_bsum[i] = bih[i] + bhh[i];
}
__global__ void k_prep_global(const float* __restrict__ W_in, const float* __restrict__ Wih,
                              const float* __restrict__ Whh){
    int i = blockIdx.x*256 + threadIdx.x;
    if(i < 128*256) g_Winh[i] = __float2half(W_in[i]);
    if(i < 512*128){ g_Wihh[i] = __float2half(Wih[i]); g_Whhh[i] = __float2half(Whh[i]); }
}
__global__ void k_prep_layer(const float* __restrict__ W1, const float* __restrict__ W2,
                             const float* __restrict__ NW1, const float* __restrict__ NW2){
    int i = blockIdx.x*256 + threadIdx.x;
    {
        int o = i >> 8, k = i & 255;
        __half v = __float2half(W1[i]);
        if(k < 128) g_W1ph[o*128 + k] = v;
        else        g_W1ph[(256+o)*128 + (k-128)] = v;
        g_W2h[i] = __float2half(W2[i]);
    }
    if(i < 128*256) g_NW1h[i] = __float2half(NW1[i]);
    if(i < 128*128) g_NW2h[i] = __float2half(NW2[i]);
}

// ---------------- build x, vectorized half2 ----------------
__global__ void k_build_x2(const float* __restrict__ itime, const float* __restrict__ iev,
                           const int* __restrict__ ann, const float* __restrict__ emb){
    int idx = blockIdx.x*blockDim.x + threadIdx.x;   // over NS*128 half2
    int row = idx >> 7, cp = idx & 127;
    float e = __ldg(&iev[row]);
    __half2 o;
    if(cp < 63){
        const float* ep = emb + (size_t)__ldg(&ann[row])*127 + cp*2;
        o = __floats2half2_rn(__ldg(ep), __ldg(ep+1));
    } else if(cp == 63){
        o = __floats2half2_rn(__ldg(&emb[(size_t)__ldg(&ann[row])*127 + 126]), e);
    } else {
        int j = cp - 64;
        float pos = exp2f(13.287712379549449f * (float)j * (1.0f/64.0f));
        float r = __ldg(&itime[row]) / pos;
        float sv = __sinf(r), cv = __cosf(r);
        if(e == 0.f){ sv = 0.f; cv = 0.f; }
        o = __floats2half2_rn(sv, cv);
    }
    *(__half2*)&g_xh[(size_t)idx*2] = o;
}

// ================= generic FP16 tensor-core GEMM (cp.async, 1 barrier/stage) =================
// NODEA: A built on the fly from fp32 agg: elu(agg*invdeg + nb1) -> fp16.
template<int ACT, bool BIAS, bool OUTH, bool NODEA>
__global__ void __launch_bounds__(256)
k_gemm(const __half* __restrict__ A, int lda,
       const float* __restrict__ aggf, const float* __restrict__ invdeg,
       const float* __restrict__ nb1,
       const __half* __restrict__ B, int ldb,
       const float* __restrict__ bias,
       void* __restrict__ Cp, int ldc, int K)
{
    __shared__ __align__(16) char sm[2*16384];
    const int m0 = blockIdx.x*128, n0 = blockIdx.y*128;
    const int tid  = threadIdx.x;
    const int warp = tid >> 5, lane = tid & 31;
    const int wm = (warp >> 1)*32;
    const int wn = (warp &  1)*64;
    const int qr = lane >> 2, qc = lane & 3;
    const uint32_t smbase = (uint32_t)__cvta_generic_to_shared(sm);

    const int j  = lane >> 3, rl = lane & 7;
    const int aj = j >> 1;
    const int bj = j & 1;
    int abase[2], asw[2], amb[2];
#pragma unroll
    for(int mi=0; mi<2; mi++){
        int m = wm + mi*16 + (j&1)*8 + rl;
        abase[mi] = (m>>1)*128; asw[mi] = (m>>1)&7; amb[mi] = (m&1)*4;
    }
    int bbase[4], bsw[4], bmb[4];
#pragma unroll
    for(int p=0; p<4; p++){
        int n = wn + p*16 + (j>>1)*8 + rl;
        bbase[p] = (n>>1)*128; bsw[p] = (n>>1)&7; bmb[p] = (n&1)*4;
    }

    float4 acc[2][8];
#pragma unroll
    for(int mi=0;mi<2;mi++)
#pragma unroll
        for(int ni=0;ni<8;ni++) acc[mi][ni] = make_float4(0.f,0.f,0.f,0.f);

    // per-thread load slots: 2 uint4 for A, 2 for B per 32-K stage
    const int lr = tid >> 2;                 // 0..63 base rows (2 slots: lr, lr+64)
    const int lc = (tid & 3) * 8;
    const int lk = tid & 3;

    uint4 raN[2];   // NODEA built A regs

    auto buildA = [&](int k0){
#pragma unroll
        for(int it=0; it<2; it++){
            int r = lr + it*64;
            const float* p = &aggf[(size_t)(m0+r)*128 + k0 + lc];
            float sc = __ldg(&invdeg[(m0+r) >> 6]);
            float4 v0 = *(const float4*)p;
            float4 v1 = *(const float4*)(p+4);
            float4 b0 = *(const float4*)&nb1[k0+lc];
            float4 b1v = *(const float4*)&nb1[k0+lc+4];
            raN[it] = make_uint4(
                f2h2(eluf(v0.x*sc+b0.x),  eluf(v0.y*sc+b0.y)),
                f2h2(eluf(v0.z*sc+b0.z),  eluf(v0.w*sc+b0.w)),
                f2h2(eluf(v1.x*sc+b1v.x), eluf(v1.y*sc+b1v.y)),
                f2h2(eluf(v1.z*sc+b1v.z), eluf(v1.w*sc+b1v.w)));
        }
    };
    auto storeA = [&](int st){
#pragma unroll
        for(int it=0; it<2; it++)
            *(uint4*)(sm + st*16384 + swatom(lr + it*64, lk)) = raN[it];
    };
    auto cpA = [&](int k0, int st){
#pragma unroll
        for(int it=0; it<2; it++){
            int r = lr + it*64;
            cpa16(smbase + st*16384 + swatom(r, lk), &A[(size_t)(m0+r)*lda + k0 + lc]);
        }
    };
    auto cpB = [&](int k0, int st){
#pragma unroll
        for(int it=0; it<2; it++){
            int r = lr + it*64;
            cpa16(smbase + st*16384 + 8192 + swatom(r, lk), &B[(size_t)(n0+r)*ldb + k0 + lc]);
        }
    };

    const int S = K >> 5;
    if(NODEA){ buildA(0); storeA(0); } else { cpA(0,0); }
    cpB(0,0);
    CP_COMMIT();

    for(int s=0; s<S; s++){
        bool more = (s+1 < S);
        if(NODEA && more) buildA((s+1)<<5);
        CP_WAIT0();
        __syncthreads();
        if(more){
            if(NODEA) storeA((s+1)&1); else cpA((s+1)<<5, (s+1)&1);
            cpB((s+1)<<5, (s+1)&1);
            CP_COMMIT();
        }

        uint32_t sAa = smbase + (s&1)*16384;
        uint32_t sBa = sAa + 8192;
#pragma unroll
        for(int kh=0; kh<2; kh++){
            int ka = kh*2;
            uint32_t a[2][4];
#pragma unroll
            for(int mi=0; mi<2; mi++){
                uint32_t addr = sAa + abase[mi] + ((((amb[mi] + ka + aj) ^ asw[mi]))<<4);
                ldsm4(a[mi][0], a[mi][1], a[mi][2], a[mi][3], addr);
            }
#pragma unroll
            for(int p=0; p<4; p++){
                uint32_t b0,b1r,b2,b3;
                uint32_t addr = sBa + bbase[p] + ((((bmb[p] + ka + bj) ^ bsw[p]))<<4);
                ldsm4(b0, b1r, b2, b3, addr);
                mma16(acc[0][2*p  ], a[0], b0, b1r);
                mma16(acc[0][2*p+1], a[0], b2, b3);
                mma16(acc[1][2*p  ], a[1], b0, b1r);
                mma16(acc[1][2*p+1], a[1], b2, b3);
            }
        }
    }

#pragma unroll
    for(int mi=0; mi<2; mi++){
#pragma unroll
        for(int rr=0; rr<2; rr++){
            int row = m0 + wm + mi*16 + qr + rr*8;
            size_t crow = (size_t)row*ldc;
#pragma unroll
            for(int ni=0; ni<8; ni++){
                int col = n0 + wn + ni*8 + qc*2;
                float v0 = (rr==0 ? acc[mi][ni].x : acc[mi][ni].z);
                float v1 = (rr==0 ? acc[mi][ni].y : acc[mi][ni].w);
                if(BIAS){ v0 += bias[col]; v1 += bias[col+1]; }
                if(ACT==1){ v0 = eluf(v0); v1 = eluf(v1); }
                if(OUTH){
                    *(__half2*)&(((__half*)Cp)[crow + col]) = __floats2half2_rn(v0, v1);
                } else {
                    *(float2*)&(((float*)Cp)[crow + col]) = make_float2(v0, v1);
                }
            }
        }
    }
}

// ================= fused edge GEMM + NW1 GEMM, 512 threads =================
// Phase 1: m2pre = (elu(P[src]+Q[dst]+b1)) @ W2^T   [128 x 256]
// Phase 2: z = elu(m2pre + b2) @ NW1^T              [128 x 128]
// Epilogue: red.v2 scatter z into agg2[dst*64+s][col].
// 16 warps; 1 barrier per K-stage; cp.async for W2/NW1.
__global__ void __launch_bounds__(512,1)
k_edge_fused(const __half* __restrict__ PQ,
             const int* __restrict__ srcp, const int* __restrict__ dstp,
             const float* __restrict__ b1,
             const __half* __restrict__ W2h, const float* __restrict__ b2,
             const __half* __restrict__ NW1h,
             float* __restrict__ agg2)
{
    extern __shared__ __align__(16) char esm[];
    const int m0 = blockIdx.x*128;
    const int tid  = threadIdx.x;
    const int warp = tid >> 5, lane = tid & 31;
    const int wm  = (warp >> 2)*32;     // 0,32,64,96
    const int wn  = (warp &  3)*64;     // phase 1: 0,64,128,192
    const int wn2 = (warp &  3)*32;     // phase 2: 0,32,64,96
    const int qr = lane >> 2, qc = lane & 3;
    const uint32_t smbase = (uint32_t)__cvta_generic_to_shared(esm);
    const uint32_t AOFF = 0, BOFF = 16384, MOFF = 0, NOFF = 65536;

    const int j  = lane >> 3, rl = lane & 7;
    const int aj = j >> 1;
    const int bj = j & 1;
    int abase[2], asw[2], amb[2];
#pragma unroll
    for(int mi=0; mi<2; mi++){
        int m = wm + mi*16 + (j&1)*8 + rl;
        abase[mi] = (m>>1)*128; asw[mi] = (m>>1)&7; amb[mi] = (m&1)*4;
    }
    int bbase[4], bsw[4], bmb[4];           // phase 1 B groups (64 cols)
#pragma unroll
    for(int p=0; p<4; p++){
        int n = wn + p*16 + (j>>1)*8 + rl;
        bbase[p] = (n>>1)*128; bsw[p] = (n>>1)&7; bmb[p] = (n&1)*4;
    }
    int cbase[2], csw[2], cmb[2];           // phase 2 B groups (32 cols)
#pragma unroll
    for(int p=0; p<2; p++){
        int n = wn2 + p*16 + (j>>1)*8 + rl;
        cbase[p] = (n>>1)*128; csw[p] = (n>>1)&7; cmb[p] = (n&1)*4;
    }

    // A-build indexing: one uint4 slot per thread
    const int ar = tid >> 2;            // 0..127
    const int ac = (tid & 3) * 8;       // 0,8,16,24
    const __half *ap, *aq;
    {
        int grow = m0 + ar;
        int e = grow >> 6, srow = grow & 63;
        ap = PQ + ((size_t)__ldg(&srcp[e])*64 + srow)*512;
        aq = PQ + ((size_t)__ldg(&dstp[e])*64 + srow)*512 + 256;
    }
    const uint32_t aslot = (uint32_t)(swatom(ar, (tid&3)));

    float4 acc[2][8];
#pragma unroll
    for(int mi=0;mi<2;mi++)
#pragma unroll
        for(int ni=0;ni<8;ni++) acc[mi][ni] = make_float4(0.f,0.f,0.f,0.f);

    uint4 ra;

    auto buildA = [&](int k0){
        int kc = k0 + ac;
        uint4 pv = *(const uint4*)(ap + kc);
        uint4 qv = *(const uint4*)(aq + kc);
        float4 bb0 = *(const float4*)&b1[kc];
        float4 bb1 = *(const float4*)&b1[kc+4];
        const __half2* phh = (const __half2*)&pv;
        const __half2* qhh = (const __half2*)&qv;
        float bl[8] = {bb0.x,bb0.y,bb0.z,bb0.w,bb1.x,bb1.y,bb1.z,bb1.w};
        uint32_t o[4];
#pragma unroll
        for(int w=0; w<4; w++){
            float2 pf = __half22float2(phh[w]);
            float2 qf = __half22float2(qhh[w]);
            o[w] = f2h2(eluf(pf.x+qf.x+bl[2*w]), eluf(pf.y+qf.y+bl[2*w+1]));
        }
        ra = make_uint4(o[0],o[1],o[2],o[3]);
    };
    auto storeA = [&](int st){
        *(uint4*)(esm + AOFF + st*8192 + aslot) = ra;
    };
    auto cpW2 = [&](int s, int st){
        int k0 = s << 5;
#pragma unroll
        for(int it=0; it<2; it++){
            int idx = tid + it*512;     // 0..1023
            int r = idx >> 2, c = (idx & 3)*8;
            cpa16(smbase + BOFF + st*16384 + swatom(r, idx&3),
                  &W2h[(size_t)r*256 + k0 + c]);
        }
    };

    // ---- phase 1 mainloop (1 barrier/stage) ----
    buildA(0); storeA(0);
    cpW2(0, 0);
    CP_COMMIT();

    for(int s=0; s<8; s++){
        bool more = (s+1 < 8);
        if(more) buildA((s+1)<<5);
        CP_WAIT0();
        __syncthreads();
        if(more){
            storeA((s+1)&1);
            cpW2(s+1, (s+1)&1);
            CP_COMMIT();
        }

        uint32_t sAa = smbase + AOFF + (s&1)*8192;
        uint32_t sBa = smbase + BOFF + (s&1)*16384;
#pragma unroll
        for(int kh=0; kh<2; kh++){
            int ka = kh*2;
            uint32_t a[2][4];
#pragma unroll
            for(int mi=0; mi<2; mi++){
                uint32_t addr = sAa + abase[mi] + ((((amb[mi] + ka + aj) ^ asw[mi]))<<4);
                ldsm4(a[mi][0], a[mi][1], a[mi][2], a[mi][3], addr);
            }
#pragma unroll
            for(int p=0; p<4; p++){
                uint32_t b0,b1r,b2r,b3;
                uint32_t addr = sBa + bbase[p] + ((((bmb[p] + ka + bj) ^ bsw[p]))<<4);
                ldsm4(b0, b1r, b2r, b3, addr);
                mma16(acc[0][2*p  ], a[0], b0, b1r);
                mma16(acc[0][2*p+1], a[0], b2r, b3);
                mma16(acc[1][2*p  ], a[1], b0, b1r);
                mma16(acc[1][2*p+1], a[1], b2r, b3);
            }
        }
    }
    __syncthreads();   // all phase-1 smem reads done before overlay

    // ---- stream first NW1 tile while writing handoff ----
    {
        int idx = tid;                  // 0..511
        int n = idx >> 2, kc = (idx & 3)*8;
        cpa16(smbase + NOFF + swatom(n, idx&3), &NW1h[(size_t)n*256 + kc]);
        CP_COMMIT();
    }

    // ---- handoff: m2 = elu(acc + b2) into smem slices (overlay) ----
#pragma unroll
    for(int mi=0; mi<2; mi++){
#pragma unroll
        for(int rr=0; rr<2; rr++){
            int row = wm + mi*16 + qr + rr*8;
#pragma unroll
            for(int ni=0; ni<8; ni++){
                int col = wn + ni*8 + qc*2;
                float v0 = (rr==0 ? acc[mi][ni].x : acc[mi][ni].z) + __ldg(&b2[col]);
                float v1 = (rr==0 ? acc[mi][ni].y : acc[mi][ni].w) + __ldg(&b2[col+1]);
                v0 = eluf(v0); v1 = eluf(v1);
                int ksl = col >> 5, c = col & 31;
                uint32_t off = MOFF + (uint32_t)ksl*8192 + swatom(row, c>>3) + (c&7)*2;
                *(__half2*)(esm + off) = __floats2half2_rn(v0, v1);
            }
        }
    }

    // ---- phase 2: z = m2 @ NW1^T (128x128x256), 1 barrier/stage ----
    float4 acc2[2][4];
#pragma unroll
    for(int mi=0;mi<2;mi++)
#pragma unroll
        for(int ni=0;ni<4;ni++) acc2[mi][ni] = make_float4(0.f,0.f,0.f,0.f);

    auto cpN = [&](int s, int st){
        int k0 = s << 5;
        int idx = tid;
        int n = idx >> 2, kc = (idx & 3)*8;
        cpa16(smbase + NOFF + st*8192 + swatom(n, idx&3),
              &NW1h[(size_t)n*256 + k0 + kc]);
    };

    for(int s2=0; s2<8; s2++){
        bool more = (s2+1 < 8);
        CP_WAIT0();
        __syncthreads();
        if(more){ cpN(s2+1, (s2+1)&1); CP_COMMIT(); }

        uint32_t sAa = smbase + MOFF + s2*8192;
        uint32_t sBa = smbase + NOFF + (s2&1)*8192;
#pragma unroll
        for(int kh=0; kh<2; kh++){
            int ka = kh*2;
            uint32_t a[2][4];
#pragma unroll
            for(int mi=0; mi<2; mi++){
                uint32_t addr = sAa + abase[mi] + ((((amb[mi] + ka + aj) ^ asw[mi]))<<4);
                ldsm4(a[mi][0], a[mi][1], a[mi][2], a[mi][3], addr);
            }
#pragma unroll
            for(int p=0; p<2; p++){
                uint32_t b0,b1r,b2r,b3;
                uint32_t addr = sBa + cbase[p] + ((((cmb[p] + ka + bj) ^ csw[p]))<<4);
                ldsm4(b0, b1r, b2r, b3, addr);
                mma16(acc2[0][2*p  ], a[0], b0, b1r);
                mma16(acc2[0][2*p+1], a[0], b2r, b3);
                mma16(acc2[1][2*p  ], a[1], b0, b1r);
                mma16(acc2[1][2*p+1], a[1], b2r, b3);
            }
        }
    }

    // ---- epilogue: scatter z (raw, pre-bias) into agg2 ----
#pragma unroll
    for(int mi=0; mi<2; mi++){
#pragma unroll
        for(int rr=0; rr<2; rr++){
            int row = m0 + wm + mi*16 + qr + rr*8;
            int e = row >> 6, s = row & 63;
            size_t crow = (size_t)(__ldg(&dstp[e])*64 + s)*128;
#pragma unroll
            for(int ni=0; ni<4; ni++){
                int col = wn2 + ni*8 + qc*2;
                float v0 = (rr==0 ? acc2[mi][ni].x : acc2[mi][ni].z);
                float v1 = (rr==0 ? acc2[mi][ni].y : acc2[mi][ni].w);
                redv2(&agg2[crow + col], v0, v1);
            }
        }
    }
}

// ================= tensor-core persistent LSTM =================
__global__ void __launch_bounds__(256,1)
k_lstm_mma(const __half* __restrict__ Whh, const __half* __restrict__ gates){
    __shared__ __align__(16) __half hA[16*136];
    __shared__ float G[8][512];
    const int tid = threadIdx.x, warp = tid>>5, lane = tid&31;
    const int nb = blockIdx.x*8;
    const int wn = warp*64;
    const uint32_t hAb = (uint32_t)__cvta_generic_to_shared(hA);

    float cst[4] = {0.f,0.f,0.f,0.f};
    for(int i=tid; i<16*136; i+=256) hA[i] = __float2half(0.f);

    uint32_t bf[8][8][2];
    {
        int bn = lane>>2, bk = (lane&3)*2;
#pragma unroll
        for(int nt=0; nt<8; nt++)
#pragma unroll
        for(int kt=0; kt<8; kt++){
            const __half* p = Whh + (size_t)(wn + nt*8 + bn)*128 + kt*16 + bk;
            bf[nt][kt][0] = *(const uint32_t*)p;
            bf[nt][kt][1] = *(const uint32_t*)(p + 8);
        }
    }
    __syncthreads();

    const int j = lane>>3, rl = lane&7;
    const int arow = (j&1)*8 + rl;
    const int cr = lane>>2, cc = (lane&3)*2;

    for(int t=0; t<64; t++){
        uint32_t a[8][4];
#pragma unroll
        for(int kt=0; kt<8; kt++){
            uint32_t addr = hAb + arow*272 + (uint32_t)((kt*2 + (j>>1))*16);
            ldsm4(a[kt][0], a[kt][1], a[kt][2], a[kt][3], addr);
        }
        float4 acc[8];
#pragma unroll
        for(int nt=0; nt<8; nt++) acc[nt] = make_float4(0.f,0.f,0.f,0.f);
#pragma unroll
        for(int kt=0; kt<8; kt++)
#pragma unroll
            for(int nt=0; nt<8; nt++)
                mma16(acc[nt], a[kt], bf[nt][kt][0], bf[nt][kt][1]);

#pragma unroll
        for(int nt=0; nt<8; nt++){
            int col = wn + nt*8 + cc;
            __half2 gv = *(const __half2*)&gates[((size_t)(nb+cr)*64 + t)*512 + col];
            float2 gf = __half22float2(gv);
            G[cr][col]   = acc[nt].x + gf.x;
            G[cr][col+1] = acc[nt].y + gf.y;
        }
        __syncthreads();

#pragma unroll
        for(int q=0; q<4; q++){
            int idx = q*256 + tid;
            int n = idx>>7, jj = idx&127;
            float ig=G[n][jj], fg=G[n][128+jj], gg=G[n][256+jj], og=G[n][384+jj];
            float cn = sigf(fg)*cst[q] + sigf(ig)*tanhfast(gg);
            cst[q] = cn;
            float h = sigf(og)*tanhfast(cn);
            hA[n*136 + jj] = __float2half(h);
            if(t==63) g_h[(size_t)(nb+n)*128 + jj] = h;
        }
        __syncthreads();
    }
}

// ---------------- output heads ----------------
__global__ void k_heads(const float* __restrict__ Wm, const float* __restrict__ bm,
                        const float* __restrict__ Wt, const float* __restrict__ bt,
                        const float* __restrict__ We, const float* __restrict__ be,
                        float* __restrict__ out){
    int n = blockIdx.x;
    int l = threadIdx.x;
    float sm=0.f, st=0.f, se=0.f;
    for(int jj=l;jj<128;jj+=32){
        float h = g_h[(size_t)n*128 + jj];
        sm += h*Wm[jj]; st += h*Wt[jj]; se += h*We[jj];
    }
#pragma unroll
    for(int o=16;o;o>>=1){
        sm += __shfl_down_sync(0xffffffffu, sm, o);
        st += __shfl_down_sync(0xffffffffu, st, o);
        se += __shfl_down_sync(0xffffffffu, se, o);
    }
    if(l==0){
        out[n]            = sm + bm[0];
        out[N_NODES + n]  = st + bt[0];
        out[2*N_NODES + n]= se + be[0];
    }
}

// ---------------- host launcher ----------------
extern "C" void kernel_launch(void* const* d_in, const int* in_sizes, int n_in,
                              void* d_out, int out_size)
{
    const int*   edge  = (const int*)  d_in[0];
    const float* itime = (const float*)d_in[1];
    const float* iev   = (const float*)d_in[2];
    const int*   ann   = (const int*)  d_in[3];
    const float* emb   = (const float*)d_in[4];
    const float* W_in  = (const float*)d_in[5];
    const float* b_in  = (const float*)d_in[6];
    const float* nW1   = (const float*)d_in[7];
    const float* nb1   = (const float*)d_in[8];
    const float* nW2   = (const float*)d_in[9];
    const float* nb2   = (const float*)d_in[10];
    const float* aW1   = (const float*)d_in[11];
    const float* ab1   = (const float*)d_in[12];
    const float* aW2   = (const float*)d_in[13];
    const float* ab2   = (const float*)d_in[14];
    const float* Wih   = (const float*)d_in[15];
    const float* Whh   = (const float*)d_in[16];
    const float* bih   = (const float*)d_in[17];
    const float* bhh   = (const float*)d_in[18];
    const float* Wm    = (const float*)d_in[19];
    const float* bm    = (const float*)d_in[20];
    const float* Wt    = (const float*)d_in[21];
    const float* bt    = (const float*)d_in[22];
    const float* We    = (const float*)d_in[23];
    const float* be    = (const float*)d_in[24];
    float* out = (float*)d_out;

    const int* src = edge;
    const int* dst = edge + NEDGE;

    __half *pxh, *pnfh, *pPQh, *pgatesh;
    __half *pWinh, *pW1ph, *pW2h, *pNW1h, *pNW2h, *pWihh, *pWhhh;
    float *pagg, *pinvdeg, *pbsum;
    cudaGetSymbolAddress((void**)&pxh,    g_xh);
    cudaGetSymbolAddress((void**)&pnfh,   g_nfh);
    cudaGetSymbolAddress((void**)&pPQh,   g_PQh);
    cudaGetSymbolAddress((void**)&pgatesh,g_gatesh);
    cudaGetSymbolAddress((void**)&pWinh,  g_Winh);
    cudaGetSymbolAddress((void**)&pW1ph,  g_W1ph);
    cudaGetSymbolAddress((void**)&pW2h,   g_W2h);
    cudaGetSymbolAddress((void**)&pNW1h,  g_NW1h);
    cudaGetSymbolAddress((void**)&pNW2h,  g_NW2h);
    cudaGetSymbolAddress((void**)&pWihh,  g_Wihh);
    cudaGetSymbolAddress((void**)&pWhhh,  g_Whhh);
    cudaGetSymbolAddress((void**)&pagg,   g_agg);
    cudaGetSymbolAddress((void**)&pinvdeg,g_invdeg);
    cudaGetSymbolAddress((void**)&pbsum,  g_bsum);

    cudaFuncSetAttribute(k_edge_fused, cudaFuncAttributeMaxDynamicSharedMemorySize, 81920);

    // degrees + weight prep
    k_zero_deg<<<4,256>>>();
    k_deg<<<(NEDGE+255)/256,256>>>(dst);
    k_fin_deg<<<4,256>>>();
    k_prep_global<<<256,256>>>(W_in, Wih, Whh);
    k_bsum<<<2,256>>>(bih, bhh);

    // input embedding: x -> nf
    k_build_x2<<<NS*128/256,256>>>(itime, iev, ann, emb);
    k_gemm<0,true,true,false><<<dim3(NS/128,1),256>>>(
        pxh,256, nullptr,nullptr,nullptr, pWinh,256, b_in, pnfh,128, 256);

    for(int l=0; l<2; l++){
        const float* W1 = aW1 + (size_t)l*256*256;
        const float* B1 = ab1 + (size_t)l*256;
        const float* W2 = aW2 + (size_t)l*256*256;
        const float* B2 = ab2 + (size_t)l*256;
        const float* NW1= nW1 + (size_t)l*128*256;
        const float* NB1= nb1 + (size_t)l*128;
        const float* NW2= nW2 + (size_t)l*128*128;
        const float* NB2= nb2 + (size_t)l*128;

        k_prep_layer<<<256,256>>>(W1, W2, NW1, NW2);

        // [P|Q] = nf @ W1p^T -> fp16 [NS,512]
        k_gemm<0,false,true,false><<<dim3(NS/128,4),256>>>(
            pnfh,128, nullptr,nullptr,nullptr, pW1ph,128, nullptr, pPQh,512, 128);

        // zero agg2 (128-wide), fused edge+NW1 GEMM with red.v2 scatter
        cudaMemsetAsync(pagg, 0, (size_t)NS*128*sizeof(float));
        k_edge_fused<<<ES/128,512,81920>>>(pPQh, src, dst, B1, pW2h, B2, pNW1h, pagg);

        // NW2 GEMM with fused node1 (A = elu(agg*invdeg + NB1) built on the fly)
        k_gemm<1,true,true,true><<<dim3(NS/128,1),256>>>(
            nullptr,128, pagg, pinvdeg, NB1, pNW2h,128, NB2, pnfh,128, 128);
    }

    // LSTM: input gates for all timesteps, then tensor-core recurrence
    k_gemm<0,true,true,false><<<dim3(NS/128,4),256>>>(
        pnfh,128, nullptr,nullptr,nullptr, pWihh,128, pbsum, pgatesh,512, 128);
    k_lstm_mma<<<128,256>>>(pWhhh, pgatesh);

    k_heads<<<N_NODES,32>>>(Wm,bm,Wt,bt,We,be,out);
}

// round 12
// speedup vs baseline: 5.9937x; 1.0778x over previous
#include <cuda_runtime.h>
#include <cuda_fp16.h>
#include <math.h>
#include <stdint.h>

#define N_NODES 1024
#define SEQ     64
#define NEDGE   4096
#define NS      (N_NODES*SEQ)   /* 65536  */
#define ES      (NEDGE*SEQ)     /* 262144 */

// ---------------- scratch (device globals) ----------------
__device__ __half g_xh[NS*256];
__device__ __half g_nfh[NS*128];
__device__ __half g_PQh[NS*512];
__device__ float  g_agg[NS*128];
__device__ __half g_gatesh[NS*512];
__device__ __half g_Winh[128*256];
__device__ __half g_W1ph[2*512*128];
__device__ __half g_W2h[2*256*256];
__device__ __half g_NW1h[2*128*256];
__device__ __half g_NW2h[2*128*128];
__device__ __half g_Wihh[512*128];
__device__ __half g_Whhh[512*128];
__device__ float  g_invdeg[N_NODES];
__device__ float  g_h[N_NODES*128];
__device__ float  g_bsum[512];

// ---------------- helpers ----------------
__device__ __forceinline__ float eluf(float v){ return v > 0.f ? v : (__expf(v) - 1.f); }
__device__ __forceinline__ float sigf(float v){ return 1.f/(1.f+__expf(-v)); }
__device__ __forceinline__ float tanhfast(float v){ return 1.f - 2.f/(__expf(2.f*v)+1.f); }
__device__ __forceinline__ uint32_t f2h2(float lo, float hi){
    __half2 h = __floats2half2_rn(lo, hi);
    return *(uint32_t*)&h;
}
__device__ __forceinline__ void mma16(float4 &d, const uint32_t a[4], uint32_t b0, uint32_t b1){
    asm volatile("mma.sync.aligned.m16n8k16.row.col.f32.f16.f16.f32 "
        "{%0,%1,%2,%3}, {%4,%5,%6,%7}, {%8,%9}, {%0,%1,%2,%3};\n"
        : "+f"(d.x), "+f"(d.y), "+f"(d.z), "+f"(d.w)
        : "r"(a[0]), "r"(a[1]), "r"(a[2]), "r"(a[3]), "r"(b0), "r"(b1));
}
__device__ __forceinline__ void ldsm4(uint32_t &r0, uint32_t &r1, uint32_t &r2, uint32_t &r3, uint32_t addr){
    asm volatile("ldmatrix.sync.aligned.m8n8.x4.shared.b16 {%0,%1,%2,%3}, [%4];"
        : "=r"(r0), "=r"(r1), "=r"(r2), "=r"(r3) : "r"(addr));
}
__device__ __forceinline__ void redv2(float* p, float v0, float v1){
    asm volatile("red.global.add.v2.f32 [%0], {%1, %2};" :: "l"(p), "f"(v0), "f"(v1) : "memory");
}
__device__ __forceinline__ void cpa16(uint32_t dst, const void* src){
    asm volatile("cp.async.cg.shared.global [%0], [%1], 16;" :: "r"(dst), "l"(src));
}
#define CP_COMMIT() asm volatile("cp.async.commit_group;" ::: "memory")
#define CP_WAIT0()  asm volatile("cp.async.wait_group 0;" ::: "memory")
// swizzled 16B-atom byte offset, 2 rows per 128B line, 4 k-atoms per row
__device__ __forceinline__ int swatom(int r, int katom){
    return (r>>1)*128 + ((((r&1)*4 + katom) ^ ((r>>1)&7))<<4);
}

// ---------------- degree ----------------
__global__ void k_zero_deg(){
    int i = blockIdx.x*blockDim.x + threadIdx.x;
    if(i < N_NODES) g_invdeg[i] = 0.f;
}
__global__ void k_deg(const int* __restrict__ dst){
    int e = blockIdx.x*blockDim.x + threadIdx.x;
    if(e < NEDGE) atomicAdd(&g_invdeg[dst[e]], 1.f);
}
__global__ void k_fin_deg(){
    int i = blockIdx.x*blockDim.x + threadIdx.x;
    if(i < N_NODES){ float d = g_invdeg[i]; g_invdeg[i] = 1.f/fmaxf(d,1.f); }
}

// ---------------- merged weight prep (both layers, once) ----------------
__global__ void k_prep_all(const float* __restrict__ W_in,
                           const float* __restrict__ Wih, const float* __restrict__ Whh,
                           const float* __restrict__ bih, const float* __restrict__ bhh,
                           const float* __restrict__ aW1, const float* __restrict__ aW2,
                           const float* __restrict__ nW1, const float* __restrict__ nW2){
    int i = blockIdx.x*256 + threadIdx.x;   // 0..65535
    if(i < 128*256) g_Winh[i] = __float2half(W_in[i]);
    g_Wihh[i] = __float2half(Wih[i]);
    g_Whhh[i] = __float2half(Whh[i]);
    if(i < 512) g_bsum[i] = bih[i] + bhh[i];
#pragma unroll
    for(int l=0; l<2; l++){
        const float* W1 = aW1 + (size_t)l*65536;
        int o = i >> 8, k = i & 255;
        __half v = __float2half(W1[i]);
        if(k < 128) g_W1ph[l*65536 + o*128 + k] = v;
        else        g_W1ph[l*65536 + (256+o)*128 + (k-128)] = v;
        g_W2h[l*65536 + i] = __float2half(aW2[(size_t)l*65536 + i]);
        if(i < 128*256) g_NW1h[l*32768 + i] = __float2half(nW1[(size_t)l*32768 + i]);
        if(i < 128*128) g_NW2h[l*16384 + i] = __float2half(nW2[(size_t)l*16384 + i]);
    }
}

// ---------------- build x, vectorized half2 ----------------
__global__ void k_build_x2(const float* __restrict__ itime, const float* __restrict__ iev,
                           const int* __restrict__ ann, const float* __restrict__ emb){
    int idx = blockIdx.x*blockDim.x + threadIdx.x;   // over NS*128 half2
    int row = idx >> 7, cp = idx & 127;
    float e = __ldg(&iev[row]);
    __half2 o;
    if(cp < 63){
        const float* ep = emb + (size_t)__ldg(&ann[row])*127 + cp*2;
        o = __floats2half2_rn(__ldg(ep), __ldg(ep+1));
    } else if(cp == 63){
        o = __floats2half2_rn(__ldg(&emb[(size_t)__ldg(&ann[row])*127 + 126]), e);
    } else {
        int j = cp - 64;
        float pos = exp2f(13.287712379549449f * (float)j * (1.0f/64.0f));
        float r = __ldg(&itime[row]) / pos;
        float sv = __sinf(r), cv = __cosf(r);
        if(e == 0.f){ sv = 0.f; cv = 0.f; }
        o = __floats2half2_rn(sv, cv);
    }
    *(__half2*)&g_xh[(size_t)idx*2] = o;
}

// ================= generic FP16 tensor-core GEMM (cp.async, 1 barrier/stage) =================
// NODEA: A built on the fly from fp32 agg: elu(agg*invdeg + nb1) -> fp16.
template<int ACT, bool BIAS, bool OUTH, bool NODEA>
__global__ void __launch_bounds__(256)
k_gemm(const __half* __restrict__ A, int lda,
       const float* __restrict__ aggf, const float* __restrict__ invdeg,
       const float* __restrict__ nb1,
       const __half* __restrict__ B, int ldb,
       const float* __restrict__ bias,
       void* __restrict__ Cp, int ldc, int K)
{
    __shared__ __align__(16) char sm[2*16384];
    const int m0 = blockIdx.x*128, n0 = blockIdx.y*128;
    const int tid  = threadIdx.x;
    const int warp = tid >> 5, lane = tid & 31;
    const int wm = (warp >> 1)*32;
    const int wn = (warp &  1)*64;
    const int qr = lane >> 2, qc = lane & 3;
    const uint32_t smbase = (uint32_t)__cvta_generic_to_shared(sm);

    const int j  = lane >> 3, rl = lane & 7;
    const int aj = j >> 1;
    const int bj = j & 1;
    int abase[2], asw[2], amb[2];
#pragma unroll
    for(int mi=0; mi<2; mi++){
        int m = wm + mi*16 + (j&1)*8 + rl;
        abase[mi] = (m>>1)*128; asw[mi] = (m>>1)&7; amb[mi] = (m&1)*4;
    }
    int bbase[4], bsw[4], bmb[4];
#pragma unroll
    for(int p=0; p<4; p++){
        int n = wn + p*16 + (j>>1)*8 + rl;
        bbase[p] = (n>>1)*128; bsw[p] = (n>>1)&7; bmb[p] = (n&1)*4;
    }

    float4 acc[2][8];
#pragma unroll
    for(int mi=0;mi<2;mi++)
#pragma unroll
        for(int ni=0;ni<8;ni++) acc[mi][ni] = make_float4(0.f,0.f,0.f,0.f);

    const int lr = tid >> 2;
    const int lc = (tid & 3) * 8;
    const int lk = tid & 3;

    uint4 raN[2];

    auto buildA = [&](int k0){
#pragma unroll
        for(int it=0; it<2; it++){
            int r = lr + it*64;
            const float* p = &aggf[(size_t)(m0+r)*128 + k0 + lc];
            float sc = __ldg(&invdeg[(m0+r) >> 6]);
            float4 v0 = *(const float4*)p;
            float4 v1 = *(const float4*)(p+4);
            float4 b0 = *(const float4*)&nb1[k0+lc];
            float4 b1v = *(const float4*)&nb1[k0+lc+4];
            raN[it] = make_uint4(
                f2h2(eluf(v0.x*sc+b0.x),  eluf(v0.y*sc+b0.y)),
                f2h2(eluf(v0.z*sc+b0.z),  eluf(v0.w*sc+b0.w)),
                f2h2(eluf(v1.x*sc+b1v.x), eluf(v1.y*sc+b1v.y)),
                f2h2(eluf(v1.z*sc+b1v.z), eluf(v1.w*sc+b1v.w)));
        }
    };
    auto storeA = [&](int st){
#pragma unroll
        for(int it=0; it<2; it++)
            *(uint4*)(sm + st*16384 + swatom(lr + it*64, lk)) = raN[it];
    };
    auto cpA = [&](int k0, int st){
#pragma unroll
        for(int it=0; it<2; it++){
            int r = lr + it*64;
            cpa16(smbase + st*16384 + swatom(r, lk), &A[(size_t)(m0+r)*lda + k0 + lc]);
        }
    };
    auto cpB = [&](int k0, int st){
#pragma unroll
        for(int it=0; it<2; it++){
            int r = lr + it*64;
            cpa16(smbase + st*16384 + 8192 + swatom(r, lk), &B[(size_t)(n0+r)*ldb + k0 + lc]);
        }
    };

    const int S = K >> 5;
    if(NODEA){ buildA(0); storeA(0); } else { cpA(0,0); }
    cpB(0,0);
    CP_COMMIT();

    for(int s=0; s<S; s++){
        bool more = (s+1 < S);
        CP_WAIT0();
        __syncthreads();
        if(more){
            if(!NODEA) cpA((s+1)<<5, (s+1)&1);
            cpB((s+1)<<5, (s+1)&1);
            CP_COMMIT();
            if(NODEA) buildA((s+1)<<5);   // LDGs drain under mma below
        }

        uint32_t sAa = smbase + (s&1)*16384;
        uint32_t sBa = sAa + 8192;
#pragma unroll
        for(int kh=0; kh<2; kh++){
            int ka = kh*2;
            uint32_t a[2][4];
#pragma unroll
            for(int mi=0; mi<2; mi++){
                uint32_t addr = sAa + abase[mi] + ((((amb[mi] + ka + aj) ^ asw[mi]))<<4);
                ldsm4(a[mi][0], a[mi][1], a[mi][2], a[mi][3], addr);
            }
#pragma unroll
            for(int p=0; p<4; p++){
                uint32_t b0,b1r,b2,b3;
                uint32_t addr = sBa + bbase[p] + ((((bmb[p] + ka + bj) ^ bsw[p]))<<4);
                ldsm4(b0, b1r, b2, b3, addr);
                mma16(acc[0][2*p  ], a[0], b0, b1r);
                mma16(acc[0][2*p+1], a[0], b2, b3);
                mma16(acc[1][2*p  ], a[1], b0, b1r);
                mma16(acc[1][2*p+1], a[1], b2, b3);
            }
        }
        if(NODEA && more) storeA((s+1)&1);   // after mma: hides LDG latency
    }

#pragma unroll
    for(int mi=0; mi<2; mi++){
#pragma unroll
        for(int rr=0; rr<2; rr++){
            int row = m0 + wm + mi*16 + qr + rr*8;
            size_t crow = (size_t)row*ldc;
#pragma unroll
            for(int ni=0; ni<8; ni++){
                int col = n0 + wn + ni*8 + qc*2;
                float v0 = (rr==0 ? acc[mi][ni].x : acc[mi][ni].z);
                float v1 = (rr==0 ? acc[mi][ni].y : acc[mi][ni].w);
                if(BIAS){ v0 += bias[col]; v1 += bias[col+1]; }
                if(ACT==1){ v0 = eluf(v0); v1 = eluf(v1); }
                if(OUTH){
                    *(__half2*)&(((__half*)Cp)[crow + col]) = __floats2half2_rn(v0, v1);
                } else {
                    *(float2*)&(((float*)Cp)[crow + col]) = make_float2(v0, v1);
                }
            }
        }
    }
}

// ================= fused edge GEMM + NW1 GEMM, 512 threads =================
__global__ void __launch_bounds__(512,1)
k_edge_fused(const __half* __restrict__ PQ,
             const int* __restrict__ srcp, const int* __restrict__ dstp,
             const float* __restrict__ b1,
             const __half* __restrict__ W2h, const float* __restrict__ b2,
             const __half* __restrict__ NW1h,
             float* __restrict__ agg2)
{
    extern __shared__ __align__(16) char esm[];
    const int m0 = blockIdx.x*128;
    const int tid  = threadIdx.x;
    const int warp = tid >> 5, lane = tid & 31;
    const int wm  = (warp >> 2)*32;
    const int wn  = (warp &  3)*64;
    const int wn2 = (warp &  3)*32;
    const int qr = lane >> 2, qc = lane & 3;
    const uint32_t smbase = (uint32_t)__cvta_generic_to_shared(esm);
    const uint32_t AOFF = 0, BOFF = 16384, MOFF = 0, NOFF = 65536;

    const int j  = lane >> 3, rl = lane & 7;
    const int aj = j >> 1;
    const int bj = j & 1;
    int abase[2], asw[2], amb[2];
#pragma unroll
    for(int mi=0; mi<2; mi++){
        int m = wm + mi*16 + (j&1)*8 + rl;
        abase[mi] = (m>>1)*128; asw[mi] = (m>>1)&7; amb[mi] = (m&1)*4;
    }
    int bbase[4], bsw[4], bmb[4];
#pragma unroll
    for(int p=0; p<4; p++){
        int n = wn + p*16 + (j>>1)*8 + rl;
        bbase[p] = (n>>1)*128; bsw[p] = (n>>1)&7; bmb[p] = (n&1)*4;
    }
    int cbase[2], csw[2], cmb[2];
#pragma unroll
    for(int p=0; p<2; p++){
        int n = wn2 + p*16 + (j>>1)*8 + rl;
        cbase[p] = (n>>1)*128; csw[p] = (n>>1)&7; cmb[p] = (n&1)*4;
    }

    const int ar = tid >> 2;
    const int ac = (tid & 3) * 8;
    const __half *ap, *aq;
    {
        int grow = m0 + ar;
        int e = grow >> 6, srow = grow & 63;
        ap = PQ + ((size_t)__ldg(&srcp[e])*64 + srow)*512;
        aq = PQ + ((size_t)__ldg(&dstp[e])*64 + srow)*512 + 256;
    }
    const uint32_t aslot = (uint32_t)(swatom(ar, (tid&3)));

    float4 acc[2][8];
#pragma unroll
    for(int mi=0;mi<2;mi++)
#pragma unroll
        for(int ni=0;ni<8;ni++) acc[mi][ni] = make_float4(0.f,0.f,0.f,0.f);

    uint4 ra;

    auto buildA = [&](int k0){
        int kc = k0 + ac;
        uint4 pv = *(const uint4*)(ap + kc);
        uint4 qv = *(const uint4*)(aq + kc);
        float4 bb0 = *(const float4*)&b1[kc];
        float4 bb1 = *(const float4*)&b1[kc+4];
        const __half2* phh = (const __half2*)&pv;
        const __half2* qhh = (const __half2*)&qv;
        float bl[8] = {bb0.x,bb0.y,bb0.z,bb0.w,bb1.x,bb1.y,bb1.z,bb1.w};
        uint32_t o[4];
#pragma unroll
        for(int w=0; w<4; w++){
            float2 pf = __half22float2(phh[w]);
            float2 qf = __half22float2(qhh[w]);
            o[w] = f2h2(eluf(pf.x+qf.x+bl[2*w]), eluf(pf.y+qf.y+bl[2*w+1]));
        }
        ra = make_uint4(o[0],o[1],o[2],o[3]);
    };
    auto storeA = [&](int st){
        *(uint4*)(esm + AOFF + st*8192 + aslot) = ra;
    };
    auto cpW2 = [&](int s, int st){
        int k0 = s << 5;
#pragma unroll
        for(int it=0; it<2; it++){
            int idx = tid + it*512;
            int r = idx >> 2, c = (idx & 3)*8;
            cpa16(smbase + BOFF + st*16384 + swatom(r, idx&3),
                  &W2h[(size_t)r*256 + k0 + c]);
        }
    };

    // ---- phase 1 mainloop: 1 barrier/stage, loads issued before mma, STS after ----
    buildA(0); storeA(0);
    cpW2(0, 0);
    CP_COMMIT();

    for(int s=0; s<8; s++){
        bool more = (s+1 < 8);
        CP_WAIT0();
        __syncthreads();
        if(more){
            cpW2(s+1, (s+1)&1);
            CP_COMMIT();
            buildA((s+1)<<5);            // LDGs drain under mma below
        }

        uint32_t sAa = smbase + AOFF + (s&1)*8192;
        uint32_t sBa = smbase + BOFF + (s&1)*16384;
#pragma unroll
        for(int kh=0; kh<2; kh++){
            int ka = kh*2;
            uint32_t a[2][4];
#pragma unroll
            for(int mi=0; mi<2; mi++){
                uint32_t addr = sAa + abase[mi] + ((((amb[mi] + ka + aj) ^ asw[mi]))<<4);
                ldsm4(a[mi][0], a[mi][1], a[mi][2], a[mi][3], addr);
            }
#pragma unroll
            for(int p=0; p<4; p++){
                uint32_t b0,b1r,b2r,b3;
                uint32_t addr = sBa + bbase[p] + ((((bmb[p] + ka + bj) ^ bsw[p]))<<4);
                ldsm4(b0, b1r, b2r, b3, addr);
                mma16(acc[0][2*p  ], a[0], b0, b1r);
                mma16(acc[0][2*p+1], a[0], b2r, b3);
                mma16(acc[1][2*p  ], a[1], b0, b1r);
                mma16(acc[1][2*p+1], a[1], b2r, b3);
            }
        }
        if(more) storeA((s+1)&1);        // after mma: hides LDG latency
    }
    __syncthreads();   // all phase-1 smem reads done before overlay

    // ---- stream first NW1 tile while writing handoff ----
    {
        int idx = tid;
        int n = idx >> 2, kc = (idx & 3)*8;
        cpa16(smbase + NOFF + swatom(n, idx&3), &NW1h[(size_t)n*256 + kc]);
        CP_COMMIT();
    }

    // ---- handoff: m2 = elu(acc + b2) into smem slices (overlay) ----
#pragma unroll
    for(int mi=0; mi<2; mi++){
#pragma unroll
        for(int rr=0; rr<2; rr++){
            int row = wm + mi*16 + qr + rr*8;
#pragma unroll
            for(int ni=0; ni<8; ni++){
                int col = wn + ni*8 + qc*2;
                float v0 = (rr==0 ? acc[mi][ni].x : acc[mi][ni].z) + __ldg(&b2[col]);
                float v1 = (rr==0 ? acc[mi][ni].y : acc[mi][ni].w) + __ldg(&b2[col+1]);
                v0 = eluf(v0); v1 = eluf(v1);
                int ksl = col >> 5, c = col & 31;
                uint32_t off = MOFF + (uint32_t)ksl*8192 + swatom(row, c>>3) + (c&7)*2;
                *(__half2*)(esm + off) = __floats2half2_rn(v0, v1);
            }
        }
    }

    // ---- phase 2: z = m2 @ NW1^T (128x128x256), 1 barrier/stage ----
    float4 acc2[2][4];
#pragma unroll
    for(int mi=0;mi<2;mi++)
#pragma unroll
        for(int ni=0;ni<4;ni++) acc2[mi][ni] = make_float4(0.f,0.f,0.f,0.f);

    auto cpN = [&](int s, int st){
        int k0 = s << 5;
        int idx = tid;
        int n = idx >> 2, kc = (idx & 3)*8;
        cpa16(smbase + NOFF + st*8192 + swatom(n, idx&3),
              &NW1h[(size_t)n*256 + k0 + kc]);
    };

    for(int s2=0; s2<8; s2++){
        bool more = (s2+1 < 8);
        CP_WAIT0();
        __syncthreads();
        if(more){ cpN(s2+1, (s2+1)&1); CP_COMMIT(); }

        uint32_t sAa = smbase + MOFF + s2*8192;
        uint32_t sBa = smbase + NOFF + (s2&1)*8192;
#pragma unroll
        for(int kh=0; kh<2; kh++){
            int ka = kh*2;
            uint32_t a[2][4];
#pragma unroll
            for(int mi=0; mi<2; mi++){
                uint32_t addr = sAa + abase[mi] + ((((amb[mi] + ka + aj) ^ asw[mi]))<<4);
                ldsm4(a[mi][0], a[mi][1], a[mi][2], a[mi][3], addr);
            }
#pragma unroll
            for(int p=0; p<2; p++){
                uint32_t b0,b1r,b2r,b3;
                uint32_t addr = sBa + cbase[p] + ((((cmb[p] + ka + bj) ^ csw[p]))<<4);
                ldsm4(b0, b1r, b2r, b3, addr);
                mma16(acc2[0][2*p  ], a[0], b0, b1r);
                mma16(acc2[0][2*p+1], a[0], b2r, b3);
                mma16(acc2[1][2*p  ], a[1], b0, b1r);
                mma16(acc2[1][2*p+1], a[1], b2r, b3);
            }
        }
    }

    // ---- epilogue: scatter z (raw, pre-bias) into agg2 ----
#pragma unroll
    for(int mi=0; mi<2; mi++){
#pragma unroll
        for(int rr=0; rr<2; rr++){
            int row = m0 + wm + mi*16 + qr + rr*8;
            int e = row >> 6, s = row & 63;
            size_t crow = (size_t)(__ldg(&dstp[e])*64 + s)*128;
#pragma unroll
            for(int ni=0; ni<4; ni++){
                int col = wn2 + ni*8 + qc*2;
                float v0 = (rr==0 ? acc2[mi][ni].x : acc2[mi][ni].z);
                float v1 = (rr==0 ? acc2[mi][ni].y : acc2[mi][ni].w);
                redv2(&agg2[crow + col], v0, v1);
            }
        }
    }
}

// ================= tensor-core persistent LSTM =================
__global__ void __launch_bounds__(256,1)
k_lstm_mma(const __half* __restrict__ Whh, const __half* __restrict__ gates){
    __shared__ __align__(16) __half hA[16*136];
    __shared__ float G[8][512];
    const int tid = threadIdx.x, warp = tid>>5, lane = tid&31;
    const int nb = blockIdx.x*8;
    const int wn = warp*64;
    const uint32_t hAb = (uint32_t)__cvta_generic_to_shared(hA);

    float cst[4] = {0.f,0.f,0.f,0.f};
    for(int i=tid; i<16*136; i+=256) hA[i] = __float2half(0.f);

    uint32_t bf[8][8][2];
    {
        int bn = lane>>2, bk = (lane&3)*2;
#pragma unroll
        for(int nt=0; nt<8; nt++)
#pragma unroll
        for(int kt=0; kt<8; kt++){
            const __half* p = Whh + (size_t)(wn + nt*8 + bn)*128 + kt*16 + bk;
            bf[nt][kt][0] = *(const uint32_t*)p;
            bf[nt][kt][1] = *(const uint32_t*)(p + 8);
        }
    }
    __syncthreads();

    const int j = lane>>3, rl = lane&7;
    const int arow = (j&1)*8 + rl;
    const int cr = lane>>2, cc = (lane&3)*2;

    for(int t=0; t<64; t++){
        // prefetch gates into regs BEFORE the asm-volatile mma wall
        uint32_t gvr[8];
#pragma unroll
        for(int nt=0; nt<8; nt++)
            gvr[nt] = *(const uint32_t*)&gates[((size_t)(nb+cr)*64 + t)*512 + wn + nt*8 + cc];

        uint32_t a[8][4];
#pragma unroll
        for(int kt=0; kt<8; kt++){
            uint32_t addr = hAb + arow*272 + (uint32_t)((kt*2 + (j>>1))*16);
            ldsm4(a[kt][0], a[kt][1], a[kt][2], a[kt][3], addr);
        }
        float4 acc[8];
#pragma unroll
        for(int nt=0; nt<8; nt++) acc[nt] = make_float4(0.f,0.f,0.f,0.f);
#pragma unroll
        for(int kt=0; kt<8; kt++)
#pragma unroll
            for(int nt=0; nt<8; nt++)
                mma16(acc[nt], a[kt], bf[nt][kt][0], bf[nt][kt][1]);

#pragma unroll
        for(int nt=0; nt<8; nt++){
            int col = wn + nt*8 + cc;
            float2 gf = __half22float2(*(__half2*)&gvr[nt]);
            G[cr][col]   = acc[nt].x + gf.x;
            G[cr][col+1] = acc[nt].y + gf.y;
        }
        __syncthreads();

#pragma unroll
        for(int q=0; q<4; q++){
            int idx = q*256 + tid;
            int n = idx>>7, jj = idx&127;
            float ig=G[n][jj], fg=G[n][128+jj], gg=G[n][256+jj], og=G[n][384+jj];
            float cn = sigf(fg)*cst[q] + sigf(ig)*tanhfast(gg);
            cst[q] = cn;
            float h = sigf(og)*tanhfast(cn);
            hA[n*136 + jj] = __float2half(h);
            if(t==63) g_h[(size_t)(nb+n)*128 + jj] = h;
        }
        __syncthreads();
    }
}

// ---------------- output heads ----------------
__global__ void k_heads(const float* __restrict__ Wm, const float* __restrict__ bm,
                        const float* __restrict__ Wt, const float* __restrict__ bt,
                        const float* __restrict__ We, const float* __restrict__ be,
                        float* __restrict__ out){
    int n = blockIdx.x;
    int l = threadIdx.x;
    float sm=0.f, st=0.f, se=0.f;
    for(int jj=l;jj<128;jj+=32){
        float h = g_h[(size_t)n*128 + jj];
        sm += h*Wm[jj]; st += h*Wt[jj]; se += h*We[jj];
    }
#pragma unroll
    for(int o=16;o;o>>=1){
        sm += __shfl_down_sync(0xffffffffu, sm, o);
        st += __shfl_down_sync(0xffffffffu, st, o);
        se += __shfl_down_sync(0xffffffffu, se, o);
    }
    if(l==0){
        out[n]            = sm + bm[0];
        out[N_NODES + n]  = st + bt[0];
        out[2*N_NODES + n]= se + be[0];
    }
}

// ---------------- host launcher ----------------
extern "C" void kernel_launch(void* const* d_in, const int* in_sizes, int n_in,
                              void* d_out, int out_size)
{
    const int*   edge  = (const int*)  d_in[0];
    const float* itime = (const float*)d_in[1];
    const float* iev   = (const float*)d_in[2];
    const int*   ann   = (const int*)  d_in[3];
    const float* emb   = (const float*)d_in[4];
    const float* W_in  = (const float*)d_in[5];
    const float* b_in  = (const float*)d_in[6];
    const float* nW1   = (const float*)d_in[7];
    const float* nb1   = (const float*)d_in[8];
    const float* nW2   = (const float*)d_in[9];
    const float* nb2   = (const float*)d_in[10];
    const float* aW1   = (const float*)d_in[11];
    const float* ab1   = (const float*)d_in[12];
    const float* aW2   = (const float*)d_in[13];
    const float* ab2   = (const float*)d_in[14];
    const float* Wih   = (const float*)d_in[15];
    const float* Whh   = (const float*)d_in[16];
    const float* bih   = (const float*)d_in[17];
    const float* bhh   = (const float*)d_in[18];
    const float* Wm    = (const float*)d_in[19];
    const float* bm    = (const float*)d_in[20];
    const float* Wt    = (const float*)d_in[21];
    const float* bt    = (const float*)d_in[22];
    const float* We    = (const float*)d_in[23];
    const float* be    = (const float*)d_in[24];
    float* out = (float*)d_out;

    const int* src = edge;
    const int* dst = edge + NEDGE;

    __half *pxh, *pnfh, *pPQh, *pgatesh;
    __half *pWinh, *pW1ph, *pW2h, *pNW1h, *pNW2h, *pWihh, *pWhhh;
    float *pagg, *pinvdeg, *pbsum;
    cudaGetSymbolAddress((void**)&pxh,    g_xh);
    cudaGetSymbolAddress((void**)&pnfh,   g_nfh);
    cudaGetSymbolAddress((void**)&pPQh,   g_PQh);
    cudaGetSymbolAddress((void**)&pgatesh,g_gatesh);
    cudaGetSymbolAddress((void**)&pWinh,  g_Winh);
    cudaGetSymbolAddress((void**)&pW1ph,  g_W1ph);
    cudaGetSymbolAddress((void**)&pW2h,   g_W2h);
    cudaGetSymbolAddress((void**)&pNW1h,  g_NW1h);
    cudaGetSymbolAddress((void**)&pNW2h,  g_NW2h);
    cudaGetSymbolAddress((void**)&pWihh,  g_Wihh);
    cudaGetSymbolAddress((void**)&pWhhh,  g_Whhh);
    cudaGetSymbolAddress((void**)&pagg,   g_agg);
    cudaGetSymbolAddress((void**)&pinvdeg,g_invdeg);
    cudaGetSymbolAddress((void**)&pbsum,  g_bsum);

    cudaFuncSetAttribute(k_edge_fused, cudaFuncAttributeMaxDynamicSharedMemorySize, 81920);

    // #1 merged prep, #2 build_x, #3 Win GEMM, #4 PQ GEMM (ncu capture target)
    k_prep_all<<<256,256>>>(W_in, Wih, Whh, bih, bhh, aW1, aW2, nW1, nW2);
    k_build_x2<<<NS*128/256,256>>>(itime, iev, ann, emb);
    k_gemm<0,true,true,false><<<dim3(NS/128,1),256>>>(
        pxh,256, nullptr,nullptr,nullptr, pWinh,256, b_in, pnfh,128, 256);

    for(int l=0; l<2; l++){
        const float* B1 = ab1 + (size_t)l*256;
        const float* B2 = ab2 + (size_t)l*256;
        const float* NB1= nb1 + (size_t)l*128;
        const float* NB2= nb2 + (size_t)l*128;
        __half* W1p = pW1ph + (size_t)l*65536;
        __half* W2h = pW2h  + (size_t)l*65536;
        __half* NW1h= pNW1h + (size_t)l*32768;
        __half* NW2h= pNW2h + (size_t)l*16384;

        // [P|Q] = nf @ W1p^T -> fp16 [NS,512]
        k_gemm<0,false,true,false><<<dim3(NS/128,4),256>>>(
            pnfh,128, nullptr,nullptr,nullptr, W1p,128, nullptr, pPQh,512, 128);

        if(l == 0){  // degrees (only needed from the NW2 GEMM onward)
            k_zero_deg<<<4,256>>>();
            k_deg<<<(NEDGE+255)/256,256>>>(dst);
            k_fin_deg<<<4,256>>>();
        }

        // zero agg2 (128-wide), fused edge+NW1 GEMM with red.v2 scatter
        cudaMemsetAsync(pagg, 0, (size_t)NS*128*sizeof(float));
        k_edge_fused<<<ES/128,512,81920>>>(pPQh, src, dst, B1, W2h, B2, NW1h, pagg);

        // NW2 GEMM with fused node1 (A = elu(agg*invdeg + NB1) built on the fly)
        k_gemm<1,true,true,true><<<dim3(NS/128,1),256>>>(
            nullptr,128, pagg, pinvdeg, NB1, NW2h,128, NB2, pnfh,128, 128);
    }

    // LSTM: input gates for all timesteps, then tensor-core recurrence
    k_gemm<0,true,true,false><<<dim3(NS/128,4),256>>>(
        pnfh,128, nullptr,nullptr,nullptr, pWihh,128, pbsum, pgatesh,512, 128);
    k_lstm_mma<<<128,256>>>(pWhhh, pgatesh);

    k_heads<<<N_NODES,32>>>(Wm,bm,Wt,bt,We,be,out);
}